// round 9
// baseline (speedup 1.0000x reference)
#include <cuda_runtime.h>
#include <cuda_fp16.h>
#include <math.h>
#include <cstdint>

#define NN 16384
#define CC 256
#define HH 8
#define HD 512
#define QKVW 1536
#define HIDD 512
#define OUTD 64
#define H2D 532
#define ATTKP 576   // 520 padded to 64-multiple
#define H2KP 576    // 532 padded

// ---------------- scratch (static device arrays; no allocation) ----------------
__device__ float g_QKV[NN * QKVW];          // fp32 Q|K|V for attention
__device__ float g_G[NN * HH];
__device__ float g_Z[NN * OUTD];
__device__ float g_part[NN];                // per-node vq loss partials

// activation fp16 limbs (zero-init pads stay zero forever)
__device__ __half g_xl0[NN * CC], g_xl1[NN * CC];
__device__ __half g_Al0[NN * ATTKP], g_Al1[NN * ATTKP];
__device__ __half g_Tl0[NN * CC], g_Tl1[NN * CC];
__device__ __half g_Hl0[NN * H2KP], g_Hl1[NN * H2KP];

// weight fp16 limbs, [N, Kp] K-major
__device__ __half g_Bq0[QKVW * CC], g_Bq1[QKVW * CC];
__device__ __half g_Bo0[CC * ATTKP], g_Bo1[CC * ATTKP];
__device__ __half g_Bl0[HIDD * CC], g_Bl1[HIDD * CC];
__device__ __half g_Bu0[OUTD * H2KP], g_Bu1[OUTD * H2KP];

// ---------------- helpers ----------------
__device__ __forceinline__ float gelu_tanh(float x) {
    float x3 = x * x * x;
    return 0.5f * x * (1.0f + tanhf(0.7978845608028654f * (x + 0.044715f * x3)));
}

__device__ __forceinline__ void store2(__half* p0, __half* p1, size_t off, float v) {
    __half h0 = __float2half_rn(v);
    __half h1 = __float2half_rn(v - __half2float(h0));
    p0[off] = h0;
    p1[off] = h1;
}

__device__ __forceinline__ uint32_t smem_u32(const void* p) {
    uint32_t a;
    asm("{ .reg .u64 t; cvta.to.shared.u64 t, %1; cvt.u32.u64 %0, t; }" : "=r"(a) : "l"(p));
    return a;
}

__device__ __forceinline__ void ldsm4(uint32_t* r, uint32_t addr) {
    asm volatile("ldmatrix.sync.aligned.m8n8.x4.shared.b16 {%0,%1,%2,%3}, [%4];"
                 : "=r"(r[0]), "=r"(r[1]), "=r"(r[2]), "=r"(r[3]) : "r"(addr));
}

__device__ __forceinline__ void mma16816(float* c, const uint32_t* a, const uint32_t* b) {
    asm volatile(
        "mma.sync.aligned.m16n8k16.row.col.f32.f16.f16.f32 "
        "{%0,%1,%2,%3}, {%4,%5,%6,%7}, {%8,%9}, {%0,%1,%2,%3};"
        : "+f"(c[0]), "+f"(c[1]), "+f"(c[2]), "+f"(c[3])
        : "r"(a[0]), "r"(a[1]), "r"(a[2]), "r"(a[3]), "r"(b[0]), "r"(b[1]));
}

// ============== mma.sync fp16 2-limb 3-pass GEMM: C = A*B^T (R6 engine) ==========
// A limbs: [M, Kp] row-major fp16.  B limbs: [N, Kp] K-major fp16.
// CTA tile 128 x NT, 8 warps (2m x 4n), warp tile 64 x (NT/4).
// EPI: 0=fp32 plain, 1=resid+dyntanh->limbs, 2=gelu(bias)+dyntanh->limbs,
//      3=tanh(gelu(bias))->fp32
template <int NT, int EPI>
__global__ __launch_bounds__(256) void mmagemm(
        const __half* __restrict__ A0, const __half* __restrict__ A1,
        const __half* __restrict__ B0, const __half* __restrict__ B1,
        int Kp,
        float* __restrict__ outF, int ldoF,
        __half* __restrict__ O0, __half* __restrict__ O1, int ldoL,
        const float* __restrict__ bias, const float* __restrict__ resid, int ldr,
        const float* __restrict__ alpha_p,
        const float* __restrict__ gv, const float* __restrict__ bv) {
    __shared__ __half As[128][72];
    __shared__ __half Bs[NT][72];
    constexpr int NF = NT / 32;   // n-frags per warp (8 cols each)

    int tid = threadIdx.x, lane = tid & 31, wid = tid >> 5;
    int wm = wid & 1, wn = wid >> 1;
    int bm = blockIdx.y * 128, bn = blockIdx.x * NT;
    int nch = Kp >> 6;

    float acc[4][NF][4];
#pragma unroll
    for (int i = 0; i < 4; i++)
#pragma unroll
        for (int j = 0; j < NF; j++)
#pragma unroll
            for (int c = 0; c < 4; c++) acc[i][j][c] = 0.f;

    // 3 passes: h0*g0, h0*g1, h1*g0 (residual ~2^-22)
    const int laT[3] = {0, 0, 1};
    const int lbT[3] = {0, 1, 0};

#pragma unroll 1
    for (int t = 0; t < 3; t++) {
        const __half* Ab = (laT[t] == 0) ? A0 : A1;
        const __half* Bb = (lbT[t] == 0) ? B0 : B1;
#pragma unroll 1
        for (int c = 0; c < nch; c++) {
            __syncthreads();   // previous chunk's compute done
            const __half* Asrc = Ab + (size_t)bm * Kp + c * 64;
#pragma unroll
            for (int q = 0; q < 4; q++) {
                int idx = tid + q * 256;
                int row = idx >> 3, cg = idx & 7;
                uint4 v = *(const uint4*)(Asrc + (size_t)row * Kp + cg * 8);
                *(uint4*)&As[row][cg * 8] = v;
            }
            const __half* Bsrc = Bb + (size_t)bn * Kp + c * 64;
#pragma unroll
            for (int q = 0; q < NF; q++) {
                int idx = tid + q * 256;
                int row = idx >> 3, cg = idx & 7;
                uint4 v = *(const uint4*)(Bsrc + (size_t)row * Kp + cg * 8);
                *(uint4*)&Bs[row][cg * 8] = v;
            }
            __syncthreads();

#pragma unroll
            for (int kk = 0; kk < 4; kk++) {
                int k = kk * 16;
                uint32_t a[4][4];
#pragma unroll
                for (int i = 0; i < 4; i++) {
                    int row = wm * 64 + i * 16 + (lane & 15);
                    int col = k + (lane >> 4) * 8;
                    ldsm4(a[i], smem_u32(&As[row][col]));
                }
                uint32_t b[NF][2];
#pragma unroll
                for (int jj = 0; jj < NF / 2; jj++) {
                    int n0 = wn * (NT / 4) + jj * 16;
                    int g = lane >> 3;
                    int nr = n0 + ((g >> 1) << 3) + (lane & 7);
                    int kc = k + (g & 1) * 8;
                    uint32_t tmp[4];
                    ldsm4(tmp, smem_u32(&Bs[nr][kc]));
                    b[2 * jj][0] = tmp[0]; b[2 * jj][1] = tmp[1];
                    b[2 * jj + 1][0] = tmp[2]; b[2 * jj + 1][1] = tmp[3];
                }
#pragma unroll
                for (int i = 0; i < 4; i++)
#pragma unroll
                    for (int j = 0; j < NF; j++) mma16816(acc[i][j], a[i], b[j]);
            }
        }
    }

    // ---------------- epilogue ----------------
    float alpha = (EPI == 1 || EPI == 2) ? *alpha_p : 0.f;
    int gid = lane >> 2, tig = lane & 3;
#pragma unroll
    for (int i = 0; i < 4; i++) {
#pragma unroll
        for (int j = 0; j < NF; j++) {
#pragma unroll
            for (int cc = 0; cc < 4; cc++) {
                int m = bm + wm * 64 + i * 16 + gid + (cc >> 1) * 8;
                int ncol = bn + wn * (NT / 4) + j * 8 + tig * 2 + (cc & 1);
                float v = acc[i][j][cc];
                if (EPI == 0) {
                    outF[(size_t)m * ldoF + ncol] = v;
                } else if (EPI == 1) {
                    v += resid[(size_t)m * ldr + ncol];
                    v = tanhf(alpha * v) * gv[ncol] + bv[ncol];
                    store2(O0, O1, (size_t)m * ldoL + ncol, v);
                } else if (EPI == 2) {
                    v = gelu_tanh(v + bias[ncol]);
                    v = tanhf(alpha * v) * gv[ncol] + bv[ncol];
                    store2(O0, O1, (size_t)m * ldoL + ncol, v);
                } else {
                    v = tanhf(gelu_tanh(v + bias[ncol]));
                    outF[(size_t)m * ldoF + ncol] = v;
                }
            }
        }
    }
}

// ---------------- conversions ----------------
__global__ void convA_kernel(const float* __restrict__ src, __half* d0, __half* d1, int n) {
    int t = blockIdx.x * blockDim.x + threadIdx.x;
    if (t >= n) return;
    store2(d0, d1, t, src[t]);
}

__global__ void convB_kernel(const float* __restrict__ src, __half* d0, __half* d1,
                             int K, int N, int Kp) {
    int t = blockIdx.x * blockDim.x + threadIdx.x;
    if (t >= N * K) return;
    int n = t / K, k = t - n * K;
    store2(d0, d1, (size_t)n * Kp + k, src[(size_t)k * N + n]);
}

__global__ void convBqkv_kernel(const float* __restrict__ Wq, const float* __restrict__ Wk,
                                const float* __restrict__ Wv, __half* d0, __half* d1) {
    int t = blockIdx.x * blockDim.x + threadIdx.x;
    if (t >= QKVW * CC) return;
    int n = t >> 8, k = t & 255;
    const float* s = (n < 512) ? Wq : ((n < 1024) ? Wk : Wv);
    int col = n & 511;
    store2(d0, d1, (size_t)n * CC + k, s[(size_t)k * 512 + col]);
}

// ---------------- gate projection: warp per node ----------------
__global__ void gate_kernel(const float* __restrict__ x, const float* __restrict__ wg) {
    int wid = threadIdx.x >> 5, lane = threadIdx.x & 31;
    int n = blockIdx.x * 8 + wid;
    if (n >= NN) return;
    const float* xr = x + (size_t)n * CC;
    float4 v0 = *(const float4*)(xr + lane * 8);
    float4 v1 = *(const float4*)(xr + lane * 8 + 4);
    float xv[8] = {v0.x, v0.y, v0.z, v0.w, v1.x, v1.y, v1.z, v1.w};
#pragma unroll
    for (int h = 0; h < 8; h++) {
        float p = 0.f;
#pragma unroll
        for (int i = 0; i < 8; i++) p = fmaf(xv[i], wg[(lane * 8 + i) * 8 + h], p);
#pragma unroll
        for (int o = 16; o; o >>= 1) p += __shfl_xor_sync(0xffffffffu, p, o);
        if (lane == 0) g_G[(size_t)n * 8 + h] = p;
    }
}

// ---------------- attention: block per node, warp per head; writes Att limbs ------
__global__ void attn_kernel(const float* __restrict__ coors, const int* __restrict__ nbr,
                            const float* __restrict__ Wr1, const float* __restrict__ br1,
                            const float* __restrict__ Wr2, const float* __restrict__ br2) {
    int n = blockIdx.x;
    int tid = threadIdx.x;
    __shared__ int s_nbr[8];
    __shared__ float s_dist[8];
    __shared__ float s_unit[8][3];
    __shared__ float s_rad[8][8];
    __shared__ float s_gate[8][8];

    if (tid < 8) s_nbr[tid] = nbr[(size_t)n * 8 + tid];
    __syncthreads();
    if (tid < 8) {
        int j = tid;
        float cx = coors[(size_t)n * 3], cy = coors[(size_t)n * 3 + 1], cz = coors[(size_t)n * 3 + 2];
        int mm = s_nbr[j];
        float rx = coors[(size_t)mm * 3] - cx;
        float ry = coors[(size_t)mm * 3 + 1] - cy;
        float rz = coors[(size_t)mm * 3 + 2] - cz;
        float d = sqrtf(rx * rx + ry * ry + rz * rz + 1e-8f);
        s_dist[j] = d;
        s_unit[j][0] = rx / d;
        s_unit[j][1] = ry / d;
        s_unit[j][2] = rz / d;
    }
    __syncthreads();
    if (tid < 64) {
        int j = tid >> 3, h = tid & 7;
        float d = s_dist[j];
        float acc = br2[h];
#pragma unroll
        for (int i = 0; i < 16; i++)
            acc = fmaf(gelu_tanh(d * Wr1[i] + br1[i]), Wr2[i * 8 + h], acc);
        s_rad[j][h] = acc;
        s_gate[j][h] = g_G[(size_t)s_nbr[j] * HH + h];
    }
    __syncthreads();

    int w = tid >> 5, lane = tid & 31;
    int h = w;
    const float* qr = g_QKV + (size_t)n * QKVW + h * 64;
    float q0 = qr[lane * 2], q1 = qr[lane * 2 + 1];
    float logit[8];
#pragma unroll
    for (int j = 0; j < 8; j++) {
        const float* kr = g_QKV + (size_t)s_nbr[j] * QKVW + 512 + h * 64;
        float p = q0 * kr[lane * 2] + q1 * kr[lane * 2 + 1];
#pragma unroll
        for (int o = 16; o; o >>= 1) p += __shfl_xor_sync(0xffffffffu, p, o);
        p = p * 0.125f + s_rad[j][h];
        logit[j] = (s_dist[j] <= 10.0f) ? p : -1e9f;
    }
    float mx = logit[0];
#pragma unroll
    for (int j = 1; j < 8; j++) mx = fmaxf(mx, logit[j]);
    float e[8];
    float se = 0.f;
#pragma unroll
    for (int j = 0; j < 8; j++) { e[j] = expf(logit[j] - mx); se += e[j]; }
    float inv = 1.f / se;
    float a0 = 0.f, a1 = 0.f;
#pragma unroll
    for (int j = 0; j < 8; j++) {
        float at = e[j] * inv;
        const float* vr = g_QKV + (size_t)s_nbr[j] * QKVW + 1024 + h * 64;
        a0 = fmaf(at, vr[lane * 2], a0);
        a1 = fmaf(at, vr[lane * 2 + 1], a1);
    }
    size_t base = (size_t)n * ATTKP + h * 64 + lane * 2;
    store2(g_Al0, g_Al1, base, a0);
    store2(g_Al0, g_Al1, base + 1, a1);
    if (lane == 0) {
        float vx = 0.f, vy = 0.f, vz = 0.f;
#pragma unroll
        for (int j = 0; j < 8; j++) {
            float wg = e[j] * inv * s_gate[j][h];
            vx = fmaf(wg, s_unit[j][0], vx);
            vy = fmaf(wg, s_unit[j][1], vy);
            vz = fmaf(wg, s_unit[j][2], vz);
        }
        float vn = sqrtf(vx * vx + vy * vy + vz * vz + 1e-8f);
        store2(g_Al0, g_Al1, (size_t)n * ATTKP + 512 + h, vn);
    }
}

// ---------------- H2 extra columns (aa feats through dyntanh2) -> limbs ----------
__global__ void h2extra_kernel(const float* __restrict__ x, const float* __restrict__ alpha2,
                               const float* __restrict__ g2, const float* __restrict__ b2) {
    int t = blockIdx.x * blockDim.x + threadIdx.x;
    if (t >= NN * 20) return;
    int n = t / 20, j = t % 20;
    float a = *alpha2;
    float v = tanhf(a * x[(size_t)n * CC + j]) * g2[512 + j] + b2[512 + j];
    store2(g_Hl0, g_Hl1, (size_t)n * H2KP + 512 + j, v);
}

// ---------------- VQ: 4 nodes per block, no global atomics ----------------
__global__ void vq_kernel(const float* __restrict__ cb, float* __restrict__ out) {
    int grp = threadIdx.x >> 6, t = threadIdx.x & 63;
    int n = blockIdx.x * 4 + grp;
    __shared__ float s_z[4][64];
    __shared__ float s_wsc[4][2];
    __shared__ int s_wbi[4][2];
    __shared__ int s_bi[4];
    s_z[grp][t] = g_Z[(size_t)n * 64 + t];
    __syncthreads();
    float dot = 0.f, cn = 0.f;
    const float* ce = cb + (size_t)t * 64;
#pragma unroll 8
    for (int d = 0; d < 64; d++) {
        float c = ce[d];
        dot = fmaf(s_z[grp][d], c, dot);
        cn = fmaf(c, c, cn);
    }
    float sc = cn - 2.f * dot;
    int bi = t;
#pragma unroll
    for (int o = 16; o; o >>= 1) {
        float osc = __shfl_xor_sync(0xffffffffu, sc, o);
        int obi = __shfl_xor_sync(0xffffffffu, bi, o);
        if (osc < sc || (osc == sc && obi < bi)) { sc = osc; bi = obi; }
    }
    if ((t & 31) == 0) { s_wsc[grp][t >> 5] = sc; s_wbi[grp][t >> 5] = bi; }
    __syncthreads();
    if (t == 0) {
        float s0 = s_wsc[grp][0], s1 = s_wsc[grp][1];
        int b0 = s_wbi[grp][0], b1 = s_wbi[grp][1];
        s_bi[grp] = (s1 < s0 || (s1 == s0 && b1 < b0)) ? b1 : b0;
    }
    __syncthreads();
    int best = s_bi[grp];
    float zq = cb[(size_t)best * 64 + t];
    out[(size_t)n * 64 + t] = zq;
    float df = s_z[grp][t] - zq;
    df = df * df;
#pragma unroll
    for (int o = 16; o; o >>= 1) df += __shfl_xor_sync(0xffffffffu, df, o);
    if ((t & 31) == 0) s_wsc[grp][t >> 5] = df;
    __syncthreads();
    if (t == 0) g_part[n] = s_wsc[grp][0] + s_wsc[grp][1];
}

__global__ void loss_reduce_kernel(float* __restrict__ out) {
    __shared__ double s_s[32];
    int tid = threadIdx.x;
    double s = 0.0;
    for (int i = tid; i < NN; i += 1024) s += (double)g_part[i];
#pragma unroll
    for (int o = 16; o; o >>= 1) s += __shfl_xor_sync(0xffffffffu, s, o);
    if ((tid & 31) == 0) s_s[tid >> 5] = s;
    __syncthreads();
    if (tid == 0) {
        double tot = 0.0;
        for (int i = 0; i < 32; i++) tot += s_s[i];
        out[(size_t)NN * OUTD] = (float)(0.25 * tot / (double)((size_t)NN * OUTD));
    }
}

// ---------------- launch ----------------
extern "C" void kernel_launch(void* const* d_in, const int* in_sizes, int n_in,
                              void* d_out, int out_size) {
    const float *x, *coors, *Wq, *Wk, *Wv, *wg, *Wr1, *br1, *Wr2, *br2, *Wo;
    const float *a1, *g1, *b1, *Wlin, *blin, *a2, *g2, *b2, *Wout, *bout, *cb;
    const int* nbr;

    if (n_in > 5 && in_sizes[5] == 2048) {
        x = (const float*)d_in[0];   coors = (const float*)d_in[1];
        Wq = (const float*)d_in[2];  Wk = (const float*)d_in[3];  Wv = (const float*)d_in[4];
        wg = (const float*)d_in[5];  Wr1 = (const float*)d_in[6]; br1 = (const float*)d_in[7];
        Wr2 = (const float*)d_in[8]; br2 = (const float*)d_in[9]; Wo = (const float*)d_in[10];
        a1 = (const float*)d_in[11]; g1 = (const float*)d_in[12]; b1 = (const float*)d_in[13];
        Wlin = (const float*)d_in[14]; blin = (const float*)d_in[15];
        a2 = (const float*)d_in[16]; g2 = (const float*)d_in[17]; b2 = (const float*)d_in[18];
        Wout = (const float*)d_in[19]; bout = (const float*)d_in[20];
        cb = (const float*)d_in[21]; nbr = (const int*)d_in[22];
    } else {
        x = (const float*)d_in[0];   coors = (const float*)d_in[1];
        nbr = (const int*)d_in[2];
        Wq = (const float*)d_in[3];  Wk = (const float*)d_in[4];  Wv = (const float*)d_in[5];
        wg = (const float*)d_in[6];  Wr1 = (const float*)d_in[7]; br1 = (const float*)d_in[8];
        Wr2 = (const float*)d_in[9]; br2 = (const float*)d_in[10]; Wo = (const float*)d_in[11];
        a1 = (const float*)d_in[12]; g1 = (const float*)d_in[13]; b1 = (const float*)d_in[14];
        Wlin = (const float*)d_in[15]; blin = (const float*)d_in[16];
        a2 = (const float*)d_in[17]; g2 = (const float*)d_in[18]; b2 = (const float*)d_in[19];
        Wout = (const float*)d_in[20]; bout = (const float*)d_in[21];
        cb = (const float*)d_in[22];
    }

    float *pQKV, *pZ;
    cudaGetSymbolAddress((void**)&pQKV, g_QKV);
    cudaGetSymbolAddress((void**)&pZ, g_Z);
    __half *xl0, *xl1, *Al0, *Al1, *Tl0, *Tl1, *Hl0, *Hl1;
    cudaGetSymbolAddress((void**)&xl0, g_xl0); cudaGetSymbolAddress((void**)&xl1, g_xl1);
    cudaGetSymbolAddress((void**)&Al0, g_Al0); cudaGetSymbolAddress((void**)&Al1, g_Al1);
    cudaGetSymbolAddress((void**)&Tl0, g_Tl0); cudaGetSymbolAddress((void**)&Tl1, g_Tl1);
    cudaGetSymbolAddress((void**)&Hl0, g_Hl0); cudaGetSymbolAddress((void**)&Hl1, g_Hl1);
    __half *Bq0, *Bq1, *Bo0, *Bo1, *Bl0, *Bl1, *Bu0, *Bu1;
    cudaGetSymbolAddress((void**)&Bq0, g_Bq0); cudaGetSymbolAddress((void**)&Bq1, g_Bq1);
    cudaGetSymbolAddress((void**)&Bo0, g_Bo0); cudaGetSymbolAddress((void**)&Bo1, g_Bo1);
    cudaGetSymbolAddress((void**)&Bl0, g_Bl0); cudaGetSymbolAddress((void**)&Bl1, g_Bl1);
    cudaGetSymbolAddress((void**)&Bu0, g_Bu0); cudaGetSymbolAddress((void**)&Bu1, g_Bu1);

    float* out = (float*)d_out;

    // launch order keeps mmagemm<128,0> in the ncu capture slot (#4)
    convA_kernel<<<(NN * CC + 255) / 256, 256>>>(x, xl0, xl1, NN * CC);          // 1
    convBqkv_kernel<<<(QKVW * CC + 255) / 256, 256>>>(Wq, Wk, Wv, Bq0, Bq1);     // 2
    gate_kernel<<<NN / 8, 256>>>(x, wg);                                         // 3

    // QKV = x @ [Wq|Wk|Wv]  -> fp32                                             // 4
    mmagemm<128, 0><<<dim3(QKVW / 128, NN / 128), 256>>>(
        xl0, xl1, Bq0, Bq1, CC,
        pQKV, QKVW, nullptr, nullptr, 0,
        nullptr, nullptr, 0, nullptr, nullptr, nullptr);

    convB_kernel<<<(CC * 520 + 255) / 256, 256>>>(Wo, Bo0, Bo1, 520, CC, ATTKP); // 5
    attn_kernel<<<NN, 256>>>(coors, nbr, Wr1, br1, Wr2, br2);                    // 6

    // T = dyntanh(x + Att@Wo) -> limbs
    mmagemm<128, 1><<<dim3(CC / 128, NN / 128), 256>>>(
        Al0, Al1, Bo0, Bo1, ATTKP,
        nullptr, 0, Tl0, Tl1, CC,
        nullptr, x, CC, a1, g1, b1);

    convB_kernel<<<(HIDD * CC + 255) / 256, 256>>>(Wlin, Bl0, Bl1, CC, HIDD, CC);

    // H2[:, :512] = dyntanh2(gelu(T@Wlin + blin)) -> limbs
    mmagemm<128, 2><<<dim3(HIDD / 128, NN / 128), 256>>>(
        Tl0, Tl1, Bl0, Bl1, CC,
        nullptr, 0, Hl0, Hl1, H2KP,
        blin, nullptr, 0, a2, g2, b2);
    h2extra_kernel<<<(NN * 20 + 255) / 256, 256>>>(x, a2, g2, b2);
    convB_kernel<<<(OUTD * 532 + 255) / 256, 256>>>(Wout, Bu0, Bu1, 532, OUTD, H2KP);

    // Z = tanh(gelu(H2@Wout + bout)) -> fp32
    mmagemm<64, 3><<<dim3(1, NN / 128), 256>>>(
        Hl0, Hl1, Bu0, Bu1, H2KP,
        pZ, OUTD, nullptr, nullptr, 0,
        bout, nullptr, 0, nullptr, nullptr, nullptr);

    vq_kernel<<<NN / 4, 256>>>(cb, out);
    if (out_size > NN * OUTD) loss_reduce_kernel<<<1, 1024>>>(out);
}

// round 10
// speedup vs baseline: 1.4015x; 1.4015x over previous
#include <cuda_runtime.h>
#include <cuda_fp16.h>
#include <math.h>
#include <cstdint>

#define NN 16384
#define CC 256
#define HH 8
#define HD 512
#define QKVW 1536
#define HIDD 512
#define OUTD 64
#define H2D 532
#define ATTKP 576   // 520 padded to 64-multiple
#define H2KP 576    // 532 padded

// ---------------- scratch (static device arrays; no allocation) ----------------
__device__ float g_QKV[NN * QKVW];          // fp32 Q|K|V for attention
__device__ float g_G[NN * HH];
__device__ float g_part[NN];                // per-node vq loss partials

// activation fp16 limbs (zero-init pads stay zero forever)
__device__ __half g_xl0[NN * CC], g_xl1[NN * CC];
__device__ __half g_Al0[NN * ATTKP], g_Al1[NN * ATTKP];
__device__ __half g_Tl0[NN * CC], g_Tl1[NN * CC];
__device__ __half g_Hl0[NN * H2KP], g_Hl1[NN * H2KP];

// weight fp16 limbs, [N, Kp] K-major
__device__ __half g_Bq0[QKVW * CC], g_Bq1[QKVW * CC];
__device__ __half g_Bo0[CC * ATTKP], g_Bo1[CC * ATTKP];
__device__ __half g_Bl0[HIDD * CC], g_Bl1[HIDD * CC];
__device__ __half g_Bu0[OUTD * H2KP], g_Bu1[OUTD * H2KP];

// ---------------- helpers ----------------
__device__ __forceinline__ float gelu_tanh(float x) {
    float x3 = x * x * x;
    return 0.5f * x * (1.0f + tanhf(0.7978845608028654f * (x + 0.044715f * x3)));
}

__device__ __forceinline__ void store2(__half* p0, __half* p1, size_t off, float v) {
    __half h0 = __float2half_rn(v);
    __half h1 = __float2half_rn(v - __half2float(h0));
    p0[off] = h0;
    p1[off] = h1;
}

__device__ __forceinline__ uint32_t smem_u32(const void* p) {
    uint32_t a;
    asm("{ .reg .u64 t; cvta.to.shared.u64 t, %1; cvt.u32.u64 %0, t; }" : "=r"(a) : "l"(p));
    return a;
}

__device__ __forceinline__ void ldsm4(uint32_t* r, uint32_t addr) {
    asm volatile("ldmatrix.sync.aligned.m8n8.x4.shared.b16 {%0,%1,%2,%3}, [%4];"
                 : "=r"(r[0]), "=r"(r[1]), "=r"(r[2]), "=r"(r[3]) : "r"(addr));
}

__device__ __forceinline__ void mma16816(float* c, const uint32_t* a, const uint32_t* b) {
    asm volatile(
        "mma.sync.aligned.m16n8k16.row.col.f32.f16.f16.f32 "
        "{%0,%1,%2,%3}, {%4,%5,%6,%7}, {%8,%9}, {%0,%1,%2,%3};"
        : "+f"(c[0]), "+f"(c[1]), "+f"(c[2]), "+f"(c[3])
        : "r"(a[0]), "r"(a[1]), "r"(a[2]), "r"(a[3]), "r"(b[0]), "r"(b[1]));
}

__device__ __forceinline__ void cpasync16(uint32_t saddr, const void* gptr) {
    asm volatile("cp.async.cg.shared.global [%0], [%1], 16;"
                 :: "r"(saddr), "l"(gptr) : "memory");
}

// ============== mma.sync fp16 2-limb 3-pass GEMM, cp.async 2-stage (R8 engine) ====
// EPI: 0=fp32 plain, 1=resid+dyntanh->limbs, 2=gelu(bias)+dyntanh->limbs
template <int NT, int EPI>
__global__ __launch_bounds__(256) void mmagemm(
        const __half* __restrict__ A0, const __half* __restrict__ A1,
        const __half* __restrict__ B0, const __half* __restrict__ B1,
        int Kp,
        float* __restrict__ outF, int ldoF,
        __half* __restrict__ O0, __half* __restrict__ O1, int ldoL,
        const float* __restrict__ bias, const float* __restrict__ resid, int ldr,
        const float* __restrict__ alpha_p,
        const float* __restrict__ gv, const float* __restrict__ bv) {
    extern __shared__ __half sm[];
    constexpr int NF = NT / 32;
    constexpr int ROWB = 144;
    constexpr int ABYTES = 128 * ROWB;
    constexpr int STAGE = (128 + NT) * ROWB;

    uint32_t sbase = smem_u32(sm);
    int tid = threadIdx.x, lane = tid & 31, wid = tid >> 5;
    int wm = wid & 1, wn = wid >> 1;
    int bm = blockIdx.y * 128, bn = blockIdx.x * NT;
    int nch = Kp >> 6;
    int nit = 3 * nch;

    float acc[4][NF][4];
#pragma unroll
    for (int i = 0; i < 4; i++)
#pragma unroll
        for (int j = 0; j < NF; j++)
#pragma unroll
            for (int c = 0; c < 4; c++) acc[i][j][c] = 0.f;

    auto issue = [&](int it, int s) {
        int t = it / nch, c = it - (it / nch) * nch;
        const __half* Ab = (t == 2) ? A1 : A0;
        const __half* Bb = (t == 1) ? B1 : B0;
        uint32_t abase = sbase + (uint32_t)s * STAGE;
#pragma unroll
        for (int q = 0; q < 4; q++) {
            int idx = tid + q * 256;
            int row = idx >> 3, cg = idx & 7;
            cpasync16(abase + row * ROWB + cg * 16,
                      Ab + (size_t)(bm + row) * Kp + c * 64 + cg * 8);
        }
        uint32_t bbase = abase + ABYTES;
#pragma unroll
        for (int q = 0; q < NF; q++) {
            int idx = tid + q * 256;
            int row = idx >> 3, cg = idx & 7;
            cpasync16(bbase + row * ROWB + cg * 16,
                      Bb + (size_t)(bn + row) * Kp + c * 64 + cg * 8);
        }
        asm volatile("cp.async.commit_group;" ::: "memory");
    };

    issue(0, 0);

#pragma unroll 1
    for (int it = 0; it < nit; it++) {
        int s = it & 1;
        if (it + 1 < nit) {
            issue(it + 1, s ^ 1);
            asm volatile("cp.async.wait_group 1;" ::: "memory");
        } else {
            asm volatile("cp.async.wait_group 0;" ::: "memory");
        }
        __syncthreads();

        uint32_t abase = sbase + (uint32_t)s * STAGE;
        uint32_t bbase = abase + ABYTES;
#pragma unroll
        for (int kk = 0; kk < 4; kk++) {
            int k = kk * 16;
            int arow = wm * 64 + (lane & 15);
            int acol = k + (lane >> 4) * 8;
            int g = lane >> 3;
            int nr = wn * (NT / 4) + ((g >> 1) << 3) + (lane & 7);
            int kc = k + (g & 1) * 8;

            uint32_t a[4][4];
#pragma unroll
            for (int i = 0; i < 4; i++)
                ldsm4(a[i], abase + (arow + i * 16) * ROWB + acol * 2);
            uint32_t b[NF][2];
#pragma unroll
            for (int jj = 0; jj < NF / 2; jj++) {
                uint32_t tmp[4];
                ldsm4(tmp, bbase + (nr + jj * 16) * ROWB + kc * 2);
                b[2 * jj][0] = tmp[0]; b[2 * jj][1] = tmp[1];
                b[2 * jj + 1][0] = tmp[2]; b[2 * jj + 1][1] = tmp[3];
            }
#pragma unroll
            for (int i = 0; i < 4; i++)
#pragma unroll
                for (int j = 0; j < NF; j++) mma16816(acc[i][j], a[i], b[j]);
        }
        __syncthreads();
    }

    float alpha = (EPI == 1 || EPI == 2) ? *alpha_p : 0.f;
    int gid = lane >> 2, tig = lane & 3;
#pragma unroll
    for (int i = 0; i < 4; i++) {
#pragma unroll
        for (int j = 0; j < NF; j++) {
#pragma unroll
            for (int cc = 0; cc < 4; cc++) {
                int m = bm + wm * 64 + i * 16 + gid + (cc >> 1) * 8;
                int ncol = bn + wn * (NT / 4) + j * 8 + tig * 2 + (cc & 1);
                float v = acc[i][j][cc];
                if (EPI == 0) {
                    outF[(size_t)m * ldoF + ncol] = v;
                } else if (EPI == 1) {
                    v += resid[(size_t)m * ldr + ncol];
                    v = tanhf(alpha * v) * gv[ncol] + bv[ncol];
                    store2(O0, O1, (size_t)m * ldoL + ncol, v);
                } else if (EPI == 2) {
                    v = gelu_tanh(v + bias[ncol]);
                    v = tanhf(alpha * v) * gv[ncol] + bv[ncol];
                    store2(O0, O1, (size_t)m * ldoL + ncol, v);
                }
            }
        }
    }
}

// ============== fused Z-GEMM (M-tile 64, N=64) + tanh(gelu) + VQ ==============
// Computes z = tanh(gelu(H2 @ Wout + bout)) for 64 nodes, then argmin over the
// codebook, writes codebook[best] to out and squared-error partial to g_part.
__global__ __launch_bounds__(256) void zvq_kernel(
        const __half* __restrict__ A0, const __half* __restrict__ A1,
        const __half* __restrict__ B0, const __half* __restrict__ B1,
        int Kp, const float* __restrict__ bias,
        const float* __restrict__ cb, float* __restrict__ out) {
    extern __shared__ char smz[];
    constexpr int ROWB = 144;
    constexpr int ABYTES = 64 * ROWB;
    constexpr int STAGE = (64 + 64) * ROWB;          // 18432
    constexpr int STAGES_SZ = 2 * STAGE;             // 36864
    float(*zbuf)[65] = (float(*)[65])(smz + STAGES_SZ);
    float(*cbs)[65] = (float(*)[65])(smz + STAGES_SZ + 16640);
    float* cn = (float*)(smz + STAGES_SZ + 2 * 16640);

    uint32_t sbase = smem_u32(smz);
    int tid = threadIdx.x, lane = tid & 31, wid = tid >> 5;
    int wm = wid & 1, wn = wid >> 1;
    int bm = blockIdx.y * 64;
    int nch = Kp >> 6;
    int nit = 3 * nch;

    // load codebook into padded smem + norms
    for (int i = tid; i < 4096; i += 256) cbs[i >> 6][i & 63] = cb[i];
    __syncthreads();
    if (tid < 64) {
        float s = 0.f;
#pragma unroll 8
        for (int d = 0; d < 64; d++) s = fmaf(cbs[tid][d], cbs[tid][d], s);
        cn[tid] = s;
    }

    float acc[2][2][4];
#pragma unroll
    for (int i = 0; i < 2; i++)
#pragma unroll
        for (int j = 0; j < 2; j++)
#pragma unroll
            for (int c = 0; c < 4; c++) acc[i][j][c] = 0.f;

    auto issue = [&](int it, int s) {
        int t = it / nch, c = it - (it / nch) * nch;
        const __half* Ab = (t == 2) ? A1 : A0;
        const __half* Bb = (t == 1) ? B1 : B0;
        uint32_t abase = sbase + (uint32_t)s * STAGE;
#pragma unroll
        for (int q = 0; q < 2; q++) {
            int idx = tid + q * 256;
            int row = idx >> 3, cg = idx & 7;
            cpasync16(abase + row * ROWB + cg * 16,
                      Ab + (size_t)(bm + row) * Kp + c * 64 + cg * 8);
        }
        uint32_t bbase = abase + ABYTES;
#pragma unroll
        for (int q = 0; q < 2; q++) {
            int idx = tid + q * 256;
            int row = idx >> 3, cg = idx & 7;
            cpasync16(bbase + row * ROWB + cg * 16,
                      Bb + (size_t)row * Kp + c * 64 + cg * 8);
        }
        asm volatile("cp.async.commit_group;" ::: "memory");
    };

    issue(0, 0);

#pragma unroll 1
    for (int it = 0; it < nit; it++) {
        int s = it & 1;
        if (it + 1 < nit) {
            issue(it + 1, s ^ 1);
            asm volatile("cp.async.wait_group 1;" ::: "memory");
        } else {
            asm volatile("cp.async.wait_group 0;" ::: "memory");
        }
        __syncthreads();

        uint32_t abase = sbase + (uint32_t)s * STAGE;
        uint32_t bbase = abase + ABYTES;
#pragma unroll
        for (int kk = 0; kk < 4; kk++) {
            int k = kk * 16;
            int arow = wm * 32 + (lane & 15);
            int acol = k + (lane >> 4) * 8;
            int g = lane >> 3;
            int nr = wn * 16 + ((g >> 1) << 3) + (lane & 7);
            int kc = k + (g & 1) * 8;

            uint32_t a[2][4];
#pragma unroll
            for (int i = 0; i < 2; i++)
                ldsm4(a[i], abase + (arow + i * 16) * ROWB + acol * 2);
            uint32_t b[2][2];
            {
                uint32_t tmp[4];
                ldsm4(tmp, bbase + nr * ROWB + kc * 2);
                b[0][0] = tmp[0]; b[0][1] = tmp[1];
                b[1][0] = tmp[2]; b[1][1] = tmp[3];
            }
#pragma unroll
            for (int i = 0; i < 2; i++)
#pragma unroll
                for (int j = 0; j < 2; j++) mma16816(acc[i][j], a[i], b[j]);
        }
        __syncthreads();
    }

    // stage z tile into smem
    int gid = lane >> 2, tig = lane & 3;
#pragma unroll
    for (int i = 0; i < 2; i++) {
#pragma unroll
        for (int j = 0; j < 2; j++) {
#pragma unroll
            for (int cc = 0; cc < 4; cc++) {
                int mrow = wm * 32 + i * 16 + gid + (cc >> 1) * 8;
                int ncol = wn * 16 + j * 8 + tig * 2 + (cc & 1);
                zbuf[mrow][ncol] = tanhf(gelu_tanh(acc[i][j][cc] + bias[ncol]));
            }
        }
    }
    __syncthreads();

    // VQ: warp wid handles 8 nodes
#pragma unroll 1
    for (int q = 0; q < 8; q++) {
        int ln = wid * 8 + q;
        int n = bm + ln;
        float dota = 0.f, dotb = 0.f;
#pragma unroll 8
        for (int d = 0; d < 64; d++) {
            float z = zbuf[ln][d];
            dota = fmaf(z, cbs[lane][d], dota);
            dotb = fmaf(z, cbs[lane + 32][d], dotb);
        }
        float d2a = cn[lane] - 2.f * dota;
        float d2b = cn[lane + 32] - 2.f * dotb;
        float sc;
        int bi;
        if (d2a <= d2b) { sc = d2a; bi = lane; }
        else            { sc = d2b; bi = lane + 32; }
#pragma unroll
        for (int o = 16; o; o >>= 1) {
            float osc = __shfl_xor_sync(0xffffffffu, sc, o);
            int obi = __shfl_xor_sync(0xffffffffu, bi, o);
            if (osc < sc || (osc == sc && obi < bi)) { sc = osc; bi = obi; }
        }
        float zq0 = cbs[bi][lane];
        float zq1 = cbs[bi][lane + 32];
        out[(size_t)n * 64 + lane] = zq0;
        out[(size_t)n * 64 + lane + 32] = zq1;
        float d0 = zbuf[ln][lane] - zq0;
        float d1 = zbuf[ln][lane + 32] - zq1;
        float df = d0 * d0 + d1 * d1;
#pragma unroll
        for (int o = 16; o; o >>= 1) df += __shfl_xor_sync(0xffffffffu, df, o);
        if (lane == 0) g_part[n] = df;
    }
}

// ---------------- conversions ----------------
__global__ void convA_kernel(const float* __restrict__ src, __half* d0, __half* d1, int n) {
    int t = blockIdx.x * blockDim.x + threadIdx.x;
    if (t >= n) return;
    store2(d0, d1, t, src[t]);
}

__global__ void convB_kernel(const float* __restrict__ src, __half* d0, __half* d1,
                             int K, int N, int Kp) {
    int t = blockIdx.x * blockDim.x + threadIdx.x;
    if (t >= N * K) return;
    int n = t / K, k = t - n * K;
    store2(d0, d1, (size_t)n * Kp + k, src[(size_t)k * N + n]);
}

__global__ void convBqkv_kernel(const float* __restrict__ Wq, const float* __restrict__ Wk,
                                const float* __restrict__ Wv, __half* d0, __half* d1) {
    int t = blockIdx.x * blockDim.x + threadIdx.x;
    if (t >= QKVW * CC) return;
    int n = t >> 8, k = t & 255;
    const float* s = (n < 512) ? Wq : ((n < 1024) ? Wk : Wv);
    int col = n & 511;
    store2(d0, d1, (size_t)n * CC + k, s[(size_t)k * 512 + col]);
}

// ---------------- gate projection: warp per node ----------------
__global__ void gate_kernel(const float* __restrict__ x, const float* __restrict__ wg) {
    int wid = threadIdx.x >> 5, lane = threadIdx.x & 31;
    int n = blockIdx.x * 8 + wid;
    if (n >= NN) return;
    const float* xr = x + (size_t)n * CC;
    float4 v0 = *(const float4*)(xr + lane * 8);
    float4 v1 = *(const float4*)(xr + lane * 8 + 4);
    float xv[8] = {v0.x, v0.y, v0.z, v0.w, v1.x, v1.y, v1.z, v1.w};
#pragma unroll
    for (int h = 0; h < 8; h++) {
        float p = 0.f;
#pragma unroll
        for (int i = 0; i < 8; i++) p = fmaf(xv[i], wg[(lane * 8 + i) * 8 + h], p);
#pragma unroll
        for (int o = 16; o; o >>= 1) p += __shfl_xor_sync(0xffffffffu, p, o);
        if (lane == 0) g_G[(size_t)n * 8 + h] = p;
    }
}

// ---------------- attention: block per node, warp per head; writes Att limbs ------
__global__ void attn_kernel(const float* __restrict__ coors, const int* __restrict__ nbr,
                            const float* __restrict__ Wr1, const float* __restrict__ br1,
                            const float* __restrict__ Wr2, const float* __restrict__ br2) {
    int n = blockIdx.x;
    int tid = threadIdx.x;
    __shared__ int s_nbr[8];
    __shared__ float s_dist[8];
    __shared__ float s_unit[8][3];
    __shared__ float s_rad[8][8];
    __shared__ float s_gate[8][8];

    if (tid < 8) s_nbr[tid] = nbr[(size_t)n * 8 + tid];
    __syncthreads();
    if (tid < 8) {
        int j = tid;
        float cx = coors[(size_t)n * 3], cy = coors[(size_t)n * 3 + 1], cz = coors[(size_t)n * 3 + 2];
        int mm = s_nbr[j];
        float rx = coors[(size_t)mm * 3] - cx;
        float ry = coors[(size_t)mm * 3 + 1] - cy;
        float rz = coors[(size_t)mm * 3 + 2] - cz;
        float d = sqrtf(rx * rx + ry * ry + rz * rz + 1e-8f);
        s_dist[j] = d;
        s_unit[j][0] = rx / d;
        s_unit[j][1] = ry / d;
        s_unit[j][2] = rz / d;
    }
    __syncthreads();
    if (tid < 64) {
        int j = tid >> 3, h = tid & 7;
        float d = s_dist[j];
        float acc = br2[h];
#pragma unroll
        for (int i = 0; i < 16; i++)
            acc = fmaf(gelu_tanh(d * Wr1[i] + br1[i]), Wr2[i * 8 + h], acc);
        s_rad[j][h] = acc;
        s_gate[j][h] = g_G[(size_t)s_nbr[j] * HH + h];
    }
    __syncthreads();

    int w = tid >> 5, lane = tid & 31;
    int h = w;
    const float* qr = g_QKV + (size_t)n * QKVW + h * 64;
    float q0 = qr[lane * 2], q1 = qr[lane * 2 + 1];
    float logit[8];
#pragma unroll
    for (int j = 0; j < 8; j++) {
        const float* kr = g_QKV + (size_t)s_nbr[j] * QKVW + 512 + h * 64;
        float p = q0 * kr[lane * 2] + q1 * kr[lane * 2 + 1];
#pragma unroll
        for (int o = 16; o; o >>= 1) p += __shfl_xor_sync(0xffffffffu, p, o);
        p = p * 0.125f + s_rad[j][h];
        logit[j] = (s_dist[j] <= 10.0f) ? p : -1e9f;
    }
    float mx = logit[0];
#pragma unroll
    for (int j = 1; j < 8; j++) mx = fmaxf(mx, logit[j]);
    float e[8];
    float se = 0.f;
#pragma unroll
    for (int j = 0; j < 8; j++) { e[j] = expf(logit[j] - mx); se += e[j]; }
    float inv = 1.f / se;
    float a0 = 0.f, a1 = 0.f;
#pragma unroll
    for (int j = 0; j < 8; j++) {
        float at = e[j] * inv;
        const float* vr = g_QKV + (size_t)s_nbr[j] * QKVW + 1024 + h * 64;
        a0 = fmaf(at, vr[lane * 2], a0);
        a1 = fmaf(at, vr[lane * 2 + 1], a1);
    }
    size_t base = (size_t)n * ATTKP + h * 64 + lane * 2;
    store2(g_Al0, g_Al1, base, a0);
    store2(g_Al0, g_Al1, base + 1, a1);
    if (lane == 0) {
        float vx = 0.f, vy = 0.f, vz = 0.f;
#pragma unroll
        for (int j = 0; j < 8; j++) {
            float wg = e[j] * inv * s_gate[j][h];
            vx = fmaf(wg, s_unit[j][0], vx);
            vy = fmaf(wg, s_unit[j][1], vy);
            vz = fmaf(wg, s_unit[j][2], vz);
        }
        float vn = sqrtf(vx * vx + vy * vy + vz * vz + 1e-8f);
        store2(g_Al0, g_Al1, (size_t)n * ATTKP + 512 + h, vn);
    }
}

// ---------------- H2 extra columns (aa feats through dyntanh2) -> limbs ----------
__global__ void h2extra_kernel(const float* __restrict__ x, const float* __restrict__ alpha2,
                               const float* __restrict__ g2, const float* __restrict__ b2) {
    int t = blockIdx.x * blockDim.x + threadIdx.x;
    if (t >= NN * 20) return;
    int n = t / 20, j = t % 20;
    float a = *alpha2;
    float v = tanhf(a * x[(size_t)n * CC + j]) * g2[512 + j] + b2[512 + j];
    store2(g_Hl0, g_Hl1, (size_t)n * H2KP + 512 + j, v);
}

__global__ void loss_reduce_kernel(float* __restrict__ out) {
    __shared__ double s_s[32];
    int tid = threadIdx.x;
    double s = 0.0;
    for (int i = tid; i < NN; i += 1024) s += (double)g_part[i];
#pragma unroll
    for (int o = 16; o; o >>= 1) s += __shfl_xor_sync(0xffffffffu, s, o);
    if ((tid & 31) == 0) s_s[tid >> 5] = s;
    __syncthreads();
    if (tid == 0) {
        double tot = 0.0;
        for (int i = 0; i < 32; i++) tot += s_s[i];
        out[(size_t)NN * OUTD] = (float)(0.25 * tot / (double)((size_t)NN * OUTD));
    }
}

// ---------------- launch ----------------
extern "C" void kernel_launch(void* const* d_in, const int* in_sizes, int n_in,
                              void* d_out, int out_size) {
    const float *x, *coors, *Wq, *Wk, *Wv, *wg, *Wr1, *br1, *Wr2, *br2, *Wo;
    const float *a1, *g1, *b1, *Wlin, *blin, *a2, *g2, *b2, *Wout, *bout, *cb;
    const int* nbr;

    if (n_in > 5 && in_sizes[5] == 2048) {
        x = (const float*)d_in[0];   coors = (const float*)d_in[1];
        Wq = (const float*)d_in[2];  Wk = (const float*)d_in[3];  Wv = (const float*)d_in[4];
        wg = (const float*)d_in[5];  Wr1 = (const float*)d_in[6]; br1 = (const float*)d_in[7];
        Wr2 = (const float*)d_in[8]; br2 = (const float*)d_in[9]; Wo = (const float*)d_in[10];
        a1 = (const float*)d_in[11]; g1 = (const float*)d_in[12]; b1 = (const float*)d_in[13];
        Wlin = (const float*)d_in[14]; blin = (const float*)d_in[15];
        a2 = (const float*)d_in[16]; g2 = (const float*)d_in[17]; b2 = (const float*)d_in[18];
        Wout = (const float*)d_in[19]; bout = (const float*)d_in[20];
        cb = (const float*)d_in[21]; nbr = (const int*)d_in[22];
    } else {
        x = (const float*)d_in[0];   coors = (const float*)d_in[1];
        nbr = (const int*)d_in[2];
        Wq = (const float*)d_in[3];  Wk = (const float*)d_in[4];  Wv = (const float*)d_in[5];
        wg = (const float*)d_in[6];  Wr1 = (const float*)d_in[7]; br1 = (const float*)d_in[8];
        Wr2 = (const float*)d_in[9]; br2 = (const float*)d_in[10]; Wo = (const float*)d_in[11];
        a1 = (const float*)d_in[12]; g1 = (const float*)d_in[13]; b1 = (const float*)d_in[14];
        Wlin = (const float*)d_in[15]; blin = (const float*)d_in[16];
        a2 = (const float*)d_in[17]; g2 = (const float*)d_in[18]; b2 = (const float*)d_in[19];
        Wout = (const float*)d_in[20]; bout = (const float*)d_in[21];
        cb = (const float*)d_in[22];
    }

    float* pQKV;
    cudaGetSymbolAddress((void**)&pQKV, g_QKV);
    __half *xl0, *xl1, *Al0, *Al1, *Tl0, *Tl1, *Hl0, *Hl1;
    cudaGetSymbolAddress((void**)&xl0, g_xl0); cudaGetSymbolAddress((void**)&xl1, g_xl1);
    cudaGetSymbolAddress((void**)&Al0, g_Al0); cudaGetSymbolAddress((void**)&Al1, g_Al1);
    cudaGetSymbolAddress((void**)&Tl0, g_Tl0); cudaGetSymbolAddress((void**)&Tl1, g_Tl1);
    cudaGetSymbolAddress((void**)&Hl0, g_Hl0); cudaGetSymbolAddress((void**)&Hl1, g_Hl1);
    __half *Bq0, *Bq1, *Bo0, *Bo1, *Bl0, *Bl1, *Bu0, *Bu1;
    cudaGetSymbolAddress((void**)&Bq0, g_Bq0); cudaGetSymbolAddress((void**)&Bq1, g_Bq1);
    cudaGetSymbolAddress((void**)&Bo0, g_Bo0); cudaGetSymbolAddress((void**)&Bo1, g_Bo1);
    cudaGetSymbolAddress((void**)&Bl0, g_Bl0); cudaGetSymbolAddress((void**)&Bl1, g_Bl1);
    cudaGetSymbolAddress((void**)&Bu0, g_Bu0); cudaGetSymbolAddress((void**)&Bu1, g_Bu1);

    float* out = (float*)d_out;

    constexpr int SM128 = 2 * (128 + 128) * 144;          // 73728
    constexpr int SMZ = 2 * (64 + 64) * 144 + 2 * 16640 + 256;  // 70400
    cudaFuncSetAttribute(mmagemm<128, 0>, cudaFuncAttributeMaxDynamicSharedMemorySize, SM128);
    cudaFuncSetAttribute(mmagemm<128, 1>, cudaFuncAttributeMaxDynamicSharedMemorySize, SM128);
    cudaFuncSetAttribute(mmagemm<128, 2>, cudaFuncAttributeMaxDynamicSharedMemorySize, SM128);
    cudaFuncSetAttribute(zvq_kernel, cudaFuncAttributeMaxDynamicSharedMemorySize, SMZ);

    // launch order keeps mmagemm<128,0> in the ncu capture slot (#4)
    convA_kernel<<<(NN * CC + 255) / 256, 256>>>(x, xl0, xl1, NN * CC);          // 1
    convBqkv_kernel<<<(QKVW * CC + 255) / 256, 256>>>(Wq, Wk, Wv, Bq0, Bq1);     // 2
    gate_kernel<<<NN / 8, 256>>>(x, wg);                                         // 3

    // QKV = x @ [Wq|Wk|Wv]  -> fp32                                             // 4
    mmagemm<128, 0><<<dim3(QKVW / 128, NN / 128), 256, SM128>>>(
        xl0, xl1, Bq0, Bq1, CC,
        pQKV, QKVW, nullptr, nullptr, 0,
        nullptr, nullptr, 0, nullptr, nullptr, nullptr);

    convB_kernel<<<(CC * 520 + 255) / 256, 256>>>(Wo, Bo0, Bo1, 520, CC, ATTKP); // 5
    attn_kernel<<<NN, 256>>>(coors, nbr, Wr1, br1, Wr2, br2);                    // 6

    // T = dyntanh(x + Att@Wo) -> limbs
    mmagemm<128, 1><<<dim3(CC / 128, NN / 128), 256, SM128>>>(
        Al0, Al1, Bo0, Bo1, ATTKP,
        nullptr, 0, Tl0, Tl1, CC,
        nullptr, x, CC, a1, g1, b1);

    convB_kernel<<<(HIDD * CC + 255) / 256, 256>>>(Wlin, Bl0, Bl1, CC, HIDD, CC);

    // H2[:, :512] = dyntanh2(gelu(T@Wlin + blin)) -> limbs
    mmagemm<128, 2><<<dim3(HIDD / 128, NN / 128), 256, SM128>>>(
        Tl0, Tl1, Bl0, Bl1, CC,
        nullptr, 0, Hl0, Hl1, H2KP,
        blin, nullptr, 0, a2, g2, b2);
    h2extra_kernel<<<(NN * 20 + 255) / 256, 256>>>(x, a2, g2, b2);
    convB_kernel<<<(OUTD * 532 + 255) / 256, 256>>>(Wout, Bu0, Bu1, 532, OUTD, H2KP);

    // fused Z gemm + VQ
    zvq_kernel<<<dim3(1, NN / 64), 256, SMZ>>>(
        Hl0, Hl1, Bu0, Bu1, H2KP, bout, cb, out);

    if (out_size > NN * OUTD) loss_reduce_kernel<<<1, 1024>>>(out);
}

// round 11
// speedup vs baseline: 1.4258x; 1.0173x over previous
#include <cuda_runtime.h>
#include <cuda_fp16.h>
#include <math.h>
#include <cstdint>

#define NN 16384
#define CC 256
#define HH 8
#define HD 512
#define QKVW 1536
#define HIDD 512
#define OUTD 64
#define H2D 532
#define ATTKP 576   // 520 padded to 64-multiple
#define H2KP 576    // 532 padded

// ---------------- scratch (static device arrays; no allocation) ----------------
__device__ float g_QKV[NN * QKVW];          // fp32 Q|K|V for attention
__device__ float g_G[NN * HH];
__device__ float g_part[NN];                // per-node vq loss partials

// activation fp16 limbs (zero-init pads stay zero forever)
__device__ __half g_xl0[NN * CC], g_xl1[NN * CC];
__device__ __half g_Al0[NN * ATTKP], g_Al1[NN * ATTKP];
__device__ __half g_Tl0[NN * CC], g_Tl1[NN * CC];
__device__ __half g_Hl0[NN * H2KP], g_Hl1[NN * H2KP];

// weight fp16 limbs, [N, Kp] K-major
__device__ __half g_Bq0[QKVW * CC], g_Bq1[QKVW * CC];
__device__ __half g_Bo0[CC * ATTKP], g_Bo1[CC * ATTKP];
__device__ __half g_Bl0[HIDD * CC], g_Bl1[HIDD * CC];
__device__ __half g_Bu0[OUTD * H2KP], g_Bu1[OUTD * H2KP];

// ---------------- helpers ----------------
__device__ __forceinline__ float gelu_tanh(float x) {
    float x3 = x * x * x;
    return 0.5f * x * (1.0f + tanhf(0.7978845608028654f * (x + 0.044715f * x3)));
}

__device__ __forceinline__ void store2(__half* p0, __half* p1, size_t off, float v) {
    __half h0 = __float2half_rn(v);
    __half h1 = __float2half_rn(v - __half2float(h0));
    p0[off] = h0;
    p1[off] = h1;
}

__device__ __forceinline__ uint32_t smem_u32(const void* p) {
    uint32_t a;
    asm("{ .reg .u64 t; cvta.to.shared.u64 t, %1; cvt.u32.u64 %0, t; }" : "=r"(a) : "l"(p));
    return a;
}

__device__ __forceinline__ void ldsm4(uint32_t* r, uint32_t addr) {
    asm volatile("ldmatrix.sync.aligned.m8n8.x4.shared.b16 {%0,%1,%2,%3}, [%4];"
                 : "=r"(r[0]), "=r"(r[1]), "=r"(r[2]), "=r"(r[3]) : "r"(addr));
}

__device__ __forceinline__ void mma16816(float* c, const uint32_t* a, const uint32_t* b) {
    asm volatile(
        "mma.sync.aligned.m16n8k16.row.col.f32.f16.f16.f32 "
        "{%0,%1,%2,%3}, {%4,%5,%6,%7}, {%8,%9}, {%0,%1,%2,%3};"
        : "+f"(c[0]), "+f"(c[1]), "+f"(c[2]), "+f"(c[3])
        : "r"(a[0]), "r"(a[1]), "r"(a[2]), "r"(a[3]), "r"(b[0]), "r"(b[1]));
}

__device__ __forceinline__ void cpasync16(uint32_t saddr, const void* gptr) {
    asm volatile("cp.async.cg.shared.global [%0], [%1], 16;"
                 :: "r"(saddr), "l"(gptr) : "memory");
}

// ============== mma.sync fp16 2-limb 3-pass GEMM, cp.async 2-stage (R8 engine) ====
// EPI: 0=fp32 plain, 1=resid+dyntanh->limbs, 2=gelu(bias)+dyntanh->limbs
template <int NT, int EPI>
__global__ __launch_bounds__(256) void mmagemm(
        const __half* __restrict__ A0, const __half* __restrict__ A1,
        const __half* __restrict__ B0, const __half* __restrict__ B1,
        int Kp,
        float* __restrict__ outF, int ldoF,
        __half* __restrict__ O0, __half* __restrict__ O1, int ldoL,
        const float* __restrict__ bias, const float* __restrict__ resid, int ldr,
        const float* __restrict__ alpha_p,
        const float* __restrict__ gv, const float* __restrict__ bv) {
    extern __shared__ __half sm[];
    constexpr int NF = NT / 32;
    constexpr int ROWB = 144;
    constexpr int ABYTES = 128 * ROWB;
    constexpr int STAGE = (128 + NT) * ROWB;

    uint32_t sbase = smem_u32(sm);
    int tid = threadIdx.x, lane = tid & 31, wid = tid >> 5;
    int wm = wid & 1, wn = wid >> 1;
    int bm = blockIdx.y * 128, bn = blockIdx.x * NT;
    int nch = Kp >> 6;
    int nit = 3 * nch;

    float acc[4][NF][4];
#pragma unroll
    for (int i = 0; i < 4; i++)
#pragma unroll
        for (int j = 0; j < NF; j++)
#pragma unroll
            for (int c = 0; c < 4; c++) acc[i][j][c] = 0.f;

    auto issue = [&](int it, int s) {
        int t = it / nch, c = it - (it / nch) * nch;
        const __half* Ab = (t == 2) ? A1 : A0;
        const __half* Bb = (t == 1) ? B1 : B0;
        uint32_t abase = sbase + (uint32_t)s * STAGE;
#pragma unroll
        for (int q = 0; q < 4; q++) {
            int idx = tid + q * 256;
            int row = idx >> 3, cg = idx & 7;
            cpasync16(abase + row * ROWB + cg * 16,
                      Ab + (size_t)(bm + row) * Kp + c * 64 + cg * 8);
        }
        uint32_t bbase = abase + ABYTES;
#pragma unroll
        for (int q = 0; q < NF; q++) {
            int idx = tid + q * 256;
            int row = idx >> 3, cg = idx & 7;
            cpasync16(bbase + row * ROWB + cg * 16,
                      Bb + (size_t)(bn + row) * Kp + c * 64 + cg * 8);
        }
        asm volatile("cp.async.commit_group;" ::: "memory");
    };

    issue(0, 0);

#pragma unroll 1
    for (int it = 0; it < nit; it++) {
        int s = it & 1;
        if (it + 1 < nit) {
            issue(it + 1, s ^ 1);
            asm volatile("cp.async.wait_group 1;" ::: "memory");
        } else {
            asm volatile("cp.async.wait_group 0;" ::: "memory");
        }
        __syncthreads();

        uint32_t abase = sbase + (uint32_t)s * STAGE;
        uint32_t bbase = abase + ABYTES;
#pragma unroll
        for (int kk = 0; kk < 4; kk++) {
            int k = kk * 16;
            int arow = wm * 64 + (lane & 15);
            int acol = k + (lane >> 4) * 8;
            int g = lane >> 3;
            int nr = wn * (NT / 4) + ((g >> 1) << 3) + (lane & 7);
            int kc = k + (g & 1) * 8;

            uint32_t a[4][4];
#pragma unroll
            for (int i = 0; i < 4; i++)
                ldsm4(a[i], abase + (arow + i * 16) * ROWB + acol * 2);
            uint32_t b[NF][2];
#pragma unroll
            for (int jj = 0; jj < NF / 2; jj++) {
                uint32_t tmp[4];
                ldsm4(tmp, bbase + (nr + jj * 16) * ROWB + kc * 2);
                b[2 * jj][0] = tmp[0]; b[2 * jj][1] = tmp[1];
                b[2 * jj + 1][0] = tmp[2]; b[2 * jj + 1][1] = tmp[3];
            }
#pragma unroll
            for (int i = 0; i < 4; i++)
#pragma unroll
                for (int j = 0; j < NF; j++) mma16816(acc[i][j], a[i], b[j]);
        }
        __syncthreads();
    }

    float alpha = (EPI == 1 || EPI == 2) ? *alpha_p : 0.f;
    int gid = lane >> 2, tig = lane & 3;
#pragma unroll
    for (int i = 0; i < 4; i++) {
#pragma unroll
        for (int j = 0; j < NF; j++) {
#pragma unroll
            for (int cc = 0; cc < 4; cc++) {
                int m = bm + wm * 64 + i * 16 + gid + (cc >> 1) * 8;
                int ncol = bn + wn * (NT / 4) + j * 8 + tig * 2 + (cc & 1);
                float v = acc[i][j][cc];
                if (EPI == 0) {
                    outF[(size_t)m * ldoF + ncol] = v;
                } else if (EPI == 1) {
                    v += resid[(size_t)m * ldr + ncol];
                    v = tanhf(alpha * v) * gv[ncol] + bv[ncol];
                    store2(O0, O1, (size_t)m * ldoL + ncol, v);
                } else if (EPI == 2) {
                    v = gelu_tanh(v + bias[ncol]);
                    v = tanhf(alpha * v) * gv[ncol] + bv[ncol];
                    store2(O0, O1, (size_t)m * ldoL + ncol, v);
                }
            }
        }
    }
}

// ============== fused Z-GEMM (M-tile 64, N=64) + tanh(gelu) + VQ ==============
__global__ __launch_bounds__(256) void zvq_kernel(
        const __half* __restrict__ A0, const __half* __restrict__ A1,
        const __half* __restrict__ B0, const __half* __restrict__ B1,
        int Kp, const float* __restrict__ bias,
        const float* __restrict__ cb, float* __restrict__ out) {
    extern __shared__ char smz[];
    constexpr int ROWB = 144;
    constexpr int ABYTES = 64 * ROWB;
    constexpr int STAGE = (64 + 64) * ROWB;
    constexpr int STAGES_SZ = 2 * STAGE;
    float(*zbuf)[65] = (float(*)[65])(smz + STAGES_SZ);
    float(*cbs)[65] = (float(*)[65])(smz + STAGES_SZ + 16640);
    float* cn = (float*)(smz + STAGES_SZ + 2 * 16640);

    uint32_t sbase = smem_u32(smz);
    int tid = threadIdx.x, lane = tid & 31, wid = tid >> 5;
    int wm = wid & 1, wn = wid >> 1;
    int bm = blockIdx.y * 64;
    int nch = Kp >> 6;
    int nit = 3 * nch;

    for (int i = tid; i < 4096; i += 256) cbs[i >> 6][i & 63] = cb[i];
    __syncthreads();
    if (tid < 64) {
        float s = 0.f;
#pragma unroll 8
        for (int d = 0; d < 64; d++) s = fmaf(cbs[tid][d], cbs[tid][d], s);
        cn[tid] = s;
    }

    float acc[2][2][4];
#pragma unroll
    for (int i = 0; i < 2; i++)
#pragma unroll
        for (int j = 0; j < 2; j++)
#pragma unroll
            for (int c = 0; c < 4; c++) acc[i][j][c] = 0.f;

    auto issue = [&](int it, int s) {
        int t = it / nch, c = it - (it / nch) * nch;
        const __half* Ab = (t == 2) ? A1 : A0;
        const __half* Bb = (t == 1) ? B1 : B0;
        uint32_t abase = sbase + (uint32_t)s * STAGE;
#pragma unroll
        for (int q = 0; q < 2; q++) {
            int idx = tid + q * 256;
            int row = idx >> 3, cg = idx & 7;
            cpasync16(abase + row * ROWB + cg * 16,
                      Ab + (size_t)(bm + row) * Kp + c * 64 + cg * 8);
        }
        uint32_t bbase = abase + ABYTES;
#pragma unroll
        for (int q = 0; q < 2; q++) {
            int idx = tid + q * 256;
            int row = idx >> 3, cg = idx & 7;
            cpasync16(bbase + row * ROWB + cg * 16,
                      Bb + (size_t)row * Kp + c * 64 + cg * 8);
        }
        asm volatile("cp.async.commit_group;" ::: "memory");
    };

    issue(0, 0);

#pragma unroll 1
    for (int it = 0; it < nit; it++) {
        int s = it & 1;
        if (it + 1 < nit) {
            issue(it + 1, s ^ 1);
            asm volatile("cp.async.wait_group 1;" ::: "memory");
        } else {
            asm volatile("cp.async.wait_group 0;" ::: "memory");
        }
        __syncthreads();

        uint32_t abase = sbase + (uint32_t)s * STAGE;
        uint32_t bbase = abase + ABYTES;
#pragma unroll
        for (int kk = 0; kk < 4; kk++) {
            int k = kk * 16;
            int arow = wm * 32 + (lane & 15);
            int acol = k + (lane >> 4) * 8;
            int g = lane >> 3;
            int nr = wn * 16 + ((g >> 1) << 3) + (lane & 7);
            int kc = k + (g & 1) * 8;

            uint32_t a[2][4];
#pragma unroll
            for (int i = 0; i < 2; i++)
                ldsm4(a[i], abase + (arow + i * 16) * ROWB + acol * 2);
            uint32_t b[2][2];
            {
                uint32_t tmp[4];
                ldsm4(tmp, bbase + nr * ROWB + kc * 2);
                b[0][0] = tmp[0]; b[0][1] = tmp[1];
                b[1][0] = tmp[2]; b[1][1] = tmp[3];
            }
#pragma unroll
            for (int i = 0; i < 2; i++)
#pragma unroll
                for (int j = 0; j < 2; j++) mma16816(acc[i][j], a[i], b[j]);
        }
        __syncthreads();
    }

    int gid = lane >> 2, tig = lane & 3;
#pragma unroll
    for (int i = 0; i < 2; i++) {
#pragma unroll
        for (int j = 0; j < 2; j++) {
#pragma unroll
            for (int cc = 0; cc < 4; cc++) {
                int mrow = wm * 32 + i * 16 + gid + (cc >> 1) * 8;
                int ncol = wn * 16 + j * 8 + tig * 2 + (cc & 1);
                zbuf[mrow][ncol] = tanhf(gelu_tanh(acc[i][j][cc] + bias[ncol]));
            }
        }
    }
    __syncthreads();

#pragma unroll 1
    for (int q = 0; q < 8; q++) {
        int ln = wid * 8 + q;
        int n = bm + ln;
        float dota = 0.f, dotb = 0.f;
#pragma unroll 8
        for (int d = 0; d < 64; d++) {
            float z = zbuf[ln][d];
            dota = fmaf(z, cbs[lane][d], dota);
            dotb = fmaf(z, cbs[lane + 32][d], dotb);
        }
        float d2a = cn[lane] - 2.f * dota;
        float d2b = cn[lane + 32] - 2.f * dotb;
        float sc;
        int bi;
        if (d2a <= d2b) { sc = d2a; bi = lane; }
        else            { sc = d2b; bi = lane + 32; }
#pragma unroll
        for (int o = 16; o; o >>= 1) {
            float osc = __shfl_xor_sync(0xffffffffu, sc, o);
            int obi = __shfl_xor_sync(0xffffffffu, bi, o);
            if (osc < sc || (osc == sc && obi < bi)) { sc = osc; bi = obi; }
        }
        float zq0 = cbs[bi][lane];
        float zq1 = cbs[bi][lane + 32];
        out[(size_t)n * 64 + lane] = zq0;
        out[(size_t)n * 64 + lane + 32] = zq1;
        float d0 = zbuf[ln][lane] - zq0;
        float d1 = zbuf[ln][lane + 32] - zq1;
        float df = d0 * d0 + d1 * d1;
#pragma unroll
        for (int o = 16; o; o >>= 1) df += __shfl_xor_sync(0xffffffffu, df, o);
        if (lane == 0) g_part[n] = df;
    }
}

// ============== fused prep: all input-only conversions in ONE kernel ==============
// sections: convA(x), convBqkv, convB(Wo), convB(Wlin), convB(Wout), h2extra
#define W1 (NN * CC)
#define W2 (QKVW * CC)
#define W3 (CC * 520)
#define W4 (HIDD * CC)
#define W5 (OUTD * 532)
#define W6 (NN * 20)
#define WTOT (W1 + W2 + W3 + W4 + W5 + W6)

__global__ void prep_kernel(const float* __restrict__ x,
                            const float* __restrict__ Wq, const float* __restrict__ Wk,
                            const float* __restrict__ Wv, const float* __restrict__ Wo,
                            const float* __restrict__ Wlin, const float* __restrict__ Wout,
                            const float* __restrict__ alpha2,
                            const float* __restrict__ g2, const float* __restrict__ b2) {
    int t = blockIdx.x * blockDim.x + threadIdx.x;
    if (t < W1) {
        store2(g_xl0, g_xl1, t, x[t]);
        return;
    }
    t -= W1;
    if (t < W2) {
        int n = t >> 8, k = t & 255;
        const float* s = (n < 512) ? Wq : ((n < 1024) ? Wk : Wv);
        int col = n & 511;
        store2(g_Bq0, g_Bq1, (size_t)n * CC + k, s[(size_t)k * 512 + col]);
        return;
    }
    t -= W2;
    if (t < W3) {
        int n = t / 520, k = t - n * 520;
        store2(g_Bo0, g_Bo1, (size_t)n * ATTKP + k, Wo[(size_t)k * CC + n]);
        return;
    }
    t -= W3;
    if (t < W4) {
        int n = t >> 8, k = t & 255;
        store2(g_Bl0, g_Bl1, (size_t)n * CC + k, Wlin[(size_t)k * HIDD + n]);
        return;
    }
    t -= W4;
    if (t < W5) {
        int n = t / 532, k = t - n * 532;
        store2(g_Bu0, g_Bu1, (size_t)n * H2KP + k, Wout[(size_t)k * OUTD + n]);
        return;
    }
    t -= W5;
    if (t < W6) {
        int n = t / 20, j = t - n * 20;
        float a = *alpha2;
        float v = tanhf(a * x[(size_t)n * CC + j]) * g2[512 + j] + b2[512 + j];
        store2(g_Hl0, g_Hl1, (size_t)n * H2KP + 512 + j, v);
    }
}

// ---------------- gate projection: warp per node ----------------
__global__ void gate_kernel(const float* __restrict__ x, const float* __restrict__ wg) {
    int wid = threadIdx.x >> 5, lane = threadIdx.x & 31;
    int n = blockIdx.x * 8 + wid;
    if (n >= NN) return;
    const float* xr = x + (size_t)n * CC;
    float4 v0 = *(const float4*)(xr + lane * 8);
    float4 v1 = *(const float4*)(xr + lane * 8 + 4);
    float xv[8] = {v0.x, v0.y, v0.z, v0.w, v1.x, v1.y, v1.z, v1.w};
#pragma unroll
    for (int h = 0; h < 8; h++) {
        float p = 0.f;
#pragma unroll
        for (int i = 0; i < 8; i++) p = fmaf(xv[i], wg[(lane * 8 + i) * 8 + h], p);
#pragma unroll
        for (int o = 16; o; o >>= 1) p += __shfl_xor_sync(0xffffffffu, p, o);
        if (lane == 0) g_G[(size_t)n * 8 + h] = p;
    }
}

// ---------------- attention: block per node, warp per head; writes Att limbs ------
__global__ void attn_kernel(const float* __restrict__ coors, const int* __restrict__ nbr,
                            const float* __restrict__ Wr1, const float* __restrict__ br1,
                            const float* __restrict__ Wr2, const float* __restrict__ br2) {
    int n = blockIdx.x;
    int tid = threadIdx.x;
    __shared__ int s_nbr[8];
    __shared__ float s_dist[8];
    __shared__ float s_unit[8][3];
    __shared__ float s_rad[8][8];
    __shared__ float s_gate[8][8];

    if (tid < 8) s_nbr[tid] = nbr[(size_t)n * 8 + tid];
    __syncthreads();
    if (tid < 8) {
        int j = tid;
        float cx = coors[(size_t)n * 3], cy = coors[(size_t)n * 3 + 1], cz = coors[(size_t)n * 3 + 2];
        int mm = s_nbr[j];
        float rx = coors[(size_t)mm * 3] - cx;
        float ry = coors[(size_t)mm * 3 + 1] - cy;
        float rz = coors[(size_t)mm * 3 + 2] - cz;
        float d = sqrtf(rx * rx + ry * ry + rz * rz + 1e-8f);
        s_dist[j] = d;
        s_unit[j][0] = rx / d;
        s_unit[j][1] = ry / d;
        s_unit[j][2] = rz / d;
    }
    __syncthreads();
    if (tid < 64) {
        int j = tid >> 3, h = tid & 7;
        float d = s_dist[j];
        float acc = br2[h];
#pragma unroll
        for (int i = 0; i < 16; i++)
            acc = fmaf(gelu_tanh(d * Wr1[i] + br1[i]), Wr2[i * 8 + h], acc);
        s_rad[j][h] = acc;
        s_gate[j][h] = g_G[(size_t)s_nbr[j] * HH + h];
    }
    __syncthreads();

    int w = tid >> 5, lane = tid & 31;
    int h = w;
    const float* qr = g_QKV + (size_t)n * QKVW + h * 64;
    float q0 = qr[lane * 2], q1 = qr[lane * 2 + 1];
    float logit[8];
#pragma unroll
    for (int j = 0; j < 8; j++) {
        const float* kr = g_QKV + (size_t)s_nbr[j] * QKVW + 512 + h * 64;
        float p = q0 * kr[lane * 2] + q1 * kr[lane * 2 + 1];
#pragma unroll
        for (int o = 16; o; o >>= 1) p += __shfl_xor_sync(0xffffffffu, p, o);
        p = p * 0.125f + s_rad[j][h];
        logit[j] = (s_dist[j] <= 10.0f) ? p : -1e9f;
    }
    float mx = logit[0];
#pragma unroll
    for (int j = 1; j < 8; j++) mx = fmaxf(mx, logit[j]);
    float e[8];
    float se = 0.f;
#pragma unroll
    for (int j = 0; j < 8; j++) { e[j] = expf(logit[j] - mx); se += e[j]; }
    float inv = 1.f / se;
    float a0 = 0.f, a1 = 0.f;
#pragma unroll
    for (int j = 0; j < 8; j++) {
        float at = e[j] * inv;
        const float* vr = g_QKV + (size_t)s_nbr[j] * QKVW + 1024 + h * 64;
        a0 = fmaf(at, vr[lane * 2], a0);
        a1 = fmaf(at, vr[lane * 2 + 1], a1);
    }
    size_t base = (size_t)n * ATTKP + h * 64 + lane * 2;
    store2(g_Al0, g_Al1, base, a0);
    store2(g_Al0, g_Al1, base + 1, a1);
    if (lane == 0) {
        float vx = 0.f, vy = 0.f, vz = 0.f;
#pragma unroll
        for (int j = 0; j < 8; j++) {
            float wg = e[j] * inv * s_gate[j][h];
            vx = fmaf(wg, s_unit[j][0], vx);
            vy = fmaf(wg, s_unit[j][1], vy);
            vz = fmaf(wg, s_unit[j][2], vz);
        }
        float vn = sqrtf(vx * vx + vy * vy + vz * vz + 1e-8f);
        store2(g_Al0, g_Al1, (size_t)n * ATTKP + 512 + h, vn);
    }
}

__global__ void loss_reduce_kernel(float* __restrict__ out) {
    __shared__ double s_s[32];
    int tid = threadIdx.x;
    double s = 0.0;
    for (int i = tid; i < NN; i += 1024) s += (double)g_part[i];
#pragma unroll
    for (int o = 16; o; o >>= 1) s += __shfl_xor_sync(0xffffffffu, s, o);
    if ((tid & 31) == 0) s_s[tid >> 5] = s;
    __syncthreads();
    if (tid == 0) {
        double tot = 0.0;
        for (int i = 0; i < 32; i++) tot += s_s[i];
        out[(size_t)NN * OUTD] = (float)(0.25 * tot / (double)((size_t)NN * OUTD));
    }
}

// ---------------- launch ----------------
extern "C" void kernel_launch(void* const* d_in, const int* in_sizes, int n_in,
                              void* d_out, int out_size) {
    const float *x, *coors, *Wq, *Wk, *Wv, *wg, *Wr1, *br1, *Wr2, *br2, *Wo;
    const float *a1, *g1, *b1, *Wlin, *blin, *a2, *g2, *b2, *Wout, *bout, *cb;
    const int* nbr;

    if (n_in > 5 && in_sizes[5] == 2048) {
        x = (const float*)d_in[0];   coors = (const float*)d_in[1];
        Wq = (const float*)d_in[2];  Wk = (const float*)d_in[3];  Wv = (const float*)d_in[4];
        wg = (const float*)d_in[5];  Wr1 = (const float*)d_in[6]; br1 = (const float*)d_in[7];
        Wr2 = (const float*)d_in[8]; br2 = (const float*)d_in[9]; Wo = (const float*)d_in[10];
        a1 = (const float*)d_in[11]; g1 = (const float*)d_in[12]; b1 = (const float*)d_in[13];
        Wlin = (const float*)d_in[14]; blin = (const float*)d_in[15];
        a2 = (const float*)d_in[16]; g2 = (const float*)d_in[17]; b2 = (const float*)d_in[18];
        Wout = (const float*)d_in[19]; bout = (const float*)d_in[20];
        cb = (const float*)d_in[21]; nbr = (const int*)d_in[22];
    } else {
        x = (const float*)d_in[0];   coors = (const float*)d_in[1];
        nbr = (const int*)d_in[2];
        Wq = (const float*)d_in[3];  Wk = (const float*)d_in[4];  Wv = (const float*)d_in[5];
        wg = (const float*)d_in[6];  Wr1 = (const float*)d_in[7]; br1 = (const float*)d_in[8];
        Wr2 = (const float*)d_in[9]; br2 = (const float*)d_in[10]; Wo = (const float*)d_in[11];
        a1 = (const float*)d_in[12]; g1 = (const float*)d_in[13]; b1 = (const float*)d_in[14];
        Wlin = (const float*)d_in[15]; blin = (const float*)d_in[16];
        a2 = (const float*)d_in[17]; g2 = (const float*)d_in[18]; b2 = (const float*)d_in[19];
        Wout = (const float*)d_in[20]; bout = (const float*)d_in[21];
        cb = (const float*)d_in[22];
    }

    float* pQKV;
    cudaGetSymbolAddress((void**)&pQKV, g_QKV);
    __half *xl0, *xl1, *Al0, *Al1, *Tl0, *Tl1, *Hl0, *Hl1;
    cudaGetSymbolAddress((void**)&xl0, g_xl0); cudaGetSymbolAddress((void**)&xl1, g_xl1);
    cudaGetSymbolAddress((void**)&Al0, g_Al0); cudaGetSymbolAddress((void**)&Al1, g_Al1);
    cudaGetSymbolAddress((void**)&Tl0, g_Tl0); cudaGetSymbolAddress((void**)&Tl1, g_Tl1);
    cudaGetSymbolAddress((void**)&Hl0, g_Hl0); cudaGetSymbolAddress((void**)&Hl1, g_Hl1);
    __half *Bq0, *Bq1, *Bo0, *Bo1, *Bl0, *Bl1, *Bu0, *Bu1;
    cudaGetSymbolAddress((void**)&Bq0, g_Bq0); cudaGetSymbolAddress((void**)&Bq1, g_Bq1);
    cudaGetSymbolAddress((void**)&Bo0, g_Bo0); cudaGetSymbolAddress((void**)&Bo1, g_Bo1);
    cudaGetSymbolAddress((void**)&Bl0, g_Bl0); cudaGetSymbolAddress((void**)&Bl1, g_Bl1);
    cudaGetSymbolAddress((void**)&Bu0, g_Bu0); cudaGetSymbolAddress((void**)&Bu1, g_Bu1);

    float* out = (float*)d_out;

    constexpr int SM128 = 2 * (128 + 128) * 144;                // 73728
    constexpr int SMZ = 2 * (64 + 64) * 144 + 2 * 16640 + 256;  // 70400
    cudaFuncSetAttribute(mmagemm<128, 0>, cudaFuncAttributeMaxDynamicSharedMemorySize, SM128);
    cudaFuncSetAttribute(mmagemm<128, 1>, cudaFuncAttributeMaxDynamicSharedMemorySize, SM128);
    cudaFuncSetAttribute(mmagemm<128, 2>, cudaFuncAttributeMaxDynamicSharedMemorySize, SM128);
    cudaFuncSetAttribute(zvq_kernel, cudaFuncAttributeMaxDynamicSharedMemorySize, SMZ);

    // 1: all input-only conversions + h2extra in one kernel
    prep_kernel<<<(WTOT + 255) / 256, 256>>>(x, Wq, Wk, Wv, Wo, Wlin, Wout, a2, g2, b2);
    // 2: gate projection
    gate_kernel<<<NN / 8, 256>>>(x, wg);
    // 3: QKV = x @ [Wq|Wk|Wv] -> fp32
    mmagemm<128, 0><<<dim3(QKVW / 128, NN / 128), 256, SM128>>>(
        xl0, xl1, Bq0, Bq1, CC,
        pQKV, QKVW, nullptr, nullptr, 0,
        nullptr, nullptr, 0, nullptr, nullptr, nullptr);
    // 4: attention (ncu capture slot)
    attn_kernel<<<NN, 256>>>(coors, nbr, Wr1, br1, Wr2, br2);
    // 5: T = dyntanh(x + Att@Wo) -> limbs
    mmagemm<128, 1><<<dim3(CC / 128, NN / 128), 256, SM128>>>(
        Al0, Al1, Bo0, Bo1, ATTKP,
        nullptr, 0, Tl0, Tl1, CC,
        nullptr, x, CC, a1, g1, b1);
    // 6: H2[:, :512] = dyntanh2(gelu(T@Wlin + blin)) -> limbs
    mmagemm<128, 2><<<dim3(HIDD / 128, NN / 128), 256, SM128>>>(
        Tl0, Tl1, Bl0, Bl1, CC,
        nullptr, 0, Hl0, Hl1, H2KP,
        blin, nullptr, 0, a2, g2, b2);
    // 7: fused Z gemm + VQ
    zvq_kernel<<<dim3(1, NN / 64), 256, SMZ>>>(
        Hl0, Hl1, Bu0, Bu1, H2KP, bout, cb, out);
    // 8: loss scalar
    if (out_size > NN * OUTD) loss_reduce_kernel<<<1, 1024>>>(out);
}

// round 12
// speedup vs baseline: 1.6161x; 1.1334x over previous
#include <cuda_runtime.h>
#include <cuda_fp16.h>
#include <math.h>
#include <cstdint>

#define NN 16384
#define CC 256
#define HH 8
#define HD 512
#define QKVW 1536
#define HIDD 512
#define OUTD 64
#define H2D 532
#define ATTKP 576   // 520 padded to 64-multiple
#define H2KP 576    // 532 padded

// ---------------- scratch (static device arrays; no allocation) ----------------
__device__ float g_QKV[NN * QKVW];          // fp32 Q|K|V for attention
__device__ float g_G[NN * HH];
__device__ float g_part[NN];                // per-node vq loss partials

// activation fp16 limbs (zero-init pads stay zero forever)
__device__ __half g_xl0[NN * CC], g_xl1[NN * CC];
__device__ __half g_Al0[NN * ATTKP], g_Al1[NN * ATTKP];
__device__ __half g_Tl0[NN * CC], g_Tl1[NN * CC];
__device__ __half g_Hl0[NN * H2KP], g_Hl1[NN * H2KP];

// weight fp16 limbs, [N, Kp] K-major
__device__ __half g_Bq0[QKVW * CC], g_Bq1[QKVW * CC];
__device__ __half g_Bo0[CC * ATTKP], g_Bo1[CC * ATTKP];
__device__ __half g_Bl0[HIDD * CC], g_Bl1[HIDD * CC];
__device__ __half g_Bu0[OUTD * H2KP], g_Bu1[OUTD * H2KP];

// ---------------- helpers ----------------
__device__ __forceinline__ float gelu_tanh(float x) {
    float x3 = x * x * x;
    return 0.5f * x * (1.0f + tanhf(0.7978845608028654f * (x + 0.044715f * x3)));
}

__device__ __forceinline__ void store2(__half* p0, __half* p1, size_t off, float v) {
    __half h0 = __float2half_rn(v);
    __half h1 = __float2half_rn(v - __half2float(h0));
    p0[off] = h0;
    p1[off] = h1;
}

// packed pair store: limbs of (v0,v1) at consecutive offsets (off even)
__device__ __forceinline__ void store2x2(__half* p0, __half* p1, size_t off,
                                         float v0, float v1) {
    __half a0 = __float2half_rn(v0), a1 = __float2half_rn(v1);
    *(__half2*)(p0 + off) = __halves2half2(a0, a1);
    float r0 = v0 - __half2float(a0), r1 = v1 - __half2float(a1);
    *(__half2*)(p1 + off) = __halves2half2(__float2half_rn(r0), __float2half_rn(r1));
}

__device__ __forceinline__ uint32_t smem_u32(const void* p) {
    uint32_t a;
    asm("{ .reg .u64 t; cvta.to.shared.u64 t, %1; cvt.u32.u64 %0, t; }" : "=r"(a) : "l"(p));
    return a;
}

__device__ __forceinline__ void ldsm4(uint32_t* r, uint32_t addr) {
    asm volatile("ldmatrix.sync.aligned.m8n8.x4.shared.b16 {%0,%1,%2,%3}, [%4];"
                 : "=r"(r[0]), "=r"(r[1]), "=r"(r[2]), "=r"(r[3]) : "r"(addr));
}

__device__ __forceinline__ void mma16816(float* c, const uint32_t* a, const uint32_t* b) {
    asm volatile(
        "mma.sync.aligned.m16n8k16.row.col.f32.f16.f16.f32 "
        "{%0,%1,%2,%3}, {%4,%5,%6,%7}, {%8,%9}, {%0,%1,%2,%3};"
        : "+f"(c[0]), "+f"(c[1]), "+f"(c[2]), "+f"(c[3])
        : "r"(a[0]), "r"(a[1]), "r"(a[2]), "r"(a[3]), "r"(b[0]), "r"(b[1]));
}

__device__ __forceinline__ void cpasync16(uint32_t saddr, const void* gptr) {
    asm volatile("cp.async.cg.shared.global [%0], [%1], 16;"
                 :: "r"(saddr), "l"(gptr) : "memory");
}

// ============== mma.sync fp16 2-limb 3-pass GEMM, cp.async 2-stage ==============
// EPI: 0=fp32 plain, 1=resid+dyntanh->limbs, 2=gelu(bias)+dyntanh->limbs
template <int NT, int EPI>
__global__ __launch_bounds__(256) void mmagemm(
        const __half* __restrict__ A0, const __half* __restrict__ A1,
        const __half* __restrict__ B0, const __half* __restrict__ B1,
        int Kp,
        float* __restrict__ outF, int ldoF,
        __half* __restrict__ O0, __half* __restrict__ O1, int ldoL,
        const float* __restrict__ bias, const float* __restrict__ resid, int ldr,
        const float* __restrict__ alpha_p,
        const float* __restrict__ gv, const float* __restrict__ bv) {
    extern __shared__ __half sm[];
    constexpr int NF = NT / 32;
    constexpr int ROWB = 144;
    constexpr int ABYTES = 128 * ROWB;
    constexpr int STAGE = (128 + NT) * ROWB;

    uint32_t sbase = smem_u32(sm);
    int tid = threadIdx.x, lane = tid & 31, wid = tid >> 5;
    int wm = wid & 1, wn = wid >> 1;
    int bm = blockIdx.y * 128, bn = blockIdx.x * NT;
    int nch = Kp >> 6;
    int nit = 3 * nch;

    float acc[4][NF][4];
#pragma unroll
    for (int i = 0; i < 4; i++)
#pragma unroll
        for (int j = 0; j < NF; j++)
#pragma unroll
            for (int c = 0; c < 4; c++) acc[i][j][c] = 0.f;

    auto issue = [&](int it, int s) {
        int t = it / nch, c = it - (it / nch) * nch;
        const __half* Ab = (t == 2) ? A1 : A0;
        const __half* Bb = (t == 1) ? B1 : B0;
        uint32_t abase = sbase + (uint32_t)s * STAGE;
#pragma unroll
        for (int q = 0; q < 4; q++) {
            int idx = tid + q * 256;
            int row = idx >> 3, cg = idx & 7;
            cpasync16(abase + row * ROWB + cg * 16,
                      Ab + (size_t)(bm + row) * Kp + c * 64 + cg * 8);
        }
        uint32_t bbase = abase + ABYTES;
#pragma unroll
        for (int q = 0; q < NF; q++) {
            int idx = tid + q * 256;
            int row = idx >> 3, cg = idx & 7;
            cpasync16(bbase + row * ROWB + cg * 16,
                      Bb + (size_t)(bn + row) * Kp + c * 64 + cg * 8);
        }
        asm volatile("cp.async.commit_group;" ::: "memory");
    };

    issue(0, 0);

#pragma unroll 1
    for (int it = 0; it < nit; it++) {
        int s = it & 1;
        if (it + 1 < nit) {
            issue(it + 1, s ^ 1);
            asm volatile("cp.async.wait_group 1;" ::: "memory");
        } else {
            asm volatile("cp.async.wait_group 0;" ::: "memory");
        }
        __syncthreads();

        uint32_t abase = sbase + (uint32_t)s * STAGE;
        uint32_t bbase = abase + ABYTES;
#pragma unroll
        for (int kk = 0; kk < 4; kk++) {
            int k = kk * 16;
            int arow = wm * 64 + (lane & 15);
            int acol = k + (lane >> 4) * 8;
            int g = lane >> 3;
            int nr = wn * (NT / 4) + ((g >> 1) << 3) + (lane & 7);
            int kc = k + (g & 1) * 8;

            uint32_t a[4][4];
#pragma unroll
            for (int i = 0; i < 4; i++)
                ldsm4(a[i], abase + (arow + i * 16) * ROWB + acol * 2);
            uint32_t b[NF][2];
#pragma unroll
            for (int jj = 0; jj < NF / 2; jj++) {
                uint32_t tmp[4];
                ldsm4(tmp, bbase + (nr + jj * 16) * ROWB + kc * 2);
                b[2 * jj][0] = tmp[0]; b[2 * jj][1] = tmp[1];
                b[2 * jj + 1][0] = tmp[2]; b[2 * jj + 1][1] = tmp[3];
            }
#pragma unroll
            for (int i = 0; i < 4; i++)
#pragma unroll
                for (int j = 0; j < NF; j++) mma16816(acc[i][j], a[i], b[j]);
        }
        __syncthreads();
    }

    float alpha = (EPI == 1 || EPI == 2) ? *alpha_p : 0.f;
    int gid = lane >> 2, tig = lane & 3;
#pragma unroll
    for (int i = 0; i < 4; i++) {
#pragma unroll
        for (int j = 0; j < NF; j++) {
            int ncol = bn + wn * (NT / 4) + j * 8 + tig * 2;
#pragma unroll
            for (int hf = 0; hf < 2; hf++) {
                int m = bm + wm * 64 + i * 16 + gid + hf * 8;
                float v0 = acc[i][j][hf * 2 + 0];
                float v1 = acc[i][j][hf * 2 + 1];
                if (EPI == 0) {
                    *(float2*)(outF + (size_t)m * ldoF + ncol) = make_float2(v0, v1);
                } else if (EPI == 1) {
                    v0 += resid[(size_t)m * ldr + ncol];
                    v1 += resid[(size_t)m * ldr + ncol + 1];
                    v0 = tanhf(alpha * v0) * gv[ncol] + bv[ncol];
                    v1 = tanhf(alpha * v1) * gv[ncol + 1] + bv[ncol + 1];
                    store2x2(O0, O1, (size_t)m * ldoL + ncol, v0, v1);
                } else if (EPI == 2) {
                    v0 = gelu_tanh(v0 + bias[ncol]);
                    v1 = gelu_tanh(v1 + bias[ncol + 1]);
                    v0 = tanhf(alpha * v0) * gv[ncol] + bv[ncol];
                    v1 = tanhf(alpha * v1) * gv[ncol + 1] + bv[ncol + 1];
                    store2x2(O0, O1, (size_t)m * ldoL + ncol, v0, v1);
                }
            }
        }
    }
}

// ============== fused Z-GEMM (M-tile 64, N=64) + tanh(gelu) + VQ ==============
__global__ __launch_bounds__(256) void zvq_kernel(
        const __half* __restrict__ A0, const __half* __restrict__ A1,
        const __half* __restrict__ B0, const __half* __restrict__ B1,
        int Kp, const float* __restrict__ bias,
        const float* __restrict__ cb, float* __restrict__ out) {
    extern __shared__ char smz[];
    constexpr int ROWB = 144;
    constexpr int ABYTES = 64 * ROWB;
    constexpr int STAGE = (64 + 64) * ROWB;
    constexpr int STAGES_SZ = 2 * STAGE;
    float(*zbuf)[65] = (float(*)[65])(smz + STAGES_SZ);
    float(*cbs)[65] = (float(*)[65])(smz + STAGES_SZ + 16640);
    float* cn = (float*)(smz + STAGES_SZ + 2 * 16640);

    uint32_t sbase = smem_u32(smz);
    int tid = threadIdx.x, lane = tid & 31, wid = tid >> 5;
    int wm = wid & 1, wn = wid >> 1;
    int bm = blockIdx.y * 64;
    int nch = Kp >> 6;
    int nit = 3 * nch;

    for (int i = tid; i < 4096; i += 256) cbs[i >> 6][i & 63] = cb[i];
    __syncthreads();
    if (tid < 64) {
        float s = 0.f;
#pragma unroll 8
        for (int d = 0; d < 64; d++) s = fmaf(cbs[tid][d], cbs[tid][d], s);
        cn[tid] = s;
    }

    float acc[2][2][4];
#pragma unroll
    for (int i = 0; i < 2; i++)
#pragma unroll
        for (int j = 0; j < 2; j++)
#pragma unroll
            for (int c = 0; c < 4; c++) acc[i][j][c] = 0.f;

    auto issue = [&](int it, int s) {
        int t = it / nch, c = it - (it / nch) * nch;
        const __half* Ab = (t == 2) ? A1 : A0;
        const __half* Bb = (t == 1) ? B1 : B0;
        uint32_t abase = sbase + (uint32_t)s * STAGE;
#pragma unroll
        for (int q = 0; q < 2; q++) {
            int idx = tid + q * 256;
            int row = idx >> 3, cg = idx & 7;
            cpasync16(abase + row * ROWB + cg * 16,
                      Ab + (size_t)(bm + row) * Kp + c * 64 + cg * 8);
        }
        uint32_t bbase = abase + ABYTES;
#pragma unroll
        for (int q = 0; q < 2; q++) {
            int idx = tid + q * 256;
            int row = idx >> 3, cg = idx & 7;
            cpasync16(bbase + row * ROWB + cg * 16,
                      Bb + (size_t)row * Kp + c * 64 + cg * 8);
        }
        asm volatile("cp.async.commit_group;" ::: "memory");
    };

    issue(0, 0);

#pragma unroll 1
    for (int it = 0; it < nit; it++) {
        int s = it & 1;
        if (it + 1 < nit) {
            issue(it + 1, s ^ 1);
            asm volatile("cp.async.wait_group 1;" ::: "memory");
        } else {
            asm volatile("cp.async.wait_group 0;" ::: "memory");
        }
        __syncthreads();

        uint32_t abase = sbase + (uint32_t)s * STAGE;
        uint32_t bbase = abase + ABYTES;
#pragma unroll
        for (int kk = 0; kk < 4; kk++) {
            int k = kk * 16;
            int arow = wm * 32 + (lane & 15);
            int acol = k + (lane >> 4) * 8;
            int g = lane >> 3;
            int nr = wn * 16 + ((g >> 1) << 3) + (lane & 7);
            int kc = k + (g & 1) * 8;

            uint32_t a[2][4];
#pragma unroll
            for (int i = 0; i < 2; i++)
                ldsm4(a[i], abase + (arow + i * 16) * ROWB + acol * 2);
            uint32_t b[2][2];
            {
                uint32_t tmp[4];
                ldsm4(tmp, bbase + nr * ROWB + kc * 2);
                b[0][0] = tmp[0]; b[0][1] = tmp[1];
                b[1][0] = tmp[2]; b[1][1] = tmp[3];
            }
#pragma unroll
            for (int i = 0; i < 2; i++)
#pragma unroll
                for (int j = 0; j < 2; j++) mma16816(acc[i][j], a[i], b[j]);
        }
        __syncthreads();
    }

    int gid = lane >> 2, tig = lane & 3;
#pragma unroll
    for (int i = 0; i < 2; i++) {
#pragma unroll
        for (int j = 0; j < 2; j++) {
#pragma unroll
            for (int cc = 0; cc < 4; cc++) {
                int mrow = wm * 32 + i * 16 + gid + (cc >> 1) * 8;
                int ncol = wn * 16 + j * 8 + tig * 2 + (cc & 1);
                zbuf[mrow][ncol] = tanhf(gelu_tanh(acc[i][j][cc] + bias[ncol]));
            }
        }
    }
    __syncthreads();

#pragma unroll 1
    for (int q = 0; q < 8; q++) {
        int ln = wid * 8 + q;
        int n = bm + ln;
        float dota = 0.f, dotb = 0.f;
#pragma unroll 8
        for (int d = 0; d < 64; d++) {
            float z = zbuf[ln][d];
            dota = fmaf(z, cbs[lane][d], dota);
            dotb = fmaf(z, cbs[lane + 32][d], dotb);
        }
        float d2a = cn[lane] - 2.f * dota;
        float d2b = cn[lane + 32] - 2.f * dotb;
        float sc;
        int bi;
        if (d2a <= d2b) { sc = d2a; bi = lane; }
        else            { sc = d2b; bi = lane + 32; }
#pragma unroll
        for (int o = 16; o; o >>= 1) {
            float osc = __shfl_xor_sync(0xffffffffu, sc, o);
            int obi = __shfl_xor_sync(0xffffffffu, bi, o);
            if (osc < sc || (osc == sc && obi < bi)) { sc = osc; bi = obi; }
        }
        float zq0 = cbs[bi][lane];
        float zq1 = cbs[bi][lane + 32];
        out[(size_t)n * 64 + lane] = zq0;
        out[(size_t)n * 64 + lane + 32] = zq1;
        float d0 = zbuf[ln][lane] - zq0;
        float d1 = zbuf[ln][lane + 32] - zq1;
        float df = d0 * d0 + d1 * d1;
#pragma unroll
        for (int o = 16; o; o >>= 1) df += __shfl_xor_sync(0xffffffffu, df, o);
        if (lane == 0) g_part[n] = df;
    }
}

// ============== fused prep: all input-only conversions in ONE kernel ==============
#define W1 (NN * CC)
#define W2 (QKVW * CC)
#define W3 (CC * 520)
#define W4 (HIDD * CC)
#define W5 (OUTD * 532)
#define W6 (NN * 20)
#define WTOT (W1 + W2 + W3 + W4 + W5 + W6)

__global__ void prep_kernel(const float* __restrict__ x,
                            const float* __restrict__ Wq, const float* __restrict__ Wk,
                            const float* __restrict__ Wv, const float* __restrict__ Wo,
                            const float* __restrict__ Wlin, const float* __restrict__ Wout,
                            const float* __restrict__ alpha2,
                            const float* __restrict__ g2, const float* __restrict__ b2) {
    int t = blockIdx.x * blockDim.x + threadIdx.x;
    if (t < W1) {
        store2(g_xl0, g_xl1, t, x[t]);
        return;
    }
    t -= W1;
    if (t < W2) {
        int n = t >> 8, k = t & 255;
        const float* s = (n < 512) ? Wq : ((n < 1024) ? Wk : Wv);
        int col = n & 511;
        store2(g_Bq0, g_Bq1, (size_t)n * CC + k, s[(size_t)k * 512 + col]);
        return;
    }
    t -= W2;
    if (t < W3) {
        int n = t / 520, k = t - n * 520;
        store2(g_Bo0, g_Bo1, (size_t)n * ATTKP + k, Wo[(size_t)k * CC + n]);
        return;
    }
    t -= W3;
    if (t < W4) {
        int n = t >> 8, k = t & 255;
        store2(g_Bl0, g_Bl1, (size_t)n * CC + k, Wlin[(size_t)k * HIDD + n]);
        return;
    }
    t -= W4;
    if (t < W5) {
        int n = t / 532, k = t - n * 532;
        store2(g_Bu0, g_Bu1, (size_t)n * H2KP + k, Wout[(size_t)k * OUTD + n]);
        return;
    }
    t -= W5;
    if (t < W6) {
        int n = t / 20, j = t - n * 20;
        float a = *alpha2;
        float v = tanhf(a * x[(size_t)n * CC + j]) * g2[512 + j] + b2[512 + j];
        store2(g_Hl0, g_Hl1, (size_t)n * H2KP + 512 + j, v);
    }
}

// ---------------- gate projection: warp per node ----------------
__global__ void gate_kernel(const float* __restrict__ x, const float* __restrict__ wg) {
    int wid = threadIdx.x >> 5, lane = threadIdx.x & 31;
    int n = blockIdx.x * 8 + wid;
    if (n >= NN) return;
    const float* xr = x + (size_t)n * CC;
    float4 v0 = *(const float4*)(xr + lane * 8);
    float4 v1 = *(const float4*)(xr + lane * 8 + 4);
    float xv[8] = {v0.x, v0.y, v0.z, v0.w, v1.x, v1.y, v1.z, v1.w};
#pragma unroll
    for (int h = 0; h < 8; h++) {
        float p = 0.f;
#pragma unroll
        for (int i = 0; i < 8; i++) p = fmaf(xv[i], wg[(lane * 8 + i) * 8 + h], p);
#pragma unroll
        for (int o = 16; o; o >>= 1) p += __shfl_xor_sync(0xffffffffu, p, o);
        if (lane == 0) g_G[(size_t)n * 8 + h] = p;
    }
}

// ---------------- attention v2: float4 QK dots, 2 neighbors/pass ----------------
__global__ void attn_kernel(const float* __restrict__ coors, const int* __restrict__ nbr,
                            const float* __restrict__ Wr1, const float* __restrict__ br1,
                            const float* __restrict__ Wr2, const float* __restrict__ br2) {
    int n = blockIdx.x;
    int tid = threadIdx.x;
    __shared__ int s_nbr[8];
    __shared__ float s_dist[8];
    __shared__ float s_unit[8][3];
    __shared__ float s_rad[8][8];
    __shared__ float s_gate[8][8];

    if (tid < 8) s_nbr[tid] = nbr[(size_t)n * 8 + tid];
    __syncthreads();
    if (tid < 8) {
        int j = tid;
        float cx = coors[(size_t)n * 3], cy = coors[(size_t)n * 3 + 1], cz = coors[(size_t)n * 3 + 2];
        int mm = s_nbr[j];
        float rx = coors[(size_t)mm * 3] - cx;
        float ry = coors[(size_t)mm * 3 + 1] - cy;
        float rz = coors[(size_t)mm * 3 + 2] - cz;
        float d = sqrtf(rx * rx + ry * ry + rz * rz + 1e-8f);
        s_dist[j] = d;
        s_unit[j][0] = rx / d;
        s_unit[j][1] = ry / d;
        s_unit[j][2] = rz / d;
    }
    __syncthreads();
    if (tid < 64) {
        int j = tid >> 3, h = tid & 7;
        float d = s_dist[j];
        float acc = br2[h];
#pragma unroll
        for (int i = 0; i < 16; i++)
            acc = fmaf(gelu_tanh(d * Wr1[i] + br1[i]), Wr2[i * 8 + h], acc);
        s_rad[j][h] = acc;
        s_gate[j][h] = g_G[(size_t)s_nbr[j] * HH + h];
    }
    __syncthreads();

    int w = tid >> 5, lane = tid & 31;
    int h = w;
    int sub = lane & 15, hv = lane >> 4;
    const float* qr = g_QKV + (size_t)n * QKVW + h * 64;
    float4 q4 = *(const float4*)(qr + sub * 4);

    float logit[8];
#pragma unroll
    for (int t = 0; t < 4; t++) {
        int j = 2 * t + hv;
        const float* kr = g_QKV + (size_t)s_nbr[j] * QKVW + 512 + h * 64;
        float4 k4 = *(const float4*)(kr + sub * 4);
        float p = q4.x * k4.x + q4.y * k4.y + q4.z * k4.z + q4.w * k4.w;
#pragma unroll
        for (int o = 8; o; o >>= 1) p += __shfl_xor_sync(0xffffffffu, p, o);
        logit[2 * t] = __shfl_sync(0xffffffffu, p, 0);
        logit[2 * t + 1] = __shfl_sync(0xffffffffu, p, 16);
    }
#pragma unroll
    for (int j = 0; j < 8; j++) {
        float p = logit[j] * 0.125f + s_rad[j][h];
        logit[j] = (s_dist[j] <= 10.0f) ? p : -1e9f;
    }
    float mx = logit[0];
#pragma unroll
    for (int j = 1; j < 8; j++) mx = fmaxf(mx, logit[j]);
    float e[8];
    float se = 0.f;
#pragma unroll
    for (int j = 0; j < 8; j++) { e[j] = __expf(logit[j] - mx); se += e[j]; }
    float inv = 1.f / se;
    float a0 = 0.f, a1 = 0.f;
#pragma unroll
    for (int j = 0; j < 8; j++) {
        float at = e[j] * inv;
        const float* vr = g_QKV + (size_t)s_nbr[j] * QKVW + 1024 + h * 64;
        float2 v2 = *(const float2*)(vr + lane * 2);
        a0 = fmaf(at, v2.x, a0);
        a1 = fmaf(at, v2.y, a1);
    }
    size_t base = (size_t)n * ATTKP + h * 64 + lane * 2;
    store2x2(g_Al0, g_Al1, base, a0, a1);
    if (lane == 0) {
        float vx = 0.f, vy = 0.f, vz = 0.f;
#pragma unroll
        for (int j = 0; j < 8; j++) {
            float wg = e[j] * inv * s_gate[j][h];
            vx = fmaf(wg, s_unit[j][0], vx);
            vy = fmaf(wg, s_unit[j][1], vy);
            vz = fmaf(wg, s_unit[j][2], vz);
        }
        float vn = sqrtf(vx * vx + vy * vy + vz * vz + 1e-8f);
        store2(g_Al0, g_Al1, (size_t)n * ATTKP + 512 + h, vn);
    }
}

__global__ void loss_reduce_kernel(float* __restrict__ out) {
    __shared__ double s_s[32];
    int tid = threadIdx.x;
    double s = 0.0;
    for (int i = tid; i < NN; i += 1024) s += (double)g_part[i];
#pragma unroll
    for (int o = 16; o; o >>= 1) s += __shfl_xor_sync(0xffffffffu, s, o);
    if ((tid & 31) == 0) s_s[tid >> 5] = s;
    __syncthreads();
    if (tid == 0) {
        double tot = 0.0;
        for (int i = 0; i < 32; i++) tot += s_s[i];
        out[(size_t)NN * OUTD] = (float)(0.25 * tot / (double)((size_t)NN * OUTD));
    }
}

// ---------------- launch ----------------
extern "C" void kernel_launch(void* const* d_in, const int* in_sizes, int n_in,
                              void* d_out, int out_size) {
    const float *x, *coors, *Wq, *Wk, *Wv, *wg, *Wr1, *br1, *Wr2, *br2, *Wo;
    const float *a1, *g1, *b1, *Wlin, *blin, *a2, *g2, *b2, *Wout, *bout, *cb;
    const int* nbr;

    if (n_in > 5 && in_sizes[5] == 2048) {
        x = (const float*)d_in[0];   coors = (const float*)d_in[1];
        Wq = (const float*)d_in[2];  Wk = (const float*)d_in[3];  Wv = (const float*)d_in[4];
        wg = (const float*)d_in[5];  Wr1 = (const float*)d_in[6]; br1 = (const float*)d_in[7];
        Wr2 = (const float*)d_in[8]; br2 = (const float*)d_in[9]; Wo = (const float*)d_in[10];
        a1 = (const float*)d_in[11]; g1 = (const float*)d_in[12]; b1 = (const float*)d_in[13];
        Wlin = (const float*)d_in[14]; blin = (const float*)d_in[15];
        a2 = (const float*)d_in[16]; g2 = (const float*)d_in[17]; b2 = (const float*)d_in[18];
        Wout = (const float*)d_in[19]; bout = (const float*)d_in[20];
        cb = (const float*)d_in[21]; nbr = (const int*)d_in[22];
    } else {
        x = (const float*)d_in[0];   coors = (const float*)d_in[1];
        nbr = (const int*)d_in[2];
        Wq = (const float*)d_in[3];  Wk = (const float*)d_in[4];  Wv = (const float*)d_in[5];
        wg = (const float*)d_in[6];  Wr1 = (const float*)d_in[7]; br1 = (const float*)d_in[8];
        Wr2 = (const float*)d_in[9]; br2 = (const float*)d_in[10]; Wo = (const float*)d_in[11];
        a1 = (const float*)d_in[12]; g1 = (const float*)d_in[13]; b1 = (const float*)d_in[14];
        Wlin = (const float*)d_in[15]; blin = (const float*)d_in[16];
        a2 = (const float*)d_in[17]; g2 = (const float*)d_in[18]; b2 = (const float*)d_in[19];
        Wout = (const float*)d_in[20]; bout = (const float*)d_in[21];
        cb = (const float*)d_in[22];
    }

    float* pQKV;
    cudaGetSymbolAddress((void**)&pQKV, g_QKV);
    __half *xl0, *xl1, *Al0, *Al1, *Tl0, *Tl1, *Hl0, *Hl1;
    cudaGetSymbolAddress((void**)&xl0, g_xl0); cudaGetSymbolAddress((void**)&xl1, g_xl1);
    cudaGetSymbolAddress((void**)&Al0, g_Al0); cudaGetSymbolAddress((void**)&Al1, g_Al1);
    cudaGetSymbolAddress((void**)&Tl0, g_Tl0); cudaGetSymbolAddress((void**)&Tl1, g_Tl1);
    cudaGetSymbolAddress((void**)&Hl0, g_Hl0); cudaGetSymbolAddress((void**)&Hl1, g_Hl1);
    __half *Bq0, *Bq1, *Bo0, *Bo1, *Bl0, *Bl1, *Bu0, *Bu1;
    cudaGetSymbolAddress((void**)&Bq0, g_Bq0); cudaGetSymbolAddress((void**)&Bq1, g_Bq1);
    cudaGetSymbolAddress((void**)&Bo0, g_Bo0); cudaGetSymbolAddress((void**)&Bo1, g_Bo1);
    cudaGetSymbolAddress((void**)&Bl0, g_Bl0); cudaGetSymbolAddress((void**)&Bl1, g_Bl1);
    cudaGetSymbolAddress((void**)&Bu0, g_Bu0); cudaGetSymbolAddress((void**)&Bu1, g_Bu1);

    float* out = (float*)d_out;

    constexpr int SM128 = 2 * (128 + 128) * 144;                // 73728
    constexpr int SMZ = 2 * (64 + 64) * 144 + 2 * 16640 + 256;  // 70400
    cudaFuncSetAttribute(mmagemm<128, 0>, cudaFuncAttributeMaxDynamicSharedMemorySize, SM128);
    cudaFuncSetAttribute(mmagemm<128, 1>, cudaFuncAttributeMaxDynamicSharedMemorySize, SM128);
    cudaFuncSetAttribute(mmagemm<128, 2>, cudaFuncAttributeMaxDynamicSharedMemorySize, SM128);
    cudaFuncSetAttribute(zvq_kernel, cudaFuncAttributeMaxDynamicSharedMemorySize, SMZ);

    // 1: all input-only conversions + h2extra in one kernel
    prep_kernel<<<(WTOT + 255) / 256, 256>>>(x, Wq, Wk, Wv, Wo, Wlin, Wout, a2, g2, b2);
    // 2: gate projection
    gate_kernel<<<NN / 8, 256>>>(x, wg);
    // 3: QKV = x @ [Wq|Wk|Wv] -> fp32
    mmagemm<128, 0><<<dim3(QKVW / 128, NN / 128), 256, SM128>>>(
        xl0, xl1, Bq0, Bq1, CC,
        pQKV, QKVW, nullptr, nullptr, 0,
        nullptr, nullptr, 0, nullptr, nullptr, nullptr);
    // 4: attention (ncu capture slot)
    attn_kernel<<<NN, 256>>>(coors, nbr, Wr1, br1, Wr2, br2);
    // 5: T = dyntanh(x + Att@Wo) -> limbs
    mmagemm<128, 1><<<dim3(CC / 128, NN / 128), 256, SM128>>>(
        Al0, Al1, Bo0, Bo1, ATTKP,
        nullptr, 0, Tl0, Tl1, CC,
        nullptr, x, CC, a1, g1, b1);
    // 6: H2[:, :512] = dyntanh2(gelu(T@Wlin + blin)) -> limbs
    mmagemm<128, 2><<<dim3(HIDD / 128, NN / 128), 256, SM128>>>(
        Tl0, Tl1, Bl0, Bl1, CC,
        nullptr, 0, Hl0, Hl1, H2KP,
        blin, nullptr, 0, a2, g2, b2);
    // 7: fused Z gemm + VQ
    zvq_kernel<<<dim3(1, NN / 64), 256, SMZ>>>(
        Hl0, Hl1, Bu0, Bu1, H2KP, bout, cb, out);
    // 8: loss scalar
    if (out_size > NN * OUTD) loss_reduce_kernel<<<1, 1024>>>(out);
}

// round 13
// speedup vs baseline: 1.9391x; 1.1999x over previous
#include <cuda_runtime.h>
#include <cuda_fp16.h>
#include <math.h>
#include <cstdint>

#define NN 16384
#define CC 256
#define HH 8
#define HD 512
#define QKVW 1536
#define HIDD 512
#define OUTD 64
#define H2D 532
#define ATTKP 576   // 520 padded to 64-multiple
#define H2KP 576    // 532 padded

// ---------------- scratch (static device arrays; no allocation) ----------------
__device__ float g_QKV[NN * QKVW];          // fp32 Q|K|V for attention
__device__ float g_G[NN * HH];
__device__ float g_part[NN];                // per-node vq loss partials

// activation fp16 limbs (zero-init pads stay zero forever)
__device__ __half g_xl0[NN * CC], g_xl1[NN * CC];
__device__ __half g_Al0[NN * ATTKP], g_Al1[NN * ATTKP];
__device__ __half g_Tl0[NN * CC], g_Tl1[NN * CC];
__device__ __half g_Hl0[NN * H2KP], g_Hl1[NN * H2KP];

// weight fp16 limbs, [N, Kp] K-major
__device__ __half g_Bq0[QKVW * CC], g_Bq1[QKVW * CC];
__device__ __half g_Bo0[CC * ATTKP], g_Bo1[CC * ATTKP];
__device__ __half g_Bl0[HIDD * CC], g_Bl1[HIDD * CC];
__device__ __half g_Bu0[OUTD * H2KP], g_Bu1[OUTD * H2KP];

// ---------------- helpers ----------------
__device__ __forceinline__ float gelu_tanh(float x) {
    float x3 = x * x * x;
    return 0.5f * x * (1.0f + tanhf(0.7978845608028654f * (x + 0.044715f * x3)));
}

__device__ __forceinline__ void store2(__half* p0, __half* p1, size_t off, float v) {
    __half h0 = __float2half_rn(v);
    __half h1 = __float2half_rn(v - __half2float(h0));
    p0[off] = h0;
    p1[off] = h1;
}

// packed pair store: limbs of (v0,v1) at consecutive offsets (off even)
__device__ __forceinline__ void store2x2(__half* p0, __half* p1, size_t off,
                                         float v0, float v1) {
    __half a0 = __float2half_rn(v0), a1 = __float2half_rn(v1);
    *(__half2*)(p0 + off) = __halves2half2(a0, a1);
    float r0 = v0 - __half2float(a0), r1 = v1 - __half2float(a1);
    *(__half2*)(p1 + off) = __halves2half2(__float2half_rn(r0), __float2half_rn(r1));
}

__device__ __forceinline__ uint32_t smem_u32(const void* p) {
    uint32_t a;
    asm("{ .reg .u64 t; cvta.to.shared.u64 t, %1; cvt.u32.u64 %0, t; }" : "=r"(a) : "l"(p));
    return a;
}

__device__ __forceinline__ void ldsm4(uint32_t* r, uint32_t addr) {
    asm volatile("ldmatrix.sync.aligned.m8n8.x4.shared.b16 {%0,%1,%2,%3}, [%4];"
                 : "=r"(r[0]), "=r"(r[1]), "=r"(r[2]), "=r"(r[3]) : "r"(addr));
}

__device__ __forceinline__ void mma16816(float* c, const uint32_t* a, const uint32_t* b) {
    asm volatile(
        "mma.sync.aligned.m16n8k16.row.col.f32.f16.f16.f32 "
        "{%0,%1,%2,%3}, {%4,%5,%6,%7}, {%8,%9}, {%0,%1,%2,%3};"
        : "+f"(c[0]), "+f"(c[1]), "+f"(c[2]), "+f"(c[3])
        : "r"(a[0]), "r"(a[1]), "r"(a[2]), "r"(a[3]), "r"(b[0]), "r"(b[1]));
}

__device__ __forceinline__ void cpasync16(uint32_t saddr, const void* gptr) {
    asm volatile("cp.async.cg.shared.global [%0], [%1], 16;"
                 :: "r"(saddr), "l"(gptr) : "memory");
}

// ============== mma.sync fp16 2-limb 3-pass GEMM, cp.async 3-stage ==============
// EPI: 0=fp32 plain, 1=resid+dyntanh->limbs, 2=gelu(bias)+dyntanh->limbs
template <int NT, int EPI>
__global__ __launch_bounds__(256) void mmagemm(
        const __half* __restrict__ A0, const __half* __restrict__ A1,
        const __half* __restrict__ B0, const __half* __restrict__ B1,
        int Kp,
        float* __restrict__ outF, int ldoF,
        __half* __restrict__ O0, __half* __restrict__ O1, int ldoL,
        const float* __restrict__ bias, const float* __restrict__ resid, int ldr,
        const float* __restrict__ alpha_p,
        const float* __restrict__ gv, const float* __restrict__ bv) {
    extern __shared__ __half sm[];
    constexpr int NF = NT / 32;
    constexpr int ROWB = 144;
    constexpr int ABYTES = 128 * ROWB;
    constexpr int STAGE = (128 + NT) * ROWB;

    uint32_t sbase = smem_u32(sm);
    int tid = threadIdx.x, lane = tid & 31, wid = tid >> 5;
    int wm = wid & 1, wn = wid >> 1;
    int bm = blockIdx.y * 128, bn = blockIdx.x * NT;
    int nch = Kp >> 6;
    int nit = 3 * nch;

    float acc[4][NF][4];
#pragma unroll
    for (int i = 0; i < 4; i++)
#pragma unroll
        for (int j = 0; j < NF; j++)
#pragma unroll
            for (int c = 0; c < 4; c++) acc[i][j][c] = 0.f;

    auto issue = [&](int it, int s) {
        int t = it / nch, c = it - (it / nch) * nch;
        const __half* Ab = (t == 2) ? A1 : A0;
        const __half* Bb = (t == 1) ? B1 : B0;
        uint32_t abase = sbase + (uint32_t)s * STAGE;
#pragma unroll
        for (int q = 0; q < 4; q++) {
            int idx = tid + q * 256;
            int row = idx >> 3, cg = idx & 7;
            cpasync16(abase + row * ROWB + cg * 16,
                      Ab + (size_t)(bm + row) * Kp + c * 64 + cg * 8);
        }
        uint32_t bbase = abase + ABYTES;
#pragma unroll
        for (int q = 0; q < NF; q++) {
            int idx = tid + q * 256;
            int row = idx >> 3, cg = idx & 7;
            cpasync16(bbase + row * ROWB + cg * 16,
                      Bb + (size_t)(bn + row) * Kp + c * 64 + cg * 8);
        }
        asm volatile("cp.async.commit_group;" ::: "memory");
    };

    issue(0, 0);
    issue(1, 1);

    int s = 0;
#pragma unroll 1
    for (int it = 0; it < nit; it++) {
        if (it + 1 < nit) {
            asm volatile("cp.async.wait_group 1;" ::: "memory");
        } else {
            asm volatile("cp.async.wait_group 0;" ::: "memory");
        }
        __syncthreads();
        if (it + 2 < nit) {
            int s2 = s + 2;
            if (s2 >= 3) s2 -= 3;
            issue(it + 2, s2);
        }

        uint32_t abase = sbase + (uint32_t)s * STAGE;
        uint32_t bbase = abase + ABYTES;
#pragma unroll
        for (int kk = 0; kk < 4; kk++) {
            int k = kk * 16;
            int arow = wm * 64 + (lane & 15);
            int acol = k + (lane >> 4) * 8;
            int g = lane >> 3;
            int nr = wn * (NT / 4) + ((g >> 1) << 3) + (lane & 7);
            int kc = k + (g & 1) * 8;

            uint32_t a[4][4];
#pragma unroll
            for (int i = 0; i < 4; i++)
                ldsm4(a[i], abase + (arow + i * 16) * ROWB + acol * 2);
            uint32_t b[NF][2];
#pragma unroll
            for (int jj = 0; jj < NF / 2; jj++) {
                uint32_t tmp[4];
                ldsm4(tmp, bbase + (nr + jj * 16) * ROWB + kc * 2);
                b[2 * jj][0] = tmp[0]; b[2 * jj][1] = tmp[1];
                b[2 * jj + 1][0] = tmp[2]; b[2 * jj + 1][1] = tmp[3];
            }
#pragma unroll
            for (int i = 0; i < 4; i++)
#pragma unroll
                for (int j = 0; j < NF; j++) mma16816(acc[i][j], a[i], b[j]);
        }
        if (++s == 3) s = 0;
    }

    float alpha = (EPI == 1 || EPI == 2) ? *alpha_p : 0.f;
    int gid = lane >> 2, tig = lane & 3;
#pragma unroll
    for (int i = 0; i < 4; i++) {
#pragma unroll
        for (int j = 0; j < NF; j++) {
            int ncol = bn + wn * (NT / 4) + j * 8 + tig * 2;
#pragma unroll
            for (int hf = 0; hf < 2; hf++) {
                int m = bm + wm * 64 + i * 16 + gid + hf * 8;
                float v0 = acc[i][j][hf * 2 + 0];
                float v1 = acc[i][j][hf * 2 + 1];
                if (EPI == 0) {
                    *(float2*)(outF + (size_t)m * ldoF + ncol) = make_float2(v0, v1);
                } else if (EPI == 1) {
                    v0 += resid[(size_t)m * ldr + ncol];
                    v1 += resid[(size_t)m * ldr + ncol + 1];
                    v0 = tanhf(alpha * v0) * gv[ncol] + bv[ncol];
                    v1 = tanhf(alpha * v1) * gv[ncol + 1] + bv[ncol + 1];
                    store2x2(O0, O1, (size_t)m * ldoL + ncol, v0, v1);
                } else if (EPI == 2) {
                    v0 = gelu_tanh(v0 + bias[ncol]);
                    v1 = gelu_tanh(v1 + bias[ncol + 1]);
                    v0 = tanhf(alpha * v0) * gv[ncol] + bv[ncol];
                    v1 = tanhf(alpha * v1) * gv[ncol + 1] + bv[ncol + 1];
                    store2x2(O0, O1, (size_t)m * ldoL + ncol, v0, v1);
                }
            }
        }
    }
}

// ============== fused Z-GEMM (M-tile 64, N=64) + tanh(gelu) + VQ, 3-stage =========
__global__ __launch_bounds__(256) void zvq_kernel(
        const __half* __restrict__ A0, const __half* __restrict__ A1,
        const __half* __restrict__ B0, const __half* __restrict__ B1,
        int Kp, const float* __restrict__ bias,
        const float* __restrict__ cb, float* __restrict__ out) {
    extern __shared__ char smz[];
    constexpr int ROWB = 144;
    constexpr int ABYTES = 64 * ROWB;
    constexpr int STAGE = (64 + 64) * ROWB;
    constexpr int STAGES_SZ = 3 * STAGE;
    float(*zbuf)[65] = (float(*)[65])(smz + STAGES_SZ);
    float(*cbs)[65] = (float(*)[65])(smz + STAGES_SZ + 16640);
    float* cn = (float*)(smz + STAGES_SZ + 2 * 16640);

    uint32_t sbase = smem_u32(smz);
    int tid = threadIdx.x, lane = tid & 31, wid = tid >> 5;
    int wm = wid & 1, wn = wid >> 1;
    int bm = blockIdx.y * 64;
    int nch = Kp >> 6;
    int nit = 3 * nch;

    for (int i = tid; i < 4096; i += 256) cbs[i >> 6][i & 63] = cb[i];
    __syncthreads();
    if (tid < 64) {
        float s = 0.f;
#pragma unroll 8
        for (int d = 0; d < 64; d++) s = fmaf(cbs[tid][d], cbs[tid][d], s);
        cn[tid] = s;
    }

    float acc[2][2][4];
#pragma unroll
    for (int i = 0; i < 2; i++)
#pragma unroll
        for (int j = 0; j < 2; j++)
#pragma unroll
            for (int c = 0; c < 4; c++) acc[i][j][c] = 0.f;

    auto issue = [&](int it, int s) {
        int t = it / nch, c = it - (it / nch) * nch;
        const __half* Ab = (t == 2) ? A1 : A0;
        const __half* Bb = (t == 1) ? B1 : B0;
        uint32_t abase = sbase + (uint32_t)s * STAGE;
#pragma unroll
        for (int q = 0; q < 2; q++) {
            int idx = tid + q * 256;
            int row = idx >> 3, cg = idx & 7;
            cpasync16(abase + row * ROWB + cg * 16,
                      Ab + (size_t)(bm + row) * Kp + c * 64 + cg * 8);
        }
        uint32_t bbase = abase + ABYTES;
#pragma unroll
        for (int q = 0; q < 2; q++) {
            int idx = tid + q * 256;
            int row = idx >> 3, cg = idx & 7;
            cpasync16(bbase + row * ROWB + cg * 16,
                      Bb + (size_t)row * Kp + c * 64 + cg * 8);
        }
        asm volatile("cp.async.commit_group;" ::: "memory");
    };

    issue(0, 0);
    issue(1, 1);

    int s = 0;
#pragma unroll 1
    for (int it = 0; it < nit; it++) {
        if (it + 1 < nit) {
            asm volatile("cp.async.wait_group 1;" ::: "memory");
        } else {
            asm volatile("cp.async.wait_group 0;" ::: "memory");
        }
        __syncthreads();
        if (it + 2 < nit) {
            int s2 = s + 2;
            if (s2 >= 3) s2 -= 3;
            issue(it + 2, s2);
        }

        uint32_t abase = sbase + (uint32_t)s * STAGE;
        uint32_t bbase = abase + ABYTES;
#pragma unroll
        for (int kk = 0; kk < 4; kk++) {
            int k = kk * 16;
            int arow = wm * 32 + (lane & 15);
            int acol = k + (lane >> 4) * 8;
            int g = lane >> 3;
            int nr = wn * 16 + ((g >> 1) << 3) + (lane & 7);
            int kc = k + (g & 1) * 8;

            uint32_t a[2][4];
#pragma unroll
            for (int i = 0; i < 2; i++)
                ldsm4(a[i], abase + (arow + i * 16) * ROWB + acol * 2);
            uint32_t b[2][2];
            {
                uint32_t tmp[4];
                ldsm4(tmp, bbase + nr * ROWB + kc * 2);
                b[0][0] = tmp[0]; b[0][1] = tmp[1];
                b[1][0] = tmp[2]; b[1][1] = tmp[3];
            }
#pragma unroll
            for (int i = 0; i < 2; i++)
#pragma unroll
                for (int j = 0; j < 2; j++) mma16816(acc[i][j], a[i], b[j]);
        }
        if (++s == 3) s = 0;
    }

    int gid = lane >> 2, tig = lane & 3;
#pragma unroll
    for (int i = 0; i < 2; i++) {
#pragma unroll
        for (int j = 0; j < 2; j++) {
#pragma unroll
            for (int cc = 0; cc < 4; cc++) {
                int mrow = wm * 32 + i * 16 + gid + (cc >> 1) * 8;
                int ncol = wn * 16 + j * 8 + tig * 2 + (cc & 1);
                zbuf[mrow][ncol] = tanhf(gelu_tanh(acc[i][j][cc] + bias[ncol]));
            }
        }
    }
    __syncthreads();

#pragma unroll 1
    for (int q = 0; q < 8; q++) {
        int ln = wid * 8 + q;
        int n = bm + ln;
        float dota = 0.f, dotb = 0.f;
#pragma unroll 8
        for (int d = 0; d < 64; d++) {
            float z = zbuf[ln][d];
            dota = fmaf(z, cbs[lane][d], dota);
            dotb = fmaf(z, cbs[lane + 32][d], dotb);
        }
        float d2a = cn[lane] - 2.f * dota;
        float d2b = cn[lane + 32] - 2.f * dotb;
        float sc;
        int bi;
        if (d2a <= d2b) { sc = d2a; bi = lane; }
        else            { sc = d2b; bi = lane + 32; }
#pragma unroll
        for (int o = 16; o; o >>= 1) {
            float osc = __shfl_xor_sync(0xffffffffu, sc, o);
            int obi = __shfl_xor_sync(0xffffffffu, bi, o);
            if (osc < sc || (osc == sc && obi < bi)) { sc = osc; bi = obi; }
        }
        float zq0 = cbs[bi][lane];
        float zq1 = cbs[bi][lane + 32];
        out[(size_t)n * 64 + lane] = zq0;
        out[(size_t)n * 64 + lane + 32] = zq1;
        float d0 = zbuf[ln][lane] - zq0;
        float d1 = zbuf[ln][lane + 32] - zq1;
        float df = d0 * d0 + d1 * d1;
#pragma unroll
        for (int o = 16; o; o >>= 1) df += __shfl_xor_sync(0xffffffffu, df, o);
        if (lane == 0) g_part[n] = df;
    }
}

// ============== fused prep: conversions + h2extra + gate in ONE kernel ==============
#define W1 (NN * CC)
#define W2 (QKVW * CC)
#define W3 (CC * 520)
#define W4 (HIDD * CC)
#define W5 (OUTD * 532)
#define W6 (NN * 20)
#define W7 (NN * HH)
#define WTOT (W1 + W2 + W3 + W4 + W5 + W6 + W7)

__global__ void prep_kernel(const float* __restrict__ x,
                            const float* __restrict__ Wq, const float* __restrict__ Wk,
                            const float* __restrict__ Wv, const float* __restrict__ Wo,
                            const float* __restrict__ Wlin, const float* __restrict__ Wout,
                            const float* __restrict__ alpha2,
                            const float* __restrict__ g2, const float* __restrict__ b2,
                            const float* __restrict__ wg) {
    int t = blockIdx.x * blockDim.x + threadIdx.x;
    if (t < W1) {
        store2(g_xl0, g_xl1, t, x[t]);
        return;
    }
    t -= W1;
    if (t < W2) {
        int n = t >> 8, k = t & 255;
        const float* s = (n < 512) ? Wq : ((n < 1024) ? Wk : Wv);
        int col = n & 511;
        store2(g_Bq0, g_Bq1, (size_t)n * CC + k, s[(size_t)k * 512 + col]);
        return;
    }
    t -= W2;
    if (t < W3) {
        int n = t / 520, k = t - n * 520;
        store2(g_Bo0, g_Bo1, (size_t)n * ATTKP + k, Wo[(size_t)k * CC + n]);
        return;
    }
    t -= W3;
    if (t < W4) {
        int n = t >> 8, k = t & 255;
        store2(g_Bl0, g_Bl1, (size_t)n * CC + k, Wlin[(size_t)k * HIDD + n]);
        return;
    }
    t -= W4;
    if (t < W5) {
        int n = t / 532, k = t - n * 532;
        store2(g_Bu0, g_Bu1, (size_t)n * H2KP + k, Wout[(size_t)k * OUTD + n]);
        return;
    }
    t -= W5;
    if (t < W6) {
        int n = t / 20, j = t - n * 20;
        float a = *alpha2;
        float v = tanhf(a * x[(size_t)n * CC + j]) * g2[512 + j] + b2[512 + j];
        store2(g_Hl0, g_Hl1, (size_t)n * H2KP + 512 + j, v);
        return;
    }
    t -= W6;
    if (t < W7) {
        int n = t >> 3, h = t & 7;
        const float* xr = x + (size_t)n * CC;
        float acc = 0.f;
#pragma unroll 4
        for (int c = 0; c < CC; c++) acc = fmaf(xr[c], wg[c * HH + h], acc);
        g_G[t] = acc;
    }
}

// ---------------- attention v2: float4 QK dots, 2 neighbors/pass ----------------
__global__ void attn_kernel(const float* __restrict__ coors, const int* __restrict__ nbr,
                            const float* __restrict__ Wr1, const float* __restrict__ br1,
                            const float* __restrict__ Wr2, const float* __restrict__ br2) {
    int n = blockIdx.x;
    int tid = threadIdx.x;
    __shared__ int s_nbr[8];
    __shared__ float s_dist[8];
    __shared__ float s_unit[8][3];
    __shared__ float s_rad[8][8];
    __shared__ float s_gate[8][8];

    if (tid < 8) s_nbr[tid] = nbr[(size_t)n * 8 + tid];
    __syncthreads();
    if (tid < 8) {
        int j = tid;
        float cx = coors[(size_t)n * 3], cy = coors[(size_t)n * 3 + 1], cz = coors[(size_t)n * 3 + 2];
        int mm = s_nbr[j];
        float rx = coors[(size_t)mm * 3] - cx;
        float ry = coors[(size_t)mm * 3 + 1] - cy;
        float rz = coors[(size_t)mm * 3 + 2] - cz;
        float d = sqrtf(rx * rx + ry * ry + rz * rz + 1e-8f);
        s_dist[j] = d;
        s_unit[j][0] = rx / d;
        s_unit[j][1] = ry / d;
        s_unit[j][2] = rz / d;
    }
    __syncthreads();
    if (tid < 64) {
        int j = tid >> 3, h = tid & 7;
        float d = s_dist[j];
        float acc = br2[h];
#pragma unroll
        for (int i = 0; i < 16; i++)
            acc = fmaf(gelu_tanh(d * Wr1[i] + br1[i]), Wr2[i * 8 + h], acc);
        s_rad[j][h] = acc;
        s_gate[j][h] = g_G[(size_t)s_nbr[j] * HH + h];
    }
    __syncthreads();

    int w = tid >> 5, lane = tid & 31;
    int h = w;
    int sub = lane & 15, hv = lane >> 4;
    const float* qr = g_QKV + (size_t)n * QKVW + h * 64;
    float4 q4 = *(const float4*)(qr + sub * 4);

    float logit[8];
#pragma unroll
    for (int t = 0; t < 4; t++) {
        int j = 2 * t + hv;
        const float* kr = g_QKV + (size_t)s_nbr[j] * QKVW + 512 + h * 64;
        float4 k4 = *(const float4*)(kr + sub * 4);
        float p = q4.x * k4.x + q4.y * k4.y + q4.z * k4.z + q4.w * k4.w;
#pragma unroll
        for (int o = 8; o; o >>= 1) p += __shfl_xor_sync(0xffffffffu, p, o);
        logit[2 * t] = __shfl_sync(0xffffffffu, p, 0);
        logit[2 * t + 1] = __shfl_sync(0xffffffffu, p, 16);
    }
#pragma unroll
    for (int j = 0; j < 8; j++) {
        float p = logit[j] * 0.125f + s_rad[j][h];
        logit[j] = (s_dist[j] <= 10.0f) ? p : -1e9f;
    }
    float mx = logit[0];
#pragma unroll
    for (int j = 1; j < 8; j++) mx = fmaxf(mx, logit[j]);
    float e[8];
    float se = 0.f;
#pragma unroll
    for (int j = 0; j < 8; j++) { e[j] = __expf(logit[j] - mx); se += e[j]; }
    float inv = 1.f / se;
    float a0 = 0.f, a1 = 0.f;
#pragma unroll
    for (int j = 0; j < 8; j++) {
        float at = e[j] * inv;
        const float* vr = g_QKV + (size_t)s_nbr[j] * QKVW + 1024 + h * 64;
        float2 v2 = *(const float2*)(vr + lane * 2);
        a0 = fmaf(at, v2.x, a0);
        a1 = fmaf(at, v2.y, a1);
    }
    size_t base = (size_t)n * ATTKP + h * 64 + lane * 2;
    store2x2(g_Al0, g_Al1, base, a0, a1);
    if (lane == 0) {
        float vx = 0.f, vy = 0.f, vz = 0.f;
#pragma unroll
        for (int j = 0; j < 8; j++) {
            float wg = e[j] * inv * s_gate[j][h];
            vx = fmaf(wg, s_unit[j][0], vx);
            vy = fmaf(wg, s_unit[j][1], vy);
            vz = fmaf(wg, s_unit[j][2], vz);
        }
        float vn = sqrtf(vx * vx + vy * vy + vz * vz + 1e-8f);
        store2(g_Al0, g_Al1, (size_t)n * ATTKP + 512 + h, vn);
    }
}

__global__ void loss_reduce_kernel(float* __restrict__ out) {
    __shared__ double s_s[32];
    int tid = threadIdx.x;
    double s = 0.0;
    for (int i = tid; i < NN; i += 1024) s += (double)g_part[i];
#pragma unroll
    for (int o = 16; o; o >>= 1) s += __shfl_xor_sync(0xffffffffu, s, o);
    if ((tid & 31) == 0) s_s[tid >> 5] = s;
    __syncthreads();
    if (tid == 0) {
        double tot = 0.0;
        for (int i = 0; i < 32; i++) tot += s_s[i];
        out[(size_t)NN * OUTD] = (float)(0.25 * tot / (double)((size_t)NN * OUTD));
    }
}

// ---------------- launch ----------------
extern "C" void kernel_launch(void* const* d_in, const int* in_sizes, int n_in,
                              void* d_out, int out_size) {
    const float *x, *coors, *Wq, *Wk, *Wv, *wg, *Wr1, *br1, *Wr2, *br2, *Wo;
    const float *a1, *g1, *b1, *Wlin, *blin, *a2, *g2, *b2, *Wout, *bout, *cb;
    const int* nbr;

    if (n_in > 5 && in_sizes[5] == 2048) {
        x = (const float*)d_in[0];   coors = (const float*)d_in[1];
        Wq = (const float*)d_in[2];  Wk = (const float*)d_in[3];  Wv = (const float*)d_in[4];
        wg = (const float*)d_in[5];  Wr1 = (const float*)d_in[6]; br1 = (const float*)d_in[7];
        Wr2 = (const float*)d_in[8]; br2 = (const float*)d_in[9]; Wo = (const float*)d_in[10];
        a1 = (const float*)d_in[11]; g1 = (const float*)d_in[12]; b1 = (const float*)d_in[13];
        Wlin = (const float*)d_in[14]; blin = (const float*)d_in[15];
        a2 = (const float*)d_in[16]; g2 = (const float*)d_in[17]; b2 = (const float*)d_in[18];
        Wout = (const float*)d_in[19]; bout = (const float*)d_in[20];
        cb = (const float*)d_in[21]; nbr = (const int*)d_in[22];
    } else {
        x = (const float*)d_in[0];   coors = (const float*)d_in[1];
        nbr = (const int*)d_in[2];
        Wq = (const float*)d_in[3];  Wk = (const float*)d_in[4];  Wv = (const float*)d_in[5];
        wg = (const float*)d_in[6];  Wr1 = (const float*)d_in[7]; br1 = (const float*)d_in[8];
        Wr2 = (const float*)d_in[9]; br2 = (const float*)d_in[10]; Wo = (const float*)d_in[11];
        a1 = (const float*)d_in[12]; g1 = (const float*)d_in[13]; b1 = (const float*)d_in[14];
        Wlin = (const float*)d_in[15]; blin = (const float*)d_in[16];
        a2 = (const float*)d_in[17]; g2 = (const float*)d_in[18]; b2 = (const float*)d_in[19];
        Wout = (const float*)d_in[20]; bout = (const float*)d_in[21];
        cb = (const float*)d_in[22];
    }

    float* pQKV;
    cudaGetSymbolAddress((void**)&pQKV, g_QKV);
    __half *xl0, *xl1, *Al0, *Al1, *Tl0, *Tl1, *Hl0, *Hl1;
    cudaGetSymbolAddress((void**)&xl0, g_xl0); cudaGetSymbolAddress((void**)&xl1, g_xl1);
    cudaGetSymbolAddress((void**)&Al0, g_Al0); cudaGetSymbolAddress((void**)&Al1, g_Al1);
    cudaGetSymbolAddress((void**)&Tl0, g_Tl0); cudaGetSymbolAddress((void**)&Tl1, g_Tl1);
    cudaGetSymbolAddress((void**)&Hl0, g_Hl0); cudaGetSymbolAddress((void**)&Hl1, g_Hl1);
    __half *Bq0, *Bq1, *Bo0, *Bo1, *Bl0, *Bl1, *Bu0, *Bu1;
    cudaGetSymbolAddress((void**)&Bq0, g_Bq0); cudaGetSymbolAddress((void**)&Bq1, g_Bq1);
    cudaGetSymbolAddress((void**)&Bo0, g_Bo0); cudaGetSymbolAddress((void**)&Bo1, g_Bo1);
    cudaGetSymbolAddress((void**)&Bl0, g_Bl0); cudaGetSymbolAddress((void**)&Bl1, g_Bl1);
    cudaGetSymbolAddress((void**)&Bu0, g_Bu0); cudaGetSymbolAddress((void**)&Bu1, g_Bu1);

    float* out = (float*)d_out;

    constexpr int SM128 = 3 * (128 + 128) * 144;                // 110592
    constexpr int SMZ = 3 * (64 + 64) * 144 + 2 * 16640 + 256;  // 88832
    cudaFuncSetAttribute(mmagemm<128, 0>, cudaFuncAttributeMaxDynamicSharedMemorySize, SM128);
    cudaFuncSetAttribute(mmagemm<128, 1>, cudaFuncAttributeMaxDynamicSharedMemorySize, SM128);
    cudaFuncSetAttribute(mmagemm<128, 2>, cudaFuncAttributeMaxDynamicSharedMemorySize, SM128);
    cudaFuncSetAttribute(zvq_kernel, cudaFuncAttributeMaxDynamicSharedMemorySize, SMZ);

    // 1: conversions + h2extra + gate in one kernel
    prep_kernel<<<(WTOT + 255) / 256, 256>>>(x, Wq, Wk, Wv, Wo, Wlin, Wout, a2, g2, b2, wg);
    // 2: QKV = x @ [Wq|Wk|Wv] -> fp32
    mmagemm<128, 0><<<dim3(QKVW / 128, NN / 128), 256, SM128>>>(
        xl0, xl1, Bq0, Bq1, CC,
        pQKV, QKVW, nullptr, nullptr, 0,
        nullptr, nullptr, 0, nullptr, nullptr, nullptr);
    // 3: attention
    attn_kernel<<<NN, 256>>>(coors, nbr, Wr1, br1, Wr2, br2);
    // 4: T = dyntanh(x + Att@Wo) -> limbs  (ncu capture slot)
    mmagemm<128, 1><<<dim3(CC / 128, NN / 128), 256, SM128>>>(
        Al0, Al1, Bo0, Bo1, ATTKP,
        nullptr, 0, Tl0, Tl1, CC,
        nullptr, x, CC, a1, g1, b1);
    // 5: H2[:, :512] = dyntanh2(gelu(T@Wlin + blin)) -> limbs
    mmagemm<128, 2><<<dim3(HIDD / 128, NN / 128), 256, SM128>>>(
        Tl0, Tl1, Bl0, Bl1, CC,
        nullptr, 0, Hl0, Hl1, H2KP,
        blin, nullptr, 0, a2, g2, b2);
    // 6: fused Z gemm + VQ
    zvq_kernel<<<dim3(1, NN / 64), 256, SMZ>>>(
        Hl0, Hl1, Bu0, Bu1, H2KP, bout, cb, out);
    // 7: loss scalar
    if (out_size > NN * OUTD) loss_reduce_kernel<<<1, 1024>>>(out);
}

// round 14
// speedup vs baseline: 2.0127x; 1.0379x over previous
#include <cuda_runtime.h>
#include <cuda_fp16.h>
#include <math.h>
#include <cstdint>

#define NN 16384
#define CC 256
#define HH 8
#define HD 512
#define QKVW 1536
#define HIDD 512
#define OUTD 64
#define H2D 532
#define ATTKP 576   // 520 padded to 64-multiple
#define H2KP 576    // 532 padded

// ---------------- scratch (static device arrays; no allocation) ----------------
__device__ float g_QKV[NN * QKVW];          // fp32 Q|K|V for attention
__device__ float g_G[NN * HH];
__device__ float g_part[NN];                // per-node vq loss partials

// activation fp16 limbs (zero-init pads stay zero forever)
__device__ __half g_xl0[NN * CC], g_xl1[NN * CC];
__device__ __half g_Al0[NN * ATTKP], g_Al1[NN * ATTKP];
__device__ __half g_Tl0[NN * CC], g_Tl1[NN * CC];
__device__ __half g_Hl0[NN * H2KP], g_Hl1[NN * H2KP];

// weight fp16 limbs, [N, Kp] K-major
__device__ __half g_Bq0[QKVW * CC], g_Bq1[QKVW * CC];
__device__ __half g_Bo0[CC * ATTKP], g_Bo1[CC * ATTKP];
__device__ __half g_Bl0[HIDD * CC], g_Bl1[HIDD * CC];
__device__ __half g_Bu0[OUTD * H2KP], g_Bu1[OUTD * H2KP];

// ---------------- helpers ----------------
__device__ __forceinline__ float gelu_tanh(float x) {
    float x3 = x * x * x;
    return 0.5f * x * (1.0f + tanhf(0.7978845608028654f * (x + 0.044715f * x3)));
}

__device__ __forceinline__ void store2(__half* p0, __half* p1, size_t off, float v) {
    __half h0 = __float2half_rn(v);
    __half h1 = __float2half_rn(v - __half2float(h0));
    p0[off] = h0;
    p1[off] = h1;
}

// packed pair store: limbs of (v0,v1) at consecutive offsets (off even)
__device__ __forceinline__ void store2x2(__half* p0, __half* p1, size_t off,
                                         float v0, float v1) {
    __half a0 = __float2half_rn(v0), a1 = __float2half_rn(v1);
    *(__half2*)(p0 + off) = __halves2half2(a0, a1);
    float r0 = v0 - __half2float(a0), r1 = v1 - __half2float(a1);
    *(__half2*)(p1 + off) = __halves2half2(__float2half_rn(r0), __float2half_rn(r1));
}

__device__ __forceinline__ uint32_t smem_u32(const void* p) {
    uint32_t a;
    asm("{ .reg .u64 t; cvta.to.shared.u64 t, %1; cvt.u32.u64 %0, t; }" : "=r"(a) : "l"(p));
    return a;
}

__device__ __forceinline__ void ldsm4(uint32_t* r, uint32_t addr) {
    asm volatile("ldmatrix.sync.aligned.m8n8.x4.shared.b16 {%0,%1,%2,%3}, [%4];"
                 : "=r"(r[0]), "=r"(r[1]), "=r"(r[2]), "=r"(r[3]) : "r"(addr));
}

__device__ __forceinline__ void mma16816(float* c, const uint32_t* a, const uint32_t* b) {
    asm volatile(
        "mma.sync.aligned.m16n8k16.row.col.f32.f16.f16.f32 "
        "{%0,%1,%2,%3}, {%4,%5,%6,%7}, {%8,%9}, {%0,%1,%2,%3};"
        : "+f"(c[0]), "+f"(c[1]), "+f"(c[2]), "+f"(c[3])
        : "r"(a[0]), "r"(a[1]), "r"(a[2]), "r"(a[3]), "r"(b[0]), "r"(b[1]));
}

__device__ __forceinline__ void cpasync16(uint32_t saddr, const void* gptr) {
    asm volatile("cp.async.cg.shared.global [%0], [%1], 16;"
                 :: "r"(saddr), "l"(gptr) : "memory");
}

// ============== mma.sync fp16 2-limb 3-pass GEMM, cp.async 3-stage ==============
// EPI: 0=fp32 plain, 1=resid+dyntanh->limbs, 2=gelu(bias)+dyntanh->limbs
template <int NT, int EPI>
__global__ __launch_bounds__(256) void mmagemm(
        const __half* __restrict__ A0, const __half* __restrict__ A1,
        const __half* __restrict__ B0, const __half* __restrict__ B1,
        int Kp,
        float* __restrict__ outF, int ldoF,
        __half* __restrict__ O0, __half* __restrict__ O1, int ldoL,
        const float* __restrict__ bias, const float* __restrict__ resid, int ldr,
        const float* __restrict__ alpha_p,
        const float* __restrict__ gv, const float* __restrict__ bv) {
    extern __shared__ __half sm[];
    constexpr int NF = NT / 32;
    constexpr int ROWB = 144;
    constexpr int ABYTES = 128 * ROWB;
    constexpr int STAGE = (128 + NT) * ROWB;

    uint32_t sbase = smem_u32(sm);
    int tid = threadIdx.x, lane = tid & 31, wid = tid >> 5;
    int wm = wid & 1, wn = wid >> 1;
    int bm = blockIdx.y * 128, bn = blockIdx.x * NT;
    int nch = Kp >> 6;
    int nit = 3 * nch;

    float acc[4][NF][4];
#pragma unroll
    for (int i = 0; i < 4; i++)
#pragma unroll
        for (int j = 0; j < NF; j++)
#pragma unroll
            for (int c = 0; c < 4; c++) acc[i][j][c] = 0.f;

    auto issue = [&](int it, int s) {
        int t = it / nch, c = it - (it / nch) * nch;
        const __half* Ab = (t == 2) ? A1 : A0;
        const __half* Bb = (t == 1) ? B1 : B0;
        uint32_t abase = sbase + (uint32_t)s * STAGE;
#pragma unroll
        for (int q = 0; q < 4; q++) {
            int idx = tid + q * 256;
            int row = idx >> 3, cg = idx & 7;
            cpasync16(abase + row * ROWB + cg * 16,
                      Ab + (size_t)(bm + row) * Kp + c * 64 + cg * 8);
        }
        uint32_t bbase = abase + ABYTES;
#pragma unroll
        for (int q = 0; q < NF; q++) {
            int idx = tid + q * 256;
            int row = idx >> 3, cg = idx & 7;
            cpasync16(bbase + row * ROWB + cg * 16,
                      Bb + (size_t)(bn + row) * Kp + c * 64 + cg * 8);
        }
        asm volatile("cp.async.commit_group;" ::: "memory");
    };

    issue(0, 0);
    issue(1, 1);

    int s = 0;
#pragma unroll 1
    for (int it = 0; it < nit; it++) {
        if (it + 1 < nit) {
            asm volatile("cp.async.wait_group 1;" ::: "memory");
        } else {
            asm volatile("cp.async.wait_group 0;" ::: "memory");
        }
        __syncthreads();
        if (it + 2 < nit) {
            int s2 = s + 2;
            if (s2 >= 3) s2 -= 3;
            issue(it + 2, s2);
        }

        uint32_t abase = sbase + (uint32_t)s * STAGE;
        uint32_t bbase = abase + ABYTES;
#pragma unroll
        for (int kk = 0; kk < 4; kk++) {
            int k = kk * 16;
            int arow = wm * 64 + (lane & 15);
            int acol = k + (lane >> 4) * 8;
            int g = lane >> 3;
            int nr = wn * (NT / 4) + ((g >> 1) << 3) + (lane & 7);
            int kc = k + (g & 1) * 8;

            uint32_t a[4][4];
#pragma unroll
            for (int i = 0; i < 4; i++)
                ldsm4(a[i], abase + (arow + i * 16) * ROWB + acol * 2);
            uint32_t b[NF][2];
#pragma unroll
            for (int jj = 0; jj < NF / 2; jj++) {
                uint32_t tmp[4];
                ldsm4(tmp, bbase + (nr + jj * 16) * ROWB + kc * 2);
                b[2 * jj][0] = tmp[0]; b[2 * jj][1] = tmp[1];
                b[2 * jj + 1][0] = tmp[2]; b[2 * jj + 1][1] = tmp[3];
            }
#pragma unroll
            for (int i = 0; i < 4; i++)
#pragma unroll
                for (int j = 0; j < NF; j++) mma16816(acc[i][j], a[i], b[j]);
        }
        if (++s == 3) s = 0;
    }

    float alpha = (EPI == 1 || EPI == 2) ? *alpha_p : 0.f;
    int gid = lane >> 2, tig = lane & 3;
#pragma unroll
    for (int i = 0; i < 4; i++) {
#pragma unroll
        for (int j = 0; j < NF; j++) {
            int ncol = bn + wn * (NT / 4) + j * 8 + tig * 2;
#pragma unroll
            for (int hf = 0; hf < 2; hf++) {
                int m = bm + wm * 64 + i * 16 + gid + hf * 8;
                float v0 = acc[i][j][hf * 2 + 0];
                float v1 = acc[i][j][hf * 2 + 1];
                if (EPI == 0) {
                    *(float2*)(outF + (size_t)m * ldoF + ncol) = make_float2(v0, v1);
                } else if (EPI == 1) {
                    v0 += resid[(size_t)m * ldr + ncol];
                    v1 += resid[(size_t)m * ldr + ncol + 1];
                    v0 = tanhf(alpha * v0) * gv[ncol] + bv[ncol];
                    v1 = tanhf(alpha * v1) * gv[ncol + 1] + bv[ncol + 1];
                    store2x2(O0, O1, (size_t)m * ldoL + ncol, v0, v1);
                } else if (EPI == 2) {
                    v0 = gelu_tanh(v0 + bias[ncol]);
                    v1 = gelu_tanh(v1 + bias[ncol + 1]);
                    v0 = tanhf(alpha * v0) * gv[ncol] + bv[ncol];
                    v1 = tanhf(alpha * v1) * gv[ncol + 1] + bv[ncol + 1];
                    store2x2(O0, O1, (size_t)m * ldoL + ncol, v0, v1);
                }
            }
        }
    }
}

// ============== fused Z-GEMM (M-tile 64, N=64) + tanh(gelu) + VQ, 3-stage =========
__global__ __launch_bounds__(256) void zvq_kernel(
        const __half* __restrict__ A0, const __half* __restrict__ A1,
        const __half* __restrict__ B0, const __half* __restrict__ B1,
        int Kp, const float* __restrict__ bias,
        const float* __restrict__ cb, float* __restrict__ out) {
    extern __shared__ char smz[];
    constexpr int ROWB = 144;
    constexpr int ABYTES = 64 * ROWB;
    constexpr int STAGE = (64 + 64) * ROWB;
    constexpr int STAGES_SZ = 3 * STAGE;
    float(*zbuf)[65] = (float(*)[65])(smz + STAGES_SZ);
    float(*cbs)[65] = (float(*)[65])(smz + STAGES_SZ + 16640);
    float* cn = (float*)(smz + STAGES_SZ + 2 * 16640);

    uint32_t sbase = smem_u32(smz);
    int tid = threadIdx.x, lane = tid & 31, wid = tid >> 5;
    int wm = wid & 1, wn = wid >> 1;
    int bm = blockIdx.y * 64;
    int nch = Kp >> 6;
    int nit = 3 * nch;

    for (int i = tid; i < 4096; i += 256) cbs[i >> 6][i & 63] = cb[i];
    __syncthreads();
    if (tid < 64) {
        float s = 0.f;
#pragma unroll 8
        for (int d = 0; d < 64; d++) s = fmaf(cbs[tid][d], cbs[tid][d], s);
        cn[tid] = s;
    }

    float acc[2][2][4];
#pragma unroll
    for (int i = 0; i < 2; i++)
#pragma unroll
        for (int j = 0; j < 2; j++)
#pragma unroll
            for (int c = 0; c < 4; c++) acc[i][j][c] = 0.f;

    auto issue = [&](int it, int s) {
        int t = it / nch, c = it - (it / nch) * nch;
        const __half* Ab = (t == 2) ? A1 : A0;
        const __half* Bb = (t == 1) ? B1 : B0;
        uint32_t abase = sbase + (uint32_t)s * STAGE;
#pragma unroll
        for (int q = 0; q < 2; q++) {
            int idx = tid + q * 256;
            int row = idx >> 3, cg = idx & 7;
            cpasync16(abase + row * ROWB + cg * 16,
                      Ab + (size_t)(bm + row) * Kp + c * 64 + cg * 8);
        }
        uint32_t bbase = abase + ABYTES;
#pragma unroll
        for (int q = 0; q < 2; q++) {
            int idx = tid + q * 256;
            int row = idx >> 3, cg = idx & 7;
            cpasync16(bbase + row * ROWB + cg * 16,
                      Bb + (size_t)row * Kp + c * 64 + cg * 8);
        }
        asm volatile("cp.async.commit_group;" ::: "memory");
    };

    issue(0, 0);
    issue(1, 1);

    int s = 0;
#pragma unroll 1
    for (int it = 0; it < nit; it++) {
        if (it + 1 < nit) {
            asm volatile("cp.async.wait_group 1;" ::: "memory");
        } else {
            asm volatile("cp.async.wait_group 0;" ::: "memory");
        }
        __syncthreads();
        if (it + 2 < nit) {
            int s2 = s + 2;
            if (s2 >= 3) s2 -= 3;
            issue(it + 2, s2);
        }

        uint32_t abase = sbase + (uint32_t)s * STAGE;
        uint32_t bbase = abase + ABYTES;
#pragma unroll
        for (int kk = 0; kk < 4; kk++) {
            int k = kk * 16;
            int arow = wm * 32 + (lane & 15);
            int acol = k + (lane >> 4) * 8;
            int g = lane >> 3;
            int nr = wn * 16 + ((g >> 1) << 3) + (lane & 7);
            int kc = k + (g & 1) * 8;

            uint32_t a[2][4];
#pragma unroll
            for (int i = 0; i < 2; i++)
                ldsm4(a[i], abase + (arow + i * 16) * ROWB + acol * 2);
            uint32_t b[2][2];
            {
                uint32_t tmp[4];
                ldsm4(tmp, bbase + nr * ROWB + kc * 2);
                b[0][0] = tmp[0]; b[0][1] = tmp[1];
                b[1][0] = tmp[2]; b[1][1] = tmp[3];
            }
#pragma unroll
            for (int i = 0; i < 2; i++)
#pragma unroll
                for (int j = 0; j < 2; j++) mma16816(acc[i][j], a[i], b[j]);
        }
        if (++s == 3) s = 0;
    }

    int gid = lane >> 2, tig = lane & 3;
#pragma unroll
    for (int i = 0; i < 2; i++) {
#pragma unroll
        for (int j = 0; j < 2; j++) {
#pragma unroll
            for (int cc = 0; cc < 4; cc++) {
                int mrow = wm * 32 + i * 16 + gid + (cc >> 1) * 8;
                int ncol = wn * 16 + j * 8 + tig * 2 + (cc & 1);
                zbuf[mrow][ncol] = tanhf(gelu_tanh(acc[i][j][cc] + bias[ncol]));
            }
        }
    }
    __syncthreads();

#pragma unroll 1
    for (int q = 0; q < 8; q++) {
        int ln = wid * 8 + q;
        int n = bm + ln;
        float dota = 0.f, dotb = 0.f;
#pragma unroll 8
        for (int d = 0; d < 64; d++) {
            float z = zbuf[ln][d];
            dota = fmaf(z, cbs[lane][d], dota);
            dotb = fmaf(z, cbs[lane + 32][d], dotb);
        }
        float d2a = cn[lane] - 2.f * dota;
        float d2b = cn[lane + 32] - 2.f * dotb;
        float sc;
        int bi;
        if (d2a <= d2b) { sc = d2a; bi = lane; }
        else            { sc = d2b; bi = lane + 32; }
#pragma unroll
        for (int o = 16; o; o >>= 1) {
            float osc = __shfl_xor_sync(0xffffffffu, sc, o);
            int obi = __shfl_xor_sync(0xffffffffu, bi, o);
            if (osc < sc || (osc == sc && obi < bi)) { sc = osc; bi = obi; }
        }
        float zq0 = cbs[bi][lane];
        float zq1 = cbs[bi][lane + 32];
        out[(size_t)n * 64 + lane] = zq0;
        out[(size_t)n * 64 + lane + 32] = zq1;
        float d0 = zbuf[ln][lane] - zq0;
        float d1 = zbuf[ln][lane + 32] - zq1;
        float df = d0 * d0 + d1 * d1;
#pragma unroll
        for (int o = 16; o; o >>= 1) df += __shfl_xor_sync(0xffffffffu, df, o);
        if (lane == 0) g_part[n] = df;
    }
}

// ============== fused prep: conversions + h2extra + gate in ONE kernel ==============
#define W1V (NN * CC / 4)
#define W2 (QKVW * CC)
#define W3 (CC * 520)
#define W4 (HIDD * CC)
#define W5 (OUTD * 532)
#define W6 (NN * 20)
#define W7 (NN * HH)
#define WTOT (W1V + W2 + W3 + W4 + W5 + W6 + W7)

__global__ void prep_kernel(const float* __restrict__ x,
                            const float* __restrict__ Wq, const float* __restrict__ Wk,
                            const float* __restrict__ Wv, const float* __restrict__ Wo,
                            const float* __restrict__ Wlin, const float* __restrict__ Wout,
                            const float* __restrict__ alpha2,
                            const float* __restrict__ g2, const float* __restrict__ b2,
                            const float* __restrict__ wg) {
    int t = blockIdx.x * blockDim.x + threadIdx.x;
    if (t < W1V) {
        float4 v = *(const float4*)(x + (size_t)t * 4);
        store2x2(g_xl0, g_xl1, (size_t)t * 4, v.x, v.y);
        store2x2(g_xl0, g_xl1, (size_t)t * 4 + 2, v.z, v.w);
        return;
    }
    t -= W1V;
    if (t < W2) {
        int n = t >> 8, k = t & 255;
        const float* s = (n < 512) ? Wq : ((n < 1024) ? Wk : Wv);
        int col = n & 511;
        store2(g_Bq0, g_Bq1, (size_t)n * CC + k, s[(size_t)k * 512 + col]);
        return;
    }
    t -= W2;
    if (t < W3) {
        int n = t / 520, k = t - n * 520;
        store2(g_Bo0, g_Bo1, (size_t)n * ATTKP + k, Wo[(size_t)k * CC + n]);
        return;
    }
    t -= W3;
    if (t < W4) {
        int n = t >> 8, k = t & 255;
        store2(g_Bl0, g_Bl1, (size_t)n * CC + k, Wlin[(size_t)k * HIDD + n]);
        return;
    }
    t -= W4;
    if (t < W5) {
        int n = t / 532, k = t - n * 532;
        store2(g_Bu0, g_Bu1, (size_t)n * H2KP + k, Wout[(size_t)k * OUTD + n]);
        return;
    }
    t -= W5;
    if (t < W6) {
        int n = t / 20, j = t - n * 20;
        float a = *alpha2;
        float v = tanhf(a * x[(size_t)n * CC + j]) * g2[512 + j] + b2[512 + j];
        store2(g_Hl0, g_Hl1, (size_t)n * H2KP + 512 + j, v);
        return;
    }
    t -= W6;
    if (t < W7) {
        int n = t >> 3, h = t & 7;
        const float* xr = x + (size_t)n * CC;
        float acc = 0.f;
#pragma unroll 4
        for (int c = 0; c < CC; c++) acc = fmaf(xr[c], wg[c * HH + h], acc);
        g_G[t] = acc;
    }
}

// ---------------- attention v3: dedup radial MLP (hid computed once per (j,i)) ----
__global__ void attn_kernel(const float* __restrict__ coors, const int* __restrict__ nbr,
                            const float* __restrict__ Wr1, const float* __restrict__ br1,
                            const float* __restrict__ Wr2, const float* __restrict__ br2) {
    int n = blockIdx.x;
    int tid = threadIdx.x;
    __shared__ int s_nbr[8];
    __shared__ float s_dist[8];
    __shared__ float s_unit[8][3];
    __shared__ float s_hid[8][16];
    __shared__ float s_rad[8][8];
    __shared__ float s_gate[8][8];

    // phase A: thread j loads its neighbor and computes dist/unit
    if (tid < 8) {
        int j = tid;
        int mm = nbr[(size_t)n * 8 + j];
        s_nbr[j] = mm;
        float cx = coors[(size_t)n * 3], cy = coors[(size_t)n * 3 + 1], cz = coors[(size_t)n * 3 + 2];
        float rx = coors[(size_t)mm * 3] - cx;
        float ry = coors[(size_t)mm * 3 + 1] - cy;
        float rz = coors[(size_t)mm * 3 + 2] - cz;
        float d = sqrtf(rx * rx + ry * ry + rz * rz + 1e-8f);
        s_dist[j] = d;
        s_unit[j][0] = rx / d;
        s_unit[j][1] = ry / d;
        s_unit[j][2] = rz / d;
    }
    __syncthreads();
    // phase B: hidden activations (128 distinct gelu evals) + gate gather
    if (tid < 128) {
        int j = tid >> 4, i = tid & 15;
        s_hid[j][i] = gelu_tanh(s_dist[j] * Wr1[i] + br1[i]);
    } else if (tid < 192) {
        int t2 = tid - 128;
        int j = t2 >> 3, h = t2 & 7;
        s_gate[j][h] = g_G[(size_t)s_nbr[j] * HH + h];
    }
    __syncthreads();
    // phase C: contract hid -> rad (same accumulation order as reference)
    if (tid < 64) {
        int j = tid >> 3, h = tid & 7;
        float acc = br2[h];
#pragma unroll
        for (int i = 0; i < 16; i++)
            acc = fmaf(s_hid[j][i], Wr2[i * 8 + h], acc);
        s_rad[j][h] = acc;
    }
    __syncthreads();

    int w = tid >> 5, lane = tid & 31;
    int h = w;
    int sub = lane & 15, hv = lane >> 4;
    const float* qr = g_QKV + (size_t)n * QKVW + h * 64;
    float4 q4 = *(const float4*)(qr + sub * 4);

    float logit[8];
#pragma unroll
    for (int t = 0; t < 4; t++) {
        int j = 2 * t + hv;
        const float* kr = g_QKV + (size_t)s_nbr[j] * QKVW + 512 + h * 64;
        float4 k4 = *(const float4*)(kr + sub * 4);
        float p = q4.x * k4.x + q4.y * k4.y + q4.z * k4.z + q4.w * k4.w;
#pragma unroll
        for (int o = 8; o; o >>= 1) p += __shfl_xor_sync(0xffffffffu, p, o);
        logit[2 * t] = __shfl_sync(0xffffffffu, p, 0);
        logit[2 * t + 1] = __shfl_sync(0xffffffffu, p, 16);
    }
#pragma unroll
    for (int j = 0; j < 8; j++) {
        float p = logit[j] * 0.125f + s_rad[j][h];
        logit[j] = (s_dist[j] <= 10.0f) ? p : -1e9f;
    }
    float mx = logit[0];
#pragma unroll
    for (int j = 1; j < 8; j++) mx = fmaxf(mx, logit[j]);
    float e[8];
    float se = 0.f;
#pragma unroll
    for (int j = 0; j < 8; j++) { e[j] = __expf(logit[j] - mx); se += e[j]; }
    float inv = 1.f / se;
    float a0 = 0.f, a1 = 0.f;
#pragma unroll
    for (int j = 0; j < 8; j++) {
        float at = e[j] * inv;
        const float* vr = g_QKV + (size_t)s_nbr[j] * QKVW + 1024 + h * 64;
        float2 v2 = *(const float2*)(vr + lane * 2);
        a0 = fmaf(at, v2.x, a0);
        a1 = fmaf(at, v2.y, a1);
    }
    size_t base = (size_t)n * ATTKP + h * 64 + lane * 2;
    store2x2(g_Al0, g_Al1, base, a0, a1);
    if (lane == 0) {
        float vx = 0.f, vy = 0.f, vz = 0.f;
#pragma unroll
        for (int j = 0; j < 8; j++) {
            float wg = e[j] * inv * s_gate[j][h];
            vx = fmaf(wg, s_unit[j][0], vx);
            vy = fmaf(wg, s_unit[j][1], vy);
            vz = fmaf(wg, s_unit[j][2], vz);
        }
        float vn = sqrtf(vx * vx + vy * vy + vz * vz + 1e-8f);
        store2(g_Al0, g_Al1, (size_t)n * ATTKP + 512 + h, vn);
    }
}

__global__ void loss_reduce_kernel(float* __restrict__ out) {
    __shared__ double s_s[32];
    int tid = threadIdx.x;
    double s = 0.0;
    for (int i = tid; i < NN; i += 1024) s += (double)g_part[i];
#pragma unroll
    for (int o = 16; o; o >>= 1) s += __shfl_xor_sync(0xffffffffu, s, o);
    if ((tid & 31) == 0) s_s[tid >> 5] = s;
    __syncthreads();
    if (tid == 0) {
        double tot = 0.0;
        for (int i = 0; i < 32; i++) tot += s_s[i];
        out[(size_t)NN * OUTD] = (float)(0.25 * tot / (double)((size_t)NN * OUTD));
    }
}

// ---------------- launch ----------------
extern "C" void kernel_launch(void* const* d_in, const int* in_sizes, int n_in,
                              void* d_out, int out_size) {
    const float *x, *coors, *Wq, *Wk, *Wv, *wg, *Wr1, *br1, *Wr2, *br2, *Wo;
    const float *a1, *g1, *b1, *Wlin, *blin, *a2, *g2, *b2, *Wout, *bout, *cb;
    const int* nbr;

    if (n_in > 5 && in_sizes[5] == 2048) {
        x = (const float*)d_in[0];   coors = (const float*)d_in[1];
        Wq = (const float*)d_in[2];  Wk = (const float*)d_in[3];  Wv = (const float*)d_in[4];
        wg = (const float*)d_in[5];  Wr1 = (const float*)d_in[6]; br1 = (const float*)d_in[7];
        Wr2 = (const float*)d_in[8]; br2 = (const float*)d_in[9]; Wo = (const float*)d_in[10];
        a1 = (const float*)d_in[11]; g1 = (const float*)d_in[12]; b1 = (const float*)d_in[13];
        Wlin = (const float*)d_in[14]; blin = (const float*)d_in[15];
        a2 = (const float*)d_in[16]; g2 = (const float*)d_in[17]; b2 = (const float*)d_in[18];
        Wout = (const float*)d_in[19]; bout = (const float*)d_in[20];
        cb = (const float*)d_in[21]; nbr = (const int*)d_in[22];
    } else {
        x = (const float*)d_in[0];   coors = (const float*)d_in[1];
        nbr = (const int*)d_in[2];
        Wq = (const float*)d_in[3];  Wk = (const float*)d_in[4];  Wv = (const float*)d_in[5];
        wg = (const float*)d_in[6];  Wr1 = (const float*)d_in[7]; br1 = (const float*)d_in[8];
        Wr2 = (const float*)d_in[9]; br2 = (const float*)d_in[10]; Wo = (const float*)d_in[11];
        a1 = (const float*)d_in[12]; g1 = (const float*)d_in[13]; b1 = (const float*)d_in[14];
        Wlin = (const float*)d_in[15]; blin = (const float*)d_in[16];
        a2 = (const float*)d_in[17]; g2 = (const float*)d_in[18]; b2 = (const float*)d_in[19];
        Wout = (const float*)d_in[20]; bout = (const float*)d_in[21];
        cb = (const float*)d_in[22];
    }

    float* pQKV;
    cudaGetSymbolAddress((void**)&pQKV, g_QKV);
    __half *xl0, *xl1, *Al0, *Al1, *Tl0, *Tl1, *Hl0, *Hl1;
    cudaGetSymbolAddress((void**)&xl0, g_xl0); cudaGetSymbolAddress((void**)&xl1, g_xl1);
    cudaGetSymbolAddress((void**)&Al0, g_Al0); cudaGetSymbolAddress((void**)&Al1, g_Al1);
    cudaGetSymbolAddress((void**)&Tl0, g_Tl0); cudaGetSymbolAddress((void**)&Tl1, g_Tl1);
    cudaGetSymbolAddress((void**)&Hl0, g_Hl0); cudaGetSymbolAddress((void**)&Hl1, g_Hl1);
    __half *Bq0, *Bq1, *Bo0, *Bo1, *Bl0, *Bl1, *Bu0, *Bu1;
    cudaGetSymbolAddress((void**)&Bq0, g_Bq0); cudaGetSymbolAddress((void**)&Bq1, g_Bq1);
    cudaGetSymbolAddress((void**)&Bo0, g_Bo0); cudaGetSymbolAddress((void**)&Bo1, g_Bo1);
    cudaGetSymbolAddress((void**)&Bl0, g_Bl0); cudaGetSymbolAddress((void**)&Bl1, g_Bl1);
    cudaGetSymbolAddress((void**)&Bu0, g_Bu0); cudaGetSymbolAddress((void**)&Bu1, g_Bu1);

    float* out = (float*)d_out;

    constexpr int SM128 = 3 * (128 + 128) * 144;                // 110592
    constexpr int SMZ = 3 * (64 + 64) * 144 + 2 * 16640 + 256;  // 88832
    cudaFuncSetAttribute(mmagemm<128, 0>, cudaFuncAttributeMaxDynamicSharedMemorySize, SM128);
    cudaFuncSetAttribute(mmagemm<128, 1>, cudaFuncAttributeMaxDynamicSharedMemorySize, SM128);
    cudaFuncSetAttribute(mmagemm<128, 2>, cudaFuncAttributeMaxDynamicSharedMemorySize, SM128);
    cudaFuncSetAttribute(zvq_kernel, cudaFuncAttributeMaxDynamicSharedMemorySize, SMZ);

    // 1: conversions + h2extra + gate in one kernel
    prep_kernel<<<(WTOT + 255) / 256, 256>>>(x, Wq, Wk, Wv, Wo, Wlin, Wout, a2, g2, b2, wg);
    // 2: QKV = x @ [Wq|Wk|Wv] -> fp32
    mmagemm<128, 0><<<dim3(QKVW / 128, NN / 128), 256, SM128>>>(
        xl0, xl1, Bq0, Bq1, CC,
        pQKV, QKVW, nullptr, nullptr, 0,
        nullptr, nullptr, 0, nullptr, nullptr, nullptr);
    // 3: attention
    attn_kernel<<<NN, 256>>>(coors, nbr, Wr1, br1, Wr2, br2);
    // 4: T = dyntanh(x + Att@Wo) -> limbs  (ncu capture slot)
    mmagemm<128, 1><<<dim3(CC / 128, NN / 128), 256, SM128>>>(
        Al0, Al1, Bo0, Bo1, ATTKP,
        nullptr, 0, Tl0, Tl1, CC,
        nullptr, x, CC, a1, g1, b1);
    // 5: H2[:, :512] = dyntanh2(gelu(T@Wlin + blin)) -> limbs
    mmagemm<128, 2><<<dim3(HIDD / 128, NN / 128), 256, SM128>>>(
        Tl0, Tl1, Bl0, Bl1, CC,
        nullptr, 0, Hl0, Hl1, H2KP,
        blin, nullptr, 0, a2, g2, b2);
    // 6: fused Z gemm + VQ
    zvq_kernel<<<dim3(1, NN / 64), 256, SMZ>>>(
        Hl0, Hl1, Bu0, Bu1, H2KP, bout, cb, out);
    // 7: loss scalar
    if (out_size > NN * OUTD) loss_reduce_kernel<<<1, 1024>>>(out);
}

// round 15
// speedup vs baseline: 2.0173x; 1.0023x over previous
#include <cuda_runtime.h>
#include <cuda_fp16.h>
#include <math.h>
#include <cstdint>

#define NN 16384
#define CC 256
#define HH 8
#define HD 512
#define QKVW 1536
#define HIDD 512
#define OUTD 64
#define H2D 532
#define ATTKP 576   // 520 padded to 64-multiple
#define H2KP 576    // 532 padded

// ---------------- scratch (static device arrays; no allocation) ----------------
__device__ float g_QKV[NN * QKVW];          // fp32 Q|K|V for attention
__device__ float g_G[NN * HH];
__device__ float g_part[NN];                // per-node vq loss partials

// activation fp16 limbs (zero-init pads stay zero forever)
__device__ __half g_xl0[NN * CC], g_xl1[NN * CC];
__device__ __half g_Al0[NN * ATTKP], g_Al1[NN * ATTKP];
__device__ __half g_Tl0[NN * CC], g_Tl1[NN * CC];
__device__ __half g_Hl0[NN * H2KP], g_Hl1[NN * H2KP];

// weight fp16 limbs, [N, Kp] K-major
__device__ __half g_Bq0[QKVW * CC], g_Bq1[QKVW * CC];
__device__ __half g_Bo0[CC * ATTKP], g_Bo1[CC * ATTKP];
__device__ __half g_Bl0[HIDD * CC], g_Bl1[HIDD * CC];
__device__ __half g_Bu0[OUTD * H2KP], g_Bu1[OUTD * H2KP];

// ---------------- helpers ----------------
__device__ __forceinline__ float gelu_tanh(float x) {
    float x3 = x * x * x;
    return 0.5f * x * (1.0f + tanhf(0.7978845608028654f * (x + 0.044715f * x3)));
}

__device__ __forceinline__ void store2(__half* p0, __half* p1, size_t off, float v) {
    __half h0 = __float2half_rn(v);
    __half h1 = __float2half_rn(v - __half2float(h0));
    p0[off] = h0;
    p1[off] = h1;
}

// packed pair store: limbs of (v0,v1) at consecutive offsets (off even)
__device__ __forceinline__ void store2x2(__half* p0, __half* p1, size_t off,
                                         float v0, float v1) {
    __half a0 = __float2half_rn(v0), a1 = __float2half_rn(v1);
    *(__half2*)(p0 + off) = __halves2half2(a0, a1);
    float r0 = v0 - __half2float(a0), r1 = v1 - __half2float(a1);
    *(__half2*)(p1 + off) = __halves2half2(__float2half_rn(r0), __float2half_rn(r1));
}

__device__ __forceinline__ uint32_t smem_u32(const void* p) {
    uint32_t a;
    asm("{ .reg .u64 t; cvta.to.shared.u64 t, %1; cvt.u32.u64 %0, t; }" : "=r"(a) : "l"(p));
    return a;
}

__device__ __forceinline__ void ldsm4(uint32_t* r, uint32_t addr) {
    asm volatile("ldmatrix.sync.aligned.m8n8.x4.shared.b16 {%0,%1,%2,%3}, [%4];"
                 : "=r"(r[0]), "=r"(r[1]), "=r"(r[2]), "=r"(r[3]) : "r"(addr));
}

__device__ __forceinline__ void mma16816(float* c, const uint32_t* a, const uint32_t* b) {
    asm volatile(
        "mma.sync.aligned.m16n8k16.row.col.f32.f16.f16.f32 "
        "{%0,%1,%2,%3}, {%4,%5,%6,%7}, {%8,%9}, {%0,%1,%2,%3};"
        : "+f"(c[0]), "+f"(c[1]), "+f"(c[2]), "+f"(c[3])
        : "r"(a[0]), "r"(a[1]), "r"(a[2]), "r"(a[3]), "r"(b[0]), "r"(b[1]));
}

__device__ __forceinline__ void cpasync16(uint32_t saddr, const void* gptr) {
    asm volatile("cp.async.cg.shared.global [%0], [%1], 16;"
                 :: "r"(saddr), "l"(gptr) : "memory");
}

// ============== mma.sync fp16 2-limb 3-pass GEMM, cp.async 3-stage ==============
// EPI: 0=fp32 plain, 1=resid+dyntanh->limbs, 2=gelu(bias)+dyntanh->limbs
template <int NT, int EPI>
__global__ __launch_bounds__(256) void mmagemm(
        const __half* __restrict__ A0, const __half* __restrict__ A1,
        const __half* __restrict__ B0, const __half* __restrict__ B1,
        int Kp,
        float* __restrict__ outF, int ldoF,
        __half* __restrict__ O0, __half* __restrict__ O1, int ldoL,
        const float* __restrict__ bias, const float* __restrict__ resid, int ldr,
        const float* __restrict__ alpha_p,
        const float* __restrict__ gv, const float* __restrict__ bv) {
    extern __shared__ __half sm[];
    constexpr int NF = NT / 32;
    constexpr int ROWB = 144;
    constexpr int ABYTES = 128 * ROWB;
    constexpr int STAGE = (128 + NT) * ROWB;

    uint32_t sbase = smem_u32(sm);
    int tid = threadIdx.x, lane = tid & 31, wid = tid >> 5;
    int wm = wid & 1, wn = wid >> 1;
    int bm = blockIdx.y * 128, bn = blockIdx.x * NT;
    int nch = Kp >> 6;
    int nit = 3 * nch;

    float acc[4][NF][4];
#pragma unroll
    for (int i = 0; i < 4; i++)
#pragma unroll
        for (int j = 0; j < NF; j++)
#pragma unroll
            for (int c = 0; c < 4; c++) acc[i][j][c] = 0.f;

    auto issue = [&](int it, int s) {
        int t = it / nch, c = it - (it / nch) * nch;
        const __half* Ab = (t == 2) ? A1 : A0;
        const __half* Bb = (t == 1) ? B1 : B0;
        uint32_t abase = sbase + (uint32_t)s * STAGE;
#pragma unroll
        for (int q = 0; q < 4; q++) {
            int idx = tid + q * 256;
            int row = idx >> 3, cg = idx & 7;
            cpasync16(abase + row * ROWB + cg * 16,
                      Ab + (size_t)(bm + row) * Kp + c * 64 + cg * 8);
        }
        uint32_t bbase = abase + ABYTES;
#pragma unroll
        for (int q = 0; q < NF; q++) {
            int idx = tid + q * 256;
            int row = idx >> 3, cg = idx & 7;
            cpasync16(bbase + row * ROWB + cg * 16,
                      Bb + (size_t)(bn + row) * Kp + c * 64 + cg * 8);
        }
        asm volatile("cp.async.commit_group;" ::: "memory");
    };

    issue(0, 0);
    issue(1, 1);

    int s = 0;
#pragma unroll 1
    for (int it = 0; it < nit; it++) {
        if (it + 1 < nit) {
            asm volatile("cp.async.wait_group 1;" ::: "memory");
        } else {
            asm volatile("cp.async.wait_group 0;" ::: "memory");
        }
        __syncthreads();
        if (it + 2 < nit) {
            int s2 = s + 2;
            if (s2 >= 3) s2 -= 3;
            issue(it + 2, s2);
        }

        uint32_t abase = sbase + (uint32_t)s * STAGE;
        uint32_t bbase = abase + ABYTES;
#pragma unroll
        for (int kk = 0; kk < 4; kk++) {
            int k = kk * 16;
            int arow = wm * 64 + (lane & 15);
            int acol = k + (lane >> 4) * 8;
            int g = lane >> 3;
            int nr = wn * (NT / 4) + ((g >> 1) << 3) + (lane & 7);
            int kc = k + (g & 1) * 8;

            uint32_t a[4][4];
#pragma unroll
            for (int i = 0; i < 4; i++)
                ldsm4(a[i], abase + (arow + i * 16) * ROWB + acol * 2);
            uint32_t b[NF][2];
#pragma unroll
            for (int jj = 0; jj < NF / 2; jj++) {
                uint32_t tmp[4];
                ldsm4(tmp, bbase + (nr + jj * 16) * ROWB + kc * 2);
                b[2 * jj][0] = tmp[0]; b[2 * jj][1] = tmp[1];
                b[2 * jj + 1][0] = tmp[2]; b[2 * jj + 1][1] = tmp[3];
            }
#pragma unroll
            for (int i = 0; i < 4; i++)
#pragma unroll
                for (int j = 0; j < NF; j++) mma16816(acc[i][j], a[i], b[j]);
        }
        if (++s == 3) s = 0;
    }

    float alpha = (EPI == 1 || EPI == 2) ? *alpha_p : 0.f;
    int gid = lane >> 2, tig = lane & 3;
#pragma unroll
    for (int i = 0; i < 4; i++) {
#pragma unroll
        for (int j = 0; j < NF; j++) {
            int ncol = bn + wn * (NT / 4) + j * 8 + tig * 2;
#pragma unroll
            for (int hf = 0; hf < 2; hf++) {
                int m = bm + wm * 64 + i * 16 + gid + hf * 8;
                float v0 = acc[i][j][hf * 2 + 0];
                float v1 = acc[i][j][hf * 2 + 1];
                if (EPI == 0) {
                    *(float2*)(outF + (size_t)m * ldoF + ncol) = make_float2(v0, v1);
                } else if (EPI == 1) {
                    v0 += resid[(size_t)m * ldr + ncol];
                    v1 += resid[(size_t)m * ldr + ncol + 1];
                    v0 = tanhf(alpha * v0) * gv[ncol] + bv[ncol];
                    v1 = tanhf(alpha * v1) * gv[ncol + 1] + bv[ncol + 1];
                    store2x2(O0, O1, (size_t)m * ldoL + ncol, v0, v1);
                } else if (EPI == 2) {
                    v0 = gelu_tanh(v0 + bias[ncol]);
                    v1 = gelu_tanh(v1 + bias[ncol + 1]);
                    v0 = tanhf(alpha * v0) * gv[ncol] + bv[ncol];
                    v1 = tanhf(alpha * v1) * gv[ncol + 1] + bv[ncol + 1];
                    store2x2(O0, O1, (size_t)m * ldoL + ncol, v0, v1);
                }
            }
        }
    }
}

// ============== fused Z-GEMM (M-tile 128, N=64) + tanh(gelu) + VQ, 3-stage ========
// grid (1, 128): one CTA per 128 nodes -> single clean wave on 148 SMs
__global__ __launch_bounds__(256) void zvq_kernel(
        const __half* __restrict__ A0, const __half* __restrict__ A1,
        const __half* __restrict__ B0, const __half* __restrict__ B1,
        int Kp, const float* __restrict__ bias,
        const float* __restrict__ cb, float* __restrict__ out) {
    extern __shared__ char smz[];
    constexpr int ROWB = 144;
    constexpr int ABYTES = 128 * ROWB;
    constexpr int STAGE = (128 + 64) * ROWB;   // 27648
    constexpr int STAGES_SZ = 3 * STAGE;       // 82944
    float(*zbuf)[65] = (float(*)[65])(smz + STAGES_SZ);                 // 33280
    float(*cbs)[65] = (float(*)[65])(smz + STAGES_SZ + 33280);          // 16640
    float* cn = (float*)(smz + STAGES_SZ + 33280 + 16640);

    uint32_t sbase = smem_u32(smz);
    int tid = threadIdx.x, lane = tid & 31, wid = tid >> 5;
    int wm = wid & 1, wn = wid >> 1;
    int bm = blockIdx.y * 128;
    int nch = Kp >> 6;
    int nit = 3 * nch;

    for (int i = tid; i < 4096; i += 256) cbs[i >> 6][i & 63] = cb[i];
    __syncthreads();
    if (tid < 64) {
        float s = 0.f;
#pragma unroll 8
        for (int d = 0; d < 64; d++) s = fmaf(cbs[tid][d], cbs[tid][d], s);
        cn[tid] = s;
    }

    float acc[4][2][4];
#pragma unroll
    for (int i = 0; i < 4; i++)
#pragma unroll
        for (int j = 0; j < 2; j++)
#pragma unroll
            for (int c = 0; c < 4; c++) acc[i][j][c] = 0.f;

    auto issue = [&](int it, int s) {
        int t = it / nch, c = it - (it / nch) * nch;
        const __half* Ab = (t == 2) ? A1 : A0;
        const __half* Bb = (t == 1) ? B1 : B0;
        uint32_t abase = sbase + (uint32_t)s * STAGE;
#pragma unroll
        for (int q = 0; q < 4; q++) {
            int idx = tid + q * 256;
            int row = idx >> 3, cg = idx & 7;
            cpasync16(abase + row * ROWB + cg * 16,
                      Ab + (size_t)(bm + row) * Kp + c * 64 + cg * 8);
        }
        uint32_t bbase = abase + ABYTES;
#pragma unroll
        for (int q = 0; q < 2; q++) {
            int idx = tid + q * 256;
            int row = idx >> 3, cg = idx & 7;
            cpasync16(bbase + row * ROWB + cg * 16,
                      Bb + (size_t)row * Kp + c * 64 + cg * 8);
        }
        asm volatile("cp.async.commit_group;" ::: "memory");
    };

    issue(0, 0);
    issue(1, 1);

    int s = 0;
#pragma unroll 1
    for (int it = 0; it < nit; it++) {
        if (it + 1 < nit) {
            asm volatile("cp.async.wait_group 1;" ::: "memory");
        } else {
            asm volatile("cp.async.wait_group 0;" ::: "memory");
        }
        __syncthreads();
        if (it + 2 < nit) {
            int s2 = s + 2;
            if (s2 >= 3) s2 -= 3;
            issue(it + 2, s2);
        }

        uint32_t abase = sbase + (uint32_t)s * STAGE;
        uint32_t bbase = abase + ABYTES;
#pragma unroll
        for (int kk = 0; kk < 4; kk++) {
            int k = kk * 16;
            int arow = wm * 64 + (lane & 15);
            int acol = k + (lane >> 4) * 8;
            int g = lane >> 3;
            int nr = wn * 16 + ((g >> 1) << 3) + (lane & 7);
            int kc = k + (g & 1) * 8;

            uint32_t a[4][4];
#pragma unroll
            for (int i = 0; i < 4; i++)
                ldsm4(a[i], abase + (arow + i * 16) * ROWB + acol * 2);
            uint32_t b[2][2];
            {
                uint32_t tmp[4];
                ldsm4(tmp, bbase + nr * ROWB + kc * 2);
                b[0][0] = tmp[0]; b[0][1] = tmp[1];
                b[1][0] = tmp[2]; b[1][1] = tmp[3];
            }
#pragma unroll
            for (int i = 0; i < 4; i++)
#pragma unroll
                for (int j = 0; j < 2; j++) mma16816(acc[i][j], a[i], b[j]);
        }
        if (++s == 3) s = 0;
    }

    int gid = lane >> 2, tig = lane & 3;
#pragma unroll
    for (int i = 0; i < 4; i++) {
#pragma unroll
        for (int j = 0; j < 2; j++) {
#pragma unroll
            for (int cc = 0; cc < 4; cc++) {
                int mrow = wm * 64 + i * 16 + gid + (cc >> 1) * 8;
                int ncol = wn * 16 + j * 8 + tig * 2 + (cc & 1);
                zbuf[mrow][ncol] = tanhf(gelu_tanh(acc[i][j][cc] + bias[ncol]));
            }
        }
    }
    __syncthreads();

#pragma unroll 1
    for (int q = 0; q < 16; q++) {
        int ln = wid * 16 + q;
        int n = bm + ln;
        float dota = 0.f, dotb = 0.f;
#pragma unroll 8
        for (int d = 0; d < 64; d++) {
            float z = zbuf[ln][d];
            dota = fmaf(z, cbs[lane][d], dota);
            dotb = fmaf(z, cbs[lane + 32][d], dotb);
        }
        float d2a = cn[lane] - 2.f * dota;
        float d2b = cn[lane + 32] - 2.f * dotb;
        float sc;
        int bi;
        if (d2a <= d2b) { sc = d2a; bi = lane; }
        else            { sc = d2b; bi = lane + 32; }
#pragma unroll
        for (int o = 16; o; o >>= 1) {
            float osc = __shfl_xor_sync(0xffffffffu, sc, o);
            int obi = __shfl_xor_sync(0xffffffffu, bi, o);
            if (osc < sc || (osc == sc && obi < bi)) { sc = osc; bi = obi; }
        }
        float zq0 = cbs[bi][lane];
        float zq1 = cbs[bi][lane + 32];
        out[(size_t)n * 64 + lane] = zq0;
        out[(size_t)n * 64 + lane + 32] = zq1;
        float d0 = zbuf[ln][lane] - zq0;
        float d1 = zbuf[ln][lane + 32] - zq1;
        float df = d0 * d0 + d1 * d1;
#pragma unroll
        for (int o = 16; o; o >>= 1) df += __shfl_xor_sync(0xffffffffu, df, o);
        if (lane == 0) g_part[n] = df;
    }
}

// ============== fused prep: conversions + h2extra + gate in ONE kernel ==============
#define W1V (NN * CC / 4)
#define W2 (QKVW * CC)
#define W3 (CC * 520)
#define W4 (HIDD * CC)
#define W5 (OUTD * 532)
#define W6 (NN * 20)
#define W7 (NN * HH)
#define WTOT (W1V + W2 + W3 + W4 + W5 + W6 + W7)

__global__ void prep_kernel(const float* __restrict__ x,
                            const float* __restrict__ Wq, const float* __restrict__ Wk,
                            const float* __restrict__ Wv, const float* __restrict__ Wo,
                            const float* __restrict__ Wlin, const float* __restrict__ Wout,
                            const float* __restrict__ alpha2,
                            const float* __restrict__ g2, const float* __restrict__ b2,
                            const float* __restrict__ wg) {
    int t = blockIdx.x * blockDim.x + threadIdx.x;
    if (t < W1V) {
        float4 v = *(const float4*)(x + (size_t)t * 4);
        store2x2(g_xl0, g_xl1, (size_t)t * 4, v.x, v.y);
        store2x2(g_xl0, g_xl1, (size_t)t * 4 + 2, v.z, v.w);
        return;
    }
    t -= W1V;
    if (t < W2) {
        int n = t >> 8, k = t & 255;
        const float* s = (n < 512) ? Wq : ((n < 1024) ? Wk : Wv);
        int col = n & 511;
        store2(g_Bq0, g_Bq1, (size_t)n * CC + k, s[(size_t)k * 512 + col]);
        return;
    }
    t -= W2;
    if (t < W3) {
        int n = t / 520, k = t - n * 520;
        store2(g_Bo0, g_Bo1, (size_t)n * ATTKP + k, Wo[(size_t)k * CC + n]);
        return;
    }
    t -= W3;
    if (t < W4) {
        int n = t >> 8, k = t & 255;
        store2(g_Bl0, g_Bl1, (size_t)n * CC + k, Wlin[(size_t)k * HIDD + n]);
        return;
    }
    t -= W4;
    if (t < W5) {
        int n = t / 532, k = t - n * 532;
        store2(g_Bu0, g_Bu1, (size_t)n * H2KP + k, Wout[(size_t)k * OUTD + n]);
        return;
    }
    t -= W5;
    if (t < W6) {
        int n = t / 20, j = t - n * 20;
        float a = *alpha2;
        float v = tanhf(a * x[(size_t)n * CC + j]) * g2[512 + j] + b2[512 + j];
        store2(g_Hl0, g_Hl1, (size_t)n * H2KP + 512 + j, v);
        return;
    }
    t -= W6;
    if (t < W7) {
        int n = t >> 3, h = t & 7;
        const float* xr = x + (size_t)n * CC;
        float acc = 0.f;
#pragma unroll 4
        for (int c = 0; c < CC; c++) acc = fmaf(xr[c], wg[c * HH + h], acc);
        g_G[t] = acc;
    }
}

// ---------------- attention v4: 2 nodes per block, dedup radial MLP ----------------
__global__ void attn_kernel(const float* __restrict__ coors, const int* __restrict__ nbr,
                            const float* __restrict__ Wr1, const float* __restrict__ br1,
                            const float* __restrict__ Wr2, const float* __restrict__ br2) {
    int n0 = blockIdx.x * 2;
    int tid = threadIdx.x;
    __shared__ int s_nbr[2][8];
    __shared__ float s_dist[2][8];
    __shared__ float s_unit[2][8][3];
    __shared__ float s_hid[2][8][16];
    __shared__ float s_rad[2][8][8];
    __shared__ float s_gate[2][8][8];

    // phase A: 16 threads compute dist/unit for (p, j)
    if (tid < 16) {
        int p = tid >> 3, j = tid & 7;
        int n = n0 + p;
        int mm = nbr[(size_t)n * 8 + j];
        s_nbr[p][j] = mm;
        float cx = coors[(size_t)n * 3], cy = coors[(size_t)n * 3 + 1], cz = coors[(size_t)n * 3 + 2];
        float rx = coors[(size_t)mm * 3] - cx;
        float ry = coors[(size_t)mm * 3 + 1] - cy;
        float rz = coors[(size_t)mm * 3 + 2] - cz;
        float d = sqrtf(rx * rx + ry * ry + rz * rz + 1e-8f);
        s_dist[p][j] = d;
        s_unit[p][j][0] = rx / d;
        s_unit[p][j][1] = ry / d;
        s_unit[p][j][2] = rz / d;
    }
    __syncthreads();
    // phase B: 256 threads compute hidden activations (2 nodes x 8 j x 16 i)
    {
        int p = tid >> 7, r = tid & 127;
        int j = r >> 4, i = r & 15;
        s_hid[p][j][i] = gelu_tanh(s_dist[p][j] * Wr1[i] + br1[i]);
    }
    __syncthreads();
    // phase C: rad contraction (128 threads) + gate gather (128 threads)
    if (tid < 128) {
        int p = tid >> 6, r = tid & 63;
        int j = r >> 3, h = r & 7;
        float acc = br2[h];
#pragma unroll
        for (int i = 0; i < 16; i++)
            acc = fmaf(s_hid[p][j][i], Wr2[i * 8 + h], acc);
        s_rad[p][j][h] = acc;
    } else {
        int t2 = tid - 128;
        int p = t2 >> 6, r = t2 & 63;
        int j = r >> 3, h = r & 7;
        s_gate[p][j][h] = g_G[(size_t)s_nbr[p][j] * HH + h];
    }
    __syncthreads();

    int w = tid >> 5, lane = tid & 31;
    int h = w;
    int sub = lane & 15, hv = lane >> 4;

#pragma unroll 1
    for (int p = 0; p < 2; p++) {
        int n = n0 + p;
        const float* qr = g_QKV + (size_t)n * QKVW + h * 64;
        float4 q4 = *(const float4*)(qr + sub * 4);

        float logit[8];
#pragma unroll
        for (int t = 0; t < 4; t++) {
            int j = 2 * t + hv;
            const float* kr = g_QKV + (size_t)s_nbr[p][j] * QKVW + 512 + h * 64;
            float4 k4 = *(const float4*)(kr + sub * 4);
            float pp = q4.x * k4.x + q4.y * k4.y + q4.z * k4.z + q4.w * k4.w;
#pragma unroll
            for (int o = 8; o; o >>= 1) pp += __shfl_xor_sync(0xffffffffu, pp, o);
            logit[2 * t] = __shfl_sync(0xffffffffu, pp, 0);
            logit[2 * t + 1] = __shfl_sync(0xffffffffu, pp, 16);
        }
#pragma unroll
        for (int j = 0; j < 8; j++) {
            float pp = logit[j] * 0.125f + s_rad[p][j][h];
            logit[j] = (s_dist[p][j] <= 10.0f) ? pp : -1e9f;
        }
        float mx = logit[0];
#pragma unroll
        for (int j = 1; j < 8; j++) mx = fmaxf(mx, logit[j]);
        float e[8];
        float se = 0.f;
#pragma unroll
        for (int j = 0; j < 8; j++) { e[j] = __expf(logit[j] - mx); se += e[j]; }
        float inv = 1.f / se;
        float a0 = 0.f, a1 = 0.f;
#pragma unroll
        for (int j = 0; j < 8; j++) {
            float at = e[j] * inv;
            const float* vr = g_QKV + (size_t)s_nbr[p][j] * QKVW + 1024 + h * 64;
            float2 v2 = *(const float2*)(vr + lane * 2);
            a0 = fmaf(at, v2.x, a0);
            a1 = fmaf(at, v2.y, a1);
        }
        size_t base = (size_t)n * ATTKP + h * 64 + lane * 2;
        store2x2(g_Al0, g_Al1, base, a0, a1);
        if (lane == 0) {
            float vx = 0.f, vy = 0.f, vz = 0.f;
#pragma unroll
            for (int j = 0; j < 8; j++) {
                float wg = e[j] * inv * s_gate[p][j][h];
                vx = fmaf(wg, s_unit[p][j][0], vx);
                vy = fmaf(wg, s_unit[p][j][1], vy);
                vz = fmaf(wg, s_unit[p][j][2], vz);
            }
            float vn = sqrtf(vx * vx + vy * vy + vz * vz + 1e-8f);
            store2(g_Al0, g_Al1, (size_t)n * ATTKP + 512 + h, vn);
        }
    }
}

__global__ void loss_reduce_kernel(float* __restrict__ out) {
    __shared__ double s_s[32];
    int tid = threadIdx.x;
    double s = 0.0;
    for (int i = tid; i < NN; i += 1024) s += (double)g_part[i];
#pragma unroll
    for (int o = 16; o; o >>= 1) s += __shfl_xor_sync(0xffffffffu, s, o);
    if ((tid & 31) == 0) s_s[tid >> 5] = s;
    __syncthreads();
    if (tid == 0) {
        double tot = 0.0;
        for (int i = 0; i < 32; i++) tot += s_s[i];
        out[(size_t)NN * OUTD] = (float)(0.25 * tot / (double)((size_t)NN * OUTD));
    }
}

// ---------------- launch ----------------
extern "C" void kernel_launch(void* const* d_in, const int* in_sizes, int n_in,
                              void* d_out, int out_size) {
    const float *x, *coors, *Wq, *Wk, *Wv, *wg, *Wr1, *br1, *Wr2, *br2, *Wo;
    const float *a1, *g1, *b1, *Wlin, *blin, *a2, *g2, *b2, *Wout, *bout, *cb;
    const int* nbr;

    if (n_in > 5 && in_sizes[5] == 2048) {
        x = (const float*)d_in[0];   coors = (const float*)d_in[1];
        Wq = (const float*)d_in[2];  Wk = (const float*)d_in[3];  Wv = (const float*)d_in[4];
        wg = (const float*)d_in[5];  Wr1 = (const float*)d_in[6]; br1 = (const float*)d_in[7];
        Wr2 = (const float*)d_in[8]; br2 = (const float*)d_in[9]; Wo = (const float*)d_in[10];
        a1 = (const float*)d_in[11]; g1 = (const float*)d_in[12]; b1 = (const float*)d_in[13];
        Wlin = (const float*)d_in[14]; blin = (const float*)d_in[15];
        a2 = (const float*)d_in[16]; g2 = (const float*)d_in[17]; b2 = (const float*)d_in[18];
        Wout = (const float*)d_in[19]; bout = (const float*)d_in[20];
        cb = (const float*)d_in[21]; nbr = (const int*)d_in[22];
    } else {
        x = (const float*)d_in[0];   coors = (const float*)d_in[1];
        nbr = (const int*)d_in[2];
        Wq = (const float*)d_in[3];  Wk = (const float*)d_in[4];  Wv = (const float*)d_in[5];
        wg = (const float*)d_in[6];  Wr1 = (const float*)d_in[7]; br1 = (const float*)d_in[8];
        Wr2 = (const float*)d_in[9]; br2 = (const float*)d_in[10]; Wo = (const float*)d_in[11];
        a1 = (const float*)d_in[12]; g1 = (const float*)d_in[13]; b1 = (const float*)d_in[14];
        Wlin = (const float*)d_in[15]; blin = (const float*)d_in[16];
        a2 = (const float*)d_in[17]; g2 = (const float*)d_in[18]; b2 = (const float*)d_in[19];
        Wout = (const float*)d_in[20]; bout = (const float*)d_in[21];
        cb = (const float*)d_in[22];
    }

    float* pQKV;
    cudaGetSymbolAddress((void**)&pQKV, g_QKV);
    __half *xl0, *xl1, *Al0, *Al1, *Tl0, *Tl1, *Hl0, *Hl1;
    cudaGetSymbolAddress((void**)&xl0, g_xl0); cudaGetSymbolAddress((void**)&xl1, g_xl1);
    cudaGetSymbolAddress((void**)&Al0, g_Al0); cudaGetSymbolAddress((void**)&Al1, g_Al1);
    cudaGetSymbolAddress((void**)&Tl0, g_Tl0); cudaGetSymbolAddress((void**)&Tl1, g_Tl1);
    cudaGetSymbolAddress((void**)&Hl0, g_Hl0); cudaGetSymbolAddress((void**)&Hl1, g_Hl1);
    __half *Bq0, *Bq1, *Bo0, *Bo1, *Bl0, *Bl1, *Bu0, *Bu1;
    cudaGetSymbolAddress((void**)&Bq0, g_Bq0); cudaGetSymbolAddress((void**)&Bq1, g_Bq1);
    cudaGetSymbolAddress((void**)&Bo0, g_Bo0); cudaGetSymbolAddress((void**)&Bo1, g_Bo1);
    cudaGetSymbolAddress((void**)&Bl0, g_Bl0); cudaGetSymbolAddress((void**)&Bl1, g_Bl1);
    cudaGetSymbolAddress((void**)&Bu0, g_Bu0); cudaGetSymbolAddress((void**)&Bu1, g_Bu1);

    float* out = (float*)d_out;

    constexpr int SM128 = 3 * (128 + 128) * 144;                     // 110592
    constexpr int SMZ = 3 * (128 + 64) * 144 + 33280 + 16640 + 256;  // 133120
    cudaFuncSetAttribute(mmagemm<128, 0>, cudaFuncAttributeMaxDynamicSharedMemorySize, SM128);
    cudaFuncSetAttribute(mmagemm<128, 1>, cudaFuncAttributeMaxDynamicSharedMemorySize, SM128);
    cudaFuncSetAttribute(mmagemm<128, 2>, cudaFuncAttributeMaxDynamicSharedMemorySize, SM128);
    cudaFuncSetAttribute(zvq_kernel, cudaFuncAttributeMaxDynamicSharedMemorySize, SMZ);

    // 1: conversions + h2extra + gate in one kernel
    prep_kernel<<<(WTOT + 255) / 256, 256>>>(x, Wq, Wk, Wv, Wo, Wlin, Wout, a2, g2, b2, wg);
    // 2: QKV = x @ [Wq|Wk|Wv] -> fp32
    mmagemm<128, 0><<<dim3(QKVW / 128, NN / 128), 256, SM128>>>(
        xl0, xl1, Bq0, Bq1, CC,
        pQKV, QKVW, nullptr, nullptr, 0,
        nullptr, nullptr, 0, nullptr, nullptr, nullptr);
    // 3: attention (2 nodes per block)
    attn_kernel<<<NN / 2, 256>>>(coors, nbr, Wr1, br1, Wr2, br2);
    // 4: T = dyntanh(x + Att@Wo) -> limbs  (ncu capture slot)
    mmagemm<128, 1><<<dim3(CC / 128, NN / 128), 256, SM128>>>(
        Al0, Al1, Bo0, Bo1, ATTKP,
        nullptr, 0, Tl0, Tl1, CC,
        nullptr, x, CC, a1, g1, b1);
    // 5: H2[:, :512] = dyntanh2(gelu(T@Wlin + blin)) -> limbs
    mmagemm<128, 2><<<dim3(HIDD / 128, NN / 128), 256, SM128>>>(
        Tl0, Tl1, Bl0, Bl1, CC,
        nullptr, 0, Hl0, Hl1, H2KP,
        blin, nullptr, 0, a2, g2, b2);
    // 6: fused Z gemm + VQ (M-tile 128, single wave)
    zvq_kernel<<<dim3(1, NN / 128), 256, SMZ>>>(
        Hl0, Hl1, Bu0, Bu1, H2KP, bout, cb, out);
    // 7: loss scalar
    if (out_size > NN * OUTD) loss_reduce_kernel<<<1, 1024>>>(out);
}